// round 1
// baseline (speedup 1.0000x reference)
#include <cuda_runtime.h>
#include <math.h>

// Problem constants
#define BQ   4
#define CC   256
#define DD   8
#define HH   32
#define WW   32
#define NHEAD 4
#define DHD  64
#define PP   64
#define NN   8192    // tokens = H*W*D
#define SPA  8192    // spatial = D*H*W

// ---------------- scratch (device globals; no runtime alloc) ----------------
__device__ float g_t   [(size_t)BQ * NN * CC];        // [B,N,C] transposed input
__device__ float g_qkv [(size_t)BQ * NN * 3 * CC];    // [B,N,768]
__device__ float g_cnpart[64 * 512];                  // colnorm partials
__device__ float g_rnorm [BQ * 512];                  // 1/max(||col||,eps) for q,k cols
__device__ float g_kvpart[2 * 16 * 8 * 4096];         // split-K partials for kp/vp
__device__ float g_kvp   [2 * 16 * 4096];             // kp then vp: [kind][b*4+h][e*64+p]
__device__ float g_o   [(size_t)BQ * NN * CC];        // attention output [B,N,C]
__device__ float g_o2  [(size_t)BQ * NN * CC];        // after out-proj
__device__ float g_y   [(size_t)BQ * CC * SPA];       // residual stream, NCDHW
__device__ float g_dw  [(size_t)BQ * CC * SPA];       // depthwise conv out, NCDHW

// ---------------- K0: transpose x (NCDHW) -> t [B,N,C] ----------------
__global__ void k_transpose(const float* __restrict__ x) {
    int blk = blockIdx.x;            // b*8192 + n
    int b = blk >> 13;
    int n = blk & 8191;
    int c = threadIdx.x;
    int h = n >> 8, w = (n >> 3) & 31, d = n & 7;
    int sp = d * 1024 + h * 32 + w;
    g_t[(size_t)blk * 256 + c] = x[(size_t)(b * 256 + c) * SPA + sp];
}

// ---------------- generic 64x64 tiled fp32 GEMM: C = A@B (+bias) ----------------
// A [M,K] row-major, B [K,N] row-major. M,N,K multiples of 64. 256 threads.
__global__ void k_gemm64(const float* __restrict__ A, const float* __restrict__ B,
                         const float* __restrict__ bias, float* __restrict__ C,
                         int N, int K) {
    __shared__ float As[64 * 64];
    __shared__ float Bs[64 * 64];
    int row0 = blockIdx.y * 64, col0 = blockIdx.x * 64;
    int tid = threadIdx.x;
    int tx = tid & 15, ty = tid >> 4;
    float acc[4][4] = {};
    for (int k0 = 0; k0 < K; k0 += 64) {
#pragma unroll
        for (int i = 0; i < 4; i++) {
            int v = tid + i * 256;
            int r = v >> 4, c4 = (v & 15) << 2;
            *(float4*)&As[r * 64 + c4] =
                *(const float4*)&A[(size_t)(row0 + r) * K + k0 + c4];
            *(float4*)&Bs[r * 64 + c4] =
                *(const float4*)&B[(size_t)(k0 + r) * N + col0 + c4];
        }
        __syncthreads();
#pragma unroll 16
        for (int kk = 0; kk < 64; kk++) {
            float4 bv = *(const float4*)&Bs[kk * 64 + tx * 4];
#pragma unroll
            for (int i = 0; i < 4; i++) {
                float a = As[(ty * 4 + i) * 64 + kk];
                acc[i][0] += a * bv.x;
                acc[i][1] += a * bv.y;
                acc[i][2] += a * bv.z;
                acc[i][3] += a * bv.w;
            }
        }
        __syncthreads();
    }
#pragma unroll
    for (int i = 0; i < 4; i++) {
#pragma unroll
        for (int j = 0; j < 4; j++) {
            int cc = col0 + tx * 4 + j;
            float bb = bias ? bias[cc] : 0.0f;
            C[(size_t)(row0 + ty * 4 + i) * N + cc] = acc[i][j] + bb;
        }
    }
}

// ---------------- K2: column sum-of-squares for q,k (cols 0..511) ----------------
__global__ void k_cnpart(const float* __restrict__ qkv) {
    int chunk = blockIdx.x;   // 16 chunks of 512 tokens
    int b = blockIdx.y;
    int tid = threadIdx.x;
    float s0 = 0.f, s1 = 0.f;
    int n0 = chunk * 512;
    for (int n = n0; n < n0 + 512; n++) {
        const float* row = qkv + (size_t)(b * 8192 + n) * 768;
        float v0 = row[tid];
        float v1 = row[256 + tid];
        s0 += v0 * v0;
        s1 += v1 * v1;
    }
    g_cnpart[(b * 16 + chunk) * 512 + tid] = s0;
    g_cnpart[(b * 16 + chunk) * 512 + 256 + tid] = s1;
}

__global__ void k_cnfin() {
    int idx = blockIdx.x * 256 + threadIdx.x;   // b*512 + col, 2048 total
    int b = idx >> 9, col = idx & 511;
    float s = 0.f;
#pragma unroll
    for (int ch = 0; ch < 16; ch++) s += g_cnpart[(b * 16 + ch) * 512 + col];
    g_rnorm[idx] = 1.0f / fmaxf(sqrtf(s), 1e-12f);
}

// ---------------- K3: kp/vp = (k or v)^T @ w_seq, split-K partials ----------------
__global__ void k_kvproj(const float* __restrict__ qkv, const float* __restrict__ wseq) {
    __shared__ float As[64 * 64];   // [n][e]  (k/v slice, k pre-normalized)
    __shared__ float Bs[64 * 64];   // [n][p]
    __shared__ float sc[64];
    int slice = blockIdx.x;         // 8 K-slices of 1024 tokens
    int bh = blockIdx.y;            // b*4+h
    int kind = blockIdx.z;          // 0=k, 1=v
    int b = bh >> 2, h = bh & 3;
    int colbase = (kind == 0 ? 256 : 512) + h * 64;
    int tid = threadIdx.x;
    if (tid < 64) sc[tid] = (kind == 0) ? g_rnorm[b * 512 + 256 + h * 64 + tid] : 1.0f;
    __syncthreads();
    int tx = tid & 15, ty = tid >> 4;
    float acc[4][4] = {};
    int nbeg = slice * 1024;
    for (int n0 = nbeg; n0 < nbeg + 1024; n0 += 64) {
#pragma unroll
        for (int i = 0; i < 4; i++) {
            int v = tid + i * 256;
            int r = v >> 4, c4 = (v & 15) << 2;
            float4 av = *(const float4*)&qkv[(size_t)(b * 8192 + n0 + r) * 768 + colbase + c4];
            av.x *= sc[c4 + 0]; av.y *= sc[c4 + 1];
            av.z *= sc[c4 + 2]; av.w *= sc[c4 + 3];
            *(float4*)&As[r * 64 + c4] = av;
            *(float4*)&Bs[r * 64 + c4] = *(const float4*)&wseq[(size_t)(n0 + r) * 64 + c4];
        }
        __syncthreads();
#pragma unroll 16
        for (int nn = 0; nn < 64; nn++) {
            float4 bv = *(const float4*)&Bs[nn * 64 + tx * 4];
#pragma unroll
            for (int i = 0; i < 4; i++) {
                float a = As[nn * 64 + ty * 4 + i];
                acc[i][0] += a * bv.x;
                acc[i][1] += a * bv.y;
                acc[i][2] += a * bv.z;
                acc[i][3] += a * bv.w;
            }
        }
        __syncthreads();
    }
    float* dst = g_kvpart + (size_t)((kind * 16 + bh) * 8 + slice) * 4096;
#pragma unroll
    for (int i = 0; i < 4; i++)
#pragma unroll
        for (int j = 0; j < 4; j++)
            dst[(ty * 4 + i) * 64 + tx * 4 + j] = acc[i][j];
}

__global__ void k_kvred(const float* __restrict__ bseq) {
    int idx = blockIdx.x * 256 + threadIdx.x;   // 131072 total
    int kb = idx >> 12;                          // kind*16+bh
    int ep = idx & 4095;
    float s = 0.f;
#pragma unroll
    for (int sl = 0; sl < 8; sl++) s += g_kvpart[(size_t)(kb * 8 + sl) * 4096 + ep];
    g_kvp[idx] = s + bseq[ep & 63];
}

// ---------------- K4: fused attention (logits -> softmax -> @vp^T) ----------------
// block = 128 tokens of one (b,h); kp/vp tiles in smem; logits in registers.
__global__ void __launch_bounds__(128) k_attn(const float* __restrict__ qkv,
                                              const float* __restrict__ temp,
                                              float* __restrict__ o) {
    __shared__ float kpsm[4096];   // [e][p]
    __shared__ float vpsm[4096];   // [e][p]
    __shared__ float rnsm[64];
    int tid = threadIdx.x;
    int h = blockIdx.y, b = blockIdx.z;
    int bh = b * 4 + h;
    const float4* kp4 = (const float4*)(g_kvp + (size_t)bh * 4096);
    const float4* vp4 = (const float4*)(g_kvp + (size_t)(16 + bh) * 4096);
    for (int i = tid; i < 1024; i += 128) {
        ((float4*)kpsm)[i] = kp4[i];
        ((float4*)vpsm)[i] = vp4[i];
    }
    if (tid < 64) rnsm[tid] = g_rnorm[b * 512 + h * 64 + tid];
    __syncthreads();
    float tv = temp[h];
    int n = blockIdx.x * 128 + tid;
    const float* qrow = qkv + (size_t)(b * 8192 + n) * 768 + h * 64;

    float l[64];
#pragma unroll
    for (int p = 0; p < 64; p++) l[p] = 0.f;
    for (int e = 0; e < 64; e++) {
        float qe = qrow[e] * rnsm[e];
        const float4* krow = (const float4*)(kpsm + e * 64);
#pragma unroll
        for (int p4 = 0; p4 < 16; p4++) {
            float4 kv = krow[p4];
            l[p4 * 4 + 0] += qe * kv.x;
            l[p4 * 4 + 1] += qe * kv.y;
            l[p4 * 4 + 2] += qe * kv.z;
            l[p4 * 4 + 3] += qe * kv.w;
        }
    }
    float m = -1e30f;
#pragma unroll
    for (int p = 0; p < 64; p++) { l[p] *= tv; m = fmaxf(m, l[p]); }
    float s = 0.f;
#pragma unroll
    for (int p = 0; p < 64; p++) { l[p] = __expf(l[p] - m); s += l[p]; }
    float inv = 1.0f / s;

    float4* orow = (float4*)(o + (size_t)(b * 8192 + n) * 256 + h * 64);
    for (int e4 = 0; e4 < 16; e4++) {
        float r[4];
#pragma unroll
        for (int ii = 0; ii < 4; ii++) {
            const float4* vrow = (const float4*)(vpsm + (e4 * 4 + ii) * 64);
            float a = 0.f;
#pragma unroll
            for (int p4 = 0; p4 < 16; p4++) {
                float4 vv = vrow[p4];
                a += l[p4 * 4 + 0] * vv.x + l[p4 * 4 + 1] * vv.y
                   + l[p4 * 4 + 2] * vv.z + l[p4 * 4 + 3] * vv.w;
            }
            r[ii] = a * inv;
        }
        float4 ov; ov.x = r[0]; ov.y = r[1]; ov.z = r[2]; ov.w = r[3];
        orow[e4] = ov;
    }
}

// ---------------- K5b: LayerNorm + residual + restore NCDHW ----------------
__global__ void k_lnres(const float* __restrict__ x, const float* __restrict__ g,
                        const float* __restrict__ be) {
    int blk = blockIdx.x;     // b*8192 + n
    int b = blk >> 13, n = blk & 8191;
    int tid = threadIdx.x;
    float v = g_o2[(size_t)blk * 256 + tid];
    float s = v, sq = v * v;
#pragma unroll
    for (int off = 16; off; off >>= 1) {
        s  += __shfl_xor_sync(0xffffffffu, s, off);
        sq += __shfl_xor_sync(0xffffffffu, sq, off);
    }
    __shared__ float ss[8], sqq[8];
    __shared__ float mu_s, rstd_s;
    int wid = tid >> 5;
    if ((tid & 31) == 0) { ss[wid] = s; sqq[wid] = sq; }
    __syncthreads();
    if (tid == 0) {
        float ts = 0.f, tq = 0.f;
#pragma unroll
        for (int i = 0; i < 8; i++) { ts += ss[i]; tq += sqq[i]; }
        float mu = ts * (1.0f / 256.0f);
        float var = tq * (1.0f / 256.0f) - mu * mu;
        mu_s = mu;
        rstd_s = rsqrtf(var + 1e-5f);
    }
    __syncthreads();
    float r = (v - mu_s) * rstd_s * g[tid] + be[tid];
    int hh = n >> 8, ww = (n >> 3) & 31, dd = n & 7;
    int sp = dd * 1024 + hh * 32 + ww;
    size_t idx = (size_t)(b * 256 + tid) * SPA + sp;
    g_y[idx] = x[idx] + r;
}

// ---------------- K6: depthwise 3x3x3 SAME conv ----------------
__global__ void k_dwconv(const float* __restrict__ dwk, const float* __restrict__ dwb) {
    __shared__ float tile[10 * 34 * 34];   // 11560 floats w/ halo
    __shared__ float wk[27];
    int bc = blockIdx.x;                    // b*256 + c
    int c = bc & 255;
    int tid = threadIdx.x;
    if (tid < 27) wk[tid] = dwk[c * 27 + tid];
    const float* src = g_y + (size_t)bc * SPA;
    for (int i = tid; i < 11560; i += 256) {
        int dz = i / 1156;
        int rem = i - dz * 1156;
        int hy = rem / 34;
        int wx = rem - hy * 34;
        int d = dz - 1, hh = hy - 1, w = wx - 1;
        float val = 0.f;
        if (d >= 0 && d < 8 && hh >= 0 && hh < 32 && w >= 0 && w < 32)
            val = src[d * 1024 + hh * 32 + w];
        tile[i] = val;
    }
    __syncthreads();
    float bias = dwb[c];
    for (int i = tid; i < 8192; i += 256) {
        int d = i >> 10;
        int r = i & 1023;
        int hh = r >> 5, w = r & 31;
        float acc = 0.f;
#pragma unroll
        for (int kd = 0; kd < 3; kd++)
#pragma unroll
            for (int kh = 0; kh < 3; kh++)
#pragma unroll
                for (int kw = 0; kw < 3; kw++)
                    acc += wk[kd * 9 + kh * 3 + kw]
                         * tile[(d + kd) * 1156 + (hh + kh) * 34 + (w + kw)];
        g_dw[(size_t)bc * SPA + i] = acc + bias;
    }
}

// ---------------- K7: pointwise conv GEMM + bias + final residual ----------------
__global__ void k_pwfin(const float* __restrict__ pwk, const float* __restrict__ pwb,
                        float* __restrict__ out) {
    __shared__ float As[64 * 64];   // [co][ci]
    __shared__ float Bs[64 * 64];   // [ci][sp]
    int sp0 = blockIdx.x * 64;
    int co0 = blockIdx.y * 64;
    int b = blockIdx.z;
    int tid = threadIdx.x;
    int tx = tid & 15, ty = tid >> 4;
    float acc[4][4] = {};
    for (int ci0 = 0; ci0 < 256; ci0 += 64) {
#pragma unroll
        for (int i = 0; i < 4; i++) {
            int v = tid + i * 256;
            int r = v >> 4, c4 = (v & 15) << 2;
            *(float4*)&As[r * 64 + c4] =
                *(const float4*)&pwk[(size_t)(co0 + r) * 256 + ci0 + c4];
            *(float4*)&Bs[r * 64 + c4] =
                *(const float4*)&g_dw[(size_t)(b * 256 + ci0 + r) * SPA + sp0 + c4];
        }
        __syncthreads();
#pragma unroll 16
        for (int ci = 0; ci < 64; ci++) {
            float4 bv = *(const float4*)&Bs[ci * 64 + tx * 4];
#pragma unroll
            for (int i = 0; i < 4; i++) {
                float a = As[(ty * 4 + i) * 64 + ci];
                acc[i][0] += a * bv.x;
                acc[i][1] += a * bv.y;
                acc[i][2] += a * bv.z;
                acc[i][3] += a * bv.w;
            }
        }
        __syncthreads();
    }
#pragma unroll
    for (int i = 0; i < 4; i++) {
        int co = co0 + ty * 4 + i;
        float bb = pwb[co];
#pragma unroll
        for (int j = 0; j < 4; j++) {
            size_t idx = (size_t)(b * 256 + co) * SPA + sp0 + tx * 4 + j;
            out[idx] = g_y[idx] + bb + acc[i][j];
        }
    }
}

// ---------------- launch ----------------
extern "C" void kernel_launch(void* const* d_in, const int* in_sizes, int n_in,
                              void* d_out, int out_size) {
    (void)in_sizes; (void)n_in; (void)out_size;
    const float* x    = (const float*)d_in[0];
    const float* wqkv = (const float*)d_in[1];
    const float* wseq = (const float*)d_in[2];
    const float* bseq = (const float*)d_in[3];
    const float* temp = (const float*)d_in[4];
    const float* wout = (const float*)d_in[5];
    const float* bout = (const float*)d_in[6];
    const float* lng  = (const float*)d_in[7];
    const float* lnb  = (const float*)d_in[8];
    const float* dwk  = (const float*)d_in[9];
    const float* dwb  = (const float*)d_in[10];
    const float* pwk  = (const float*)d_in[11];
    const float* pwb  = (const float*)d_in[12];
    float* out = (float*)d_out;

    float *t, *qkv, *o, *o2;
    cudaGetSymbolAddress((void**)&t,   g_t);
    cudaGetSymbolAddress((void**)&qkv, g_qkv);
    cudaGetSymbolAddress((void**)&o,   g_o);
    cudaGetSymbolAddress((void**)&o2,  g_o2);

    // 1. transpose to token-major
    k_transpose<<<32768, 256>>>(x);
    // 2. QKV GEMM: [32768,256] @ [256,768]
    k_gemm64<<<dim3(12, 512), 256>>>(t, wqkv, nullptr, qkv, 768, 256);
    // 3. column L2 norms for q,k
    k_cnpart<<<dim3(16, 4), 256>>>(qkv);
    k_cnfin<<<8, 256>>>();
    // 4. kp/vp projections (split-K) + reduce with bias
    k_kvproj<<<dim3(8, 16, 2), 256>>>(qkv, wseq);
    k_kvred<<<512, 256>>>(bseq);
    // 5. fused attention
    k_attn<<<dim3(64, 4, 4), 128>>>(qkv, temp, o);
    // 6. output projection [32768,256] @ [256,256] + bias
    k_gemm64<<<dim3(4, 512), 256>>>(o, wout, bout, o2, 256, 256);
    // 7. LayerNorm + residual, restore NCDHW
    k_lnres<<<32768, 256>>>(x, lng, lnb);
    // 8. depthwise conv
    k_dwconv<<<1024, 256>>>(dwk, dwb);
    // 9. pointwise conv + bias + final residual
    k_pwfin<<<dim3(128, 4, 4), 256>>>(pwk, pwb, out);
}

// round 5
// speedup vs baseline: 1.2872x; 1.2872x over previous
#include <cuda_runtime.h>
#include <cuda_bf16.h>
#include <math.h>
#include <stdint.h>

// Problem constants
#define BQ   4
#define CC   256
#define NHEAD 4
#define PP   64
#define NN   8192
#define SPA  8192

// ---------------- scratch (device globals) ----------------
__device__ float g_t   [(size_t)BQ * NN * CC];
__device__ float g_qkv [(size_t)BQ * NN * 3 * CC];
__device__ float g_cnpart[64 * 512];
__device__ float g_rnorm [BQ * 512];
__device__ float g_kvpart[2 * 16 * 8 * 4096];
__device__ float g_kvp   [2 * 16 * 4096];
__device__ float g_o   [(size_t)BQ * NN * CC];
__device__ float g_o2  [(size_t)BQ * NN * CC];
__device__ float g_y   [(size_t)BQ * CC * SPA];
__device__ float g_dw  [(size_t)BQ * CC * SPA];
// transposed bf16 hi/lo weights [N][K]
__device__ __nv_bfloat16 g_wqkvT_hi[768 * 256];
__device__ __nv_bfloat16 g_wqkvT_lo[768 * 256];
__device__ __nv_bfloat16 g_woutT_hi[256 * 256];
__device__ __nv_bfloat16 g_woutT_lo[256 * 256];

// ---------------- helpers ----------------
__device__ __forceinline__ uint32_t pack_bf16_hi(float a, float b) {
    __nv_bfloat16 ha = __float2bfloat16(a);
    __nv_bfloat16 hb = __float2bfloat16(b);
    return ((uint32_t)__bfloat16_as_ushort(hb) << 16) | __bfloat16_as_ushort(ha);
}
__device__ __forceinline__ uint32_t pack_bf16_lo(float a, float b) {
    __nv_bfloat16 ha = __float2bfloat16(a);
    __nv_bfloat16 hb = __float2bfloat16(b);
    __nv_bfloat16 la = __float2bfloat16(a - __bfloat162float(ha));
    __nv_bfloat16 lb = __float2bfloat16(b - __bfloat162float(hb));
    return ((uint32_t)__bfloat16_as_ushort(lb) << 16) | __bfloat16_as_ushort(la);
}

__device__ __forceinline__ void mma16816(float* d, const uint32_t* a, const uint32_t* b) {
    asm volatile(
        "mma.sync.aligned.m16n8k16.row.col.f32.bf16.bf16.f32 "
        "{%0,%1,%2,%3}, {%4,%5,%6,%7}, {%8,%9}, {%0,%1,%2,%3};"
        : "+f"(d[0]), "+f"(d[1]), "+f"(d[2]), "+f"(d[3])
        : "r"(a[0]), "r"(a[1]), "r"(a[2]), "r"(a[3]), "r"(b[0]), "r"(b[1]));
}

// ---------------- K0: coalesced transpose x (NCDHW) -> t [B,N,C] ----------------
__global__ void k_transpose(const float* __restrict__ x) {
    __shared__ float tile[64 * 65];
    int c0 = blockIdx.x * 64;
    int sp0 = blockIdx.y * 64;
    int b = blockIdx.z;
    int tid = threadIdx.x;
#pragma unroll
    for (int i = 0; i < 16; i++) {
        int idx = i * 256 + tid;
        int c = idx >> 6, s = idx & 63;
        tile[c * 65 + s] = x[(size_t)(b * 256 + c0 + c) * SPA + sp0 + s];
    }
    __syncthreads();
#pragma unroll
    for (int i = 0; i < 16; i++) {
        int idx = i * 256 + tid;
        int s = idx >> 6, c = idx & 63;
        int sp = sp0 + s;
        int d = sp >> 10, rem = sp & 1023, h = rem >> 5, w = rem & 31;
        int n = h * 256 + w * 8 + d;
        g_t[(size_t)(b * 8192 + n) * 256 + c0 + c] = tile[c * 65 + s];
    }
}

// ---------------- weight prep: fp32 [K][N] -> bf16 hi/lo [N][K] ----------------
__global__ void k_wprep(const float* __restrict__ w, __nv_bfloat16* __restrict__ thi,
                        __nv_bfloat16* __restrict__ tlo, int K, int Nn) {
    int idx = blockIdx.x * 256 + threadIdx.x;
    if (idx >= K * Nn) return;
    int k = idx / Nn, n = idx - k * Nn;
    float a = w[idx];
    __nv_bfloat16 h = __float2bfloat16(a);
    float hf = __bfloat162float(h);
    __nv_bfloat16 l = __float2bfloat16(a - hf);
    thi[n * K + k] = h;
    tlo[n * K + k] = l;
}

// ---------------- HMMA bf16-split GEMM: C[M,Ntot] = A[M,K] @ B (+bias) ----------------
// A fp32 row-major [M,K]; B transposed bf16 hi/lo [Ntot][K].
// CTA tile 128x128, K-chunk 64, 8 warps (2x4), warp tile 64x32 of m16n8k16.
#define RS 36   // smem row stride in 32-bit words (72 bf16)
__global__ void __launch_bounds__(256) k_mma(const float* __restrict__ A,
                                             const __nv_bfloat16* __restrict__ BtHi,
                                             const __nv_bfloat16* __restrict__ BtLo,
                                             const float* __restrict__ bias,
                                             float* __restrict__ C, int K, int Ntot) {
    extern __shared__ __align__(16) uint32_t sm[];
    uint32_t* sAhi = sm;                     // 128*RS words
    uint32_t* sAlo = sAhi + 128 * RS;
    uint32_t* sBhi = sAlo + 128 * RS;
    uint32_t* sBlo = sBhi + 128 * RS;

    int tid = threadIdx.x;
    int wid = tid >> 5, lane = tid & 31;
    int wr = wid >> 2, wc = wid & 3;         // warp grid 2x4
    int row0 = blockIdx.y * 128;
    int col0 = blockIdx.x * 128;
    int lq = lane >> 2;                       // lane/4: 0..7
    int lr = lane & 3;                        // lane%4

    float acc[4][4][4] = {};

    int nchunks = K >> 6;
    for (int ch = 0; ch < nchunks; ch++) {
        int k0 = ch << 6;
        // --- A chunk [128 x 64] fp32 -> bf16 hi/lo smem ---
#pragma unroll
        for (int i = 0; i < 8; i++) {
            int idx = tid + i * 256;          // 2048 float4 groups
            int r = idx >> 4, c4 = idx & 15;
            float4 av = *(const float4*)&A[(size_t)(row0 + r) * K + k0 + c4 * 4];
            uint2 vh, vl;
            vh.x = pack_bf16_hi(av.x, av.y);
            vh.y = pack_bf16_hi(av.z, av.w);
            vl.x = pack_bf16_lo(av.x, av.y);
            vl.y = pack_bf16_lo(av.z, av.w);
            *(uint2*)&sAhi[r * RS + c4 * 2] = vh;
            *(uint2*)&sAlo[r * RS + c4 * 2] = vl;
        }
        // --- B chunk [128n x 64k] bf16 hi/lo (K-major in gmem) ---
#pragma unroll
        for (int i = 0; i < 4; i++) {
            int idx = tid + i * 256;          // 1024 uint4 groups
            int n = idx >> 3, q = idx & 7;
            uint4 vh = *(const uint4*)&BtHi[(size_t)(col0 + n) * K + k0 + q * 8];
            uint4 vl = *(const uint4*)&BtLo[(size_t)(col0 + n) * K + k0 + q * 8];
            *(uint4*)&sBhi[n * RS + q * 4] = vh;
            *(uint4*)&sBlo[n * RS + q * 4] = vl;
        }
        __syncthreads();
#pragma unroll
        for (int ks = 0; ks < 4; ks++) {
            int kw = ks * 8;
            uint32_t bh[4][2], bl[4][2];
#pragma unroll
            for (int nt = 0; nt < 4; nt++) {
                int n = wc * 32 + nt * 8 + lq;
                bh[nt][0] = sBhi[n * RS + kw + lr];
                bh[nt][1] = sBhi[n * RS + kw + lr + 4];
                bl[nt][0] = sBlo[n * RS + kw + lr];
                bl[nt][1] = sBlo[n * RS + kw + lr + 4];
            }
#pragma unroll
            for (int mt = 0; mt < 4; mt++) {
                int r = wr * 64 + mt * 16 + lq;
                uint32_t ah[4], al[4];
                ah[0] = sAhi[r * RS + kw + lr];
                ah[1] = sAhi[(r + 8) * RS + kw + lr];
                ah[2] = sAhi[r * RS + kw + lr + 4];
                ah[3] = sAhi[(r + 8) * RS + kw + lr + 4];
                al[0] = sAlo[r * RS + kw + lr];
                al[1] = sAlo[(r + 8) * RS + kw + lr];
                al[2] = sAlo[r * RS + kw + lr + 4];
                al[3] = sAlo[(r + 8) * RS + kw + lr + 4];
#pragma unroll
                for (int nt = 0; nt < 4; nt++) {
                    mma16816(acc[mt][nt], ah, bh[nt]);
                    mma16816(acc[mt][nt], ah, bl[nt]);
                    mma16816(acc[mt][nt], al, bh[nt]);
                }
            }
        }
        __syncthreads();
    }
    // epilogue
#pragma unroll
    for (int mt = 0; mt < 4; mt++) {
        int r = row0 + wr * 64 + mt * 16 + lq;
#pragma unroll
        for (int nt = 0; nt < 4; nt++) {
            int c = col0 + wc * 32 + nt * 8 + lr * 2;
            float b0 = bias ? bias[c] : 0.0f;
            float b1 = bias ? bias[c + 1] : 0.0f;
            float2 v0, v1;
            v0.x = acc[mt][nt][0] + b0;
            v0.y = acc[mt][nt][1] + b1;
            v1.x = acc[mt][nt][2] + b0;
            v1.y = acc[mt][nt][3] + b1;
            *(float2*)&C[(size_t)r * Ntot + c] = v0;
            *(float2*)&C[(size_t)(r + 8) * Ntot + c] = v1;
        }
    }
}
#define SMEM_MMA (4 * 128 * RS * 4)

// ---------------- column L2 norms for q,k ----------------
__global__ void k_cnpart(const float* __restrict__ qkv) {
    int chunk = blockIdx.x;
    int b = blockIdx.y;
    int tid = threadIdx.x;
    float s0 = 0.f, s1 = 0.f;
    int n0 = chunk * 512;
    for (int n = n0; n < n0 + 512; n++) {
        const float* row = qkv + (size_t)(b * 8192 + n) * 768;
        float v0 = row[tid];
        float v1 = row[256 + tid];
        s0 += v0 * v0;
        s1 += v1 * v1;
    }
    g_cnpart[(b * 16 + chunk) * 512 + tid] = s0;
    g_cnpart[(b * 16 + chunk) * 512 + 256 + tid] = s1;
}

__global__ void k_cnfin() {
    int idx = blockIdx.x * 256 + threadIdx.x;
    int b = idx >> 9, col = idx & 511;
    float s = 0.f;
#pragma unroll
    for (int ch = 0; ch < 16; ch++) s += g_cnpart[(b * 16 + ch) * 512 + col];
    g_rnorm[idx] = 1.0f / fmaxf(sqrtf(s), 1e-12f);
}

// ---------------- kp/vp projections (SIMT split-K) ----------------
__global__ void k_kvproj(const float* __restrict__ qkv, const float* __restrict__ wseq) {
    __shared__ float As[64 * 64];
    __shared__ float Bs[64 * 64];
    __shared__ float sc[64];
    int slice = blockIdx.x;
    int bh = blockIdx.y;
    int kind = blockIdx.z;
    int b = bh >> 2, h = bh & 3;
    int colbase = (kind == 0 ? 256 : 512) + h * 64;
    int tid = threadIdx.x;
    if (tid < 64) sc[tid] = (kind == 0) ? g_rnorm[b * 512 + 256 + h * 64 + tid] : 1.0f;
    __syncthreads();
    int tx = tid & 15, ty = tid >> 4;
    float acc[4][4] = {};
    int nbeg = slice * 1024;
    for (int n0 = nbeg; n0 < nbeg + 1024; n0 += 64) {
#pragma unroll
        for (int i = 0; i < 4; i++) {
            int v = tid + i * 256;
            int r = v >> 4, c4 = (v & 15) << 2;
            float4 av = *(const float4*)&qkv[(size_t)(b * 8192 + n0 + r) * 768 + colbase + c4];
            av.x *= sc[c4 + 0]; av.y *= sc[c4 + 1];
            av.z *= sc[c4 + 2]; av.w *= sc[c4 + 3];
            *(float4*)&As[r * 64 + c4] = av;
            *(float4*)&Bs[r * 64 + c4] = *(const float4*)&wseq[(size_t)(n0 + r) * 64 + c4];
        }
        __syncthreads();
#pragma unroll 16
        for (int nn = 0; nn < 64; nn++) {
            float4 bv = *(const float4*)&Bs[nn * 64 + tx * 4];
#pragma unroll
            for (int i = 0; i < 4; i++) {
                float a = As[nn * 64 + ty * 4 + i];
                acc[i][0] += a * bv.x;
                acc[i][1] += a * bv.y;
                acc[i][2] += a * bv.z;
                acc[i][3] += a * bv.w;
            }
        }
        __syncthreads();
    }
    float* dst = g_kvpart + (size_t)((kind * 16 + bh) * 8 + slice) * 4096;
#pragma unroll
    for (int i = 0; i < 4; i++)
#pragma unroll
        for (int j = 0; j < 4; j++)
            dst[(ty * 4 + i) * 64 + tx * 4 + j] = acc[i][j];
}

__global__ void k_kvred(const float* __restrict__ bseq) {
    int idx = blockIdx.x * 256 + threadIdx.x;
    int kb = idx >> 12;
    int ep = idx & 4095;
    float s = 0.f;
#pragma unroll
    for (int sl = 0; sl < 8; sl++) s += g_kvpart[(size_t)(kb * 8 + sl) * 4096 + ep];
    g_kvp[idx] = s + bseq[ep & 63];
}

// ---------------- fused attention ----------------
__global__ void __launch_bounds__(128) k_attn(const float* __restrict__ qkv,
                                              const float* __restrict__ temp,
                                              float* __restrict__ o) {
    __shared__ float kpsm[4096];
    __shared__ float vpsm[4096];
    __shared__ float rnsm[64];
    int tid = threadIdx.x;
    int h = blockIdx.y, b = blockIdx.z;
    int bh = b * 4 + h;
    const float4* kp4 = (const float4*)(g_kvp + (size_t)bh * 4096);
    const float4* vp4 = (const float4*)(g_kvp + (size_t)(16 + bh) * 4096);
    for (int i = tid; i < 1024; i += 128) {
        ((float4*)kpsm)[i] = kp4[i];
        ((float4*)vpsm)[i] = vp4[i];
    }
    if (tid < 64) rnsm[tid] = g_rnorm[b * 512 + h * 64 + tid];
    __syncthreads();
    float tv = temp[h];
    int n = blockIdx.x * 128 + tid;
    const float* qrow = qkv + (size_t)(b * 8192 + n) * 768 + h * 64;

    float l[64];
#pragma unroll
    for (int p = 0; p < 64; p++) l[p] = 0.f;
    for (int e = 0; e < 64; e++) {
        float qe = qrow[e] * rnsm[e];
        const float4* krow = (const float4*)(kpsm + e * 64);
#pragma unroll
        for (int p4 = 0; p4 < 16; p4++) {
            float4 kv = krow[p4];
            l[p4 * 4 + 0] += qe * kv.x;
            l[p4 * 4 + 1] += qe * kv.y;
            l[p4 * 4 + 2] += qe * kv.z;
            l[p4 * 4 + 3] += qe * kv.w;
        }
    }
    float m = -1e30f;
#pragma unroll
    for (int p = 0; p < 64; p++) { l[p] *= tv; m = fmaxf(m, l[p]); }
    float s = 0.f;
#pragma unroll
    for (int p = 0; p < 64; p++) { l[p] = __expf(l[p] - m); s += l[p]; }
    float inv = 1.0f / s;

    float4* orow = (float4*)(o + (size_t)(b * 8192 + n) * 256 + h * 64);
    for (int e4 = 0; e4 < 16; e4++) {
        float r[4];
#pragma unroll
        for (int ii = 0; ii < 4; ii++) {
            const float4* vrow = (const float4*)(vpsm + (e4 * 4 + ii) * 64);
            float a = 0.f;
#pragma unroll
            for (int p4 = 0; p4 < 16; p4++) {
                float4 vv = vrow[p4];
                a += l[p4 * 4 + 0] * vv.x + l[p4 * 4 + 1] * vv.y
                   + l[p4 * 4 + 2] * vv.z + l[p4 * 4 + 3] * vv.w;
            }
            r[ii] = a * inv;
        }
        float4 ov; ov.x = r[0]; ov.y = r[1]; ov.z = r[2]; ov.w = r[3];
        orow[e4] = ov;
    }
}

// ---------------- LayerNorm + residual + restore NCDHW ----------------
__global__ void k_lnres(const float* __restrict__ x, const float* __restrict__ g,
                        const float* __restrict__ be) {
    int blk = blockIdx.x;
    int b = blk >> 13, n = blk & 8191;
    int tid = threadIdx.x;
    float v = g_o2[(size_t)blk * 256 + tid];
    float s = v, sq = v * v;
#pragma unroll
    for (int off = 16; off; off >>= 1) {
        s  += __shfl_xor_sync(0xffffffffu, s, off);
        sq += __shfl_xor_sync(0xffffffffu, sq, off);
    }
    __shared__ float ss[8], sqq[8];
    __shared__ float mu_s, rstd_s;
    int wid = tid >> 5;
    if ((tid & 31) == 0) { ss[wid] = s; sqq[wid] = sq; }
    __syncthreads();
    if (tid == 0) {
        float ts = 0.f, tq = 0.f;
#pragma unroll
        for (int i = 0; i < 8; i++) { ts += ss[i]; tq += sqq[i]; }
        float mu = ts * (1.0f / 256.0f);
        float var = tq * (1.0f / 256.0f) - mu * mu;
        mu_s = mu;
        rstd_s = rsqrtf(var + 1e-5f);
    }
    __syncthreads();
    float r = (v - mu_s) * rstd_s * g[tid] + be[tid];
    int hh = n >> 8, ww = (n >> 3) & 31, dd = n & 7;
    int sp = dd * 1024 + hh * 32 + ww;
    size_t idx = (size_t)(b * 256 + tid) * SPA + sp;
    g_y[idx] = x[idx] + r;
}

// ---------------- depthwise 3x3x3 SAME conv ----------------
__global__ void k_dwconv(const float* __restrict__ dwk, const float* __restrict__ dwb) {
    __shared__ float tile[10 * 34 * 34];
    __shared__ float wk[27];
    int bc = blockIdx.x;
    int c = bc & 255;
    int tid = threadIdx.x;
    if (tid < 27) wk[tid] = dwk[c * 27 + tid];
    const float* src = g_y + (size_t)bc * SPA;
    for (int i = tid; i < 11560; i += 256) {
        int dz = i / 1156;
        int rem = i - dz * 1156;
        int hy = rem / 34;
        int wx = rem - hy * 34;
        int d = dz - 1, hh = hy - 1, w = wx - 1;
        float val = 0.f;
        if (d >= 0 && d < 8 && hh >= 0 && hh < 32 && w >= 0 && w < 32)
            val = src[d * 1024 + hh * 32 + w];
        tile[i] = val;
    }
    __syncthreads();
    float bias = dwb[c];
    for (int i = tid; i < 8192; i += 256) {
        int d = i >> 10;
        int r = i & 1023;
        int hh = r >> 5, w = r & 31;
        float acc = 0.f;
#pragma unroll
        for (int kd = 0; kd < 3; kd++)
#pragma unroll
            for (int kh = 0; kh < 3; kh++)
#pragma unroll
                for (int kw = 0; kw < 3; kw++)
                    acc += wk[kd * 9 + kh * 3 + kw]
                         * tile[(d + kd) * 1156 + (hh + kh) * 34 + (w + kw)];
        g_dw[(size_t)bc * SPA + i] = acc + bias;
    }
}

// ---------------- pointwise conv + bias + final residual (SIMT) ----------------
__global__ void k_pwfin(const float* __restrict__ pwk, const float* __restrict__ pwb,
                        float* __restrict__ out) {
    __shared__ float As[64 * 64];
    __shared__ float Bs[64 * 64];
    int sp0 = blockIdx.x * 64;
    int co0 = blockIdx.y * 64;
    int b = blockIdx.z;
    int tid = threadIdx.x;
    int tx = tid & 15, ty = tid >> 4;
    float acc[4][4] = {};
    for (int ci0 = 0; ci0 < 256; ci0 += 64) {
#pragma unroll
        for (int i = 0; i < 4; i++) {
            int v = tid + i * 256;
            int r = v >> 4, c4 = (v & 15) << 2;
            *(float4*)&As[r * 64 + c4] =
                *(const float4*)&pwk[(size_t)(co0 + r) * 256 + ci0 + c4];
            *(float4*)&Bs[r * 64 + c4] =
                *(const float4*)&g_dw[(size_t)(b * 256 + ci0 + r) * SPA + sp0 + c4];
        }
        __syncthreads();
#pragma unroll 16
        for (int ci = 0; ci < 64; ci++) {
            float4 bv = *(const float4*)&Bs[ci * 64 + tx * 4];
#pragma unroll
            for (int i = 0; i < 4; i++) {
                float a = As[(ty * 4 + i) * 64 + ci];
                acc[i][0] += a * bv.x;
                acc[i][1] += a * bv.y;
                acc[i][2] += a * bv.z;
                acc[i][3] += a * bv.w;
            }
        }
        __syncthreads();
    }
#pragma unroll
    for (int i = 0; i < 4; i++) {
        int co = co0 + ty * 4 + i;
        float bb = pwb[co];
#pragma unroll
        for (int j = 0; j < 4; j++) {
            size_t idx = (size_t)(b * 256 + co) * SPA + sp0 + tx * 4 + j;
            out[idx] = g_y[idx] + bb + acc[i][j];
        }
    }
}

// ---------------- launch ----------------
extern "C" void kernel_launch(void* const* d_in, const int* in_sizes, int n_in,
                              void* d_out, int out_size) {
    (void)in_sizes; (void)n_in; (void)out_size;
    const float* x    = (const float*)d_in[0];
    const float* wqkv = (const float*)d_in[1];
    const float* wseq = (const float*)d_in[2];
    const float* bseq = (const float*)d_in[3];
    const float* temp = (const float*)d_in[4];
    const float* wout = (const float*)d_in[5];
    const float* bout = (const float*)d_in[6];
    const float* lng  = (const float*)d_in[7];
    const float* lnb  = (const float*)d_in[8];
    const float* dwk  = (const float*)d_in[9];
    const float* dwb  = (const float*)d_in[10];
    const float* pwk  = (const float*)d_in[11];
    const float* pwb  = (const float*)d_in[12];
    float* out = (float*)d_out;

    float *t, *qkv, *o, *o2;
    __nv_bfloat16 *wqkvT_hi, *wqkvT_lo, *woutT_hi, *woutT_lo;
    cudaGetSymbolAddress((void**)&t,   g_t);
    cudaGetSymbolAddress((void**)&qkv, g_qkv);
    cudaGetSymbolAddress((void**)&o,   g_o);
    cudaGetSymbolAddress((void**)&o2,  g_o2);
    cudaGetSymbolAddress((void**)&wqkvT_hi, g_wqkvT_hi);
    cudaGetSymbolAddress((void**)&wqkvT_lo, g_wqkvT_lo);
    cudaGetSymbolAddress((void**)&woutT_hi, g_woutT_hi);
    cudaGetSymbolAddress((void**)&woutT_lo, g_woutT_lo);

    cudaFuncSetAttribute(k_mma, cudaFuncAttributeMaxDynamicSharedMemorySize, SMEM_MMA);

    // 1. transpose to token-major (coalesced both sides)
    k_transpose<<<dim3(4, 128, 4), 256>>>(x);
    // 2. weight prep (bf16 hi/lo transposed)
    k_wprep<<<768, 256>>>(wqkv, wqkvT_hi, wqkvT_lo, 256, 768);
    k_wprep<<<256, 256>>>(wout, woutT_hi, woutT_lo, 256, 256);
    // 3. QKV GEMM on tensor cores (HMMA)
    k_mma<<<dim3(6, 256), 256, SMEM_MMA>>>(t, wqkvT_hi, wqkvT_lo, nullptr, qkv, 256, 768);
    // 4. column L2 norms for q,k
    k_cnpart<<<dim3(16, 4), 256>>>(qkv);
    k_cnfin<<<8, 256>>>();
    // 5. kp/vp projections + reduce
    k_kvproj<<<dim3(8, 16, 2), 256>>>(qkv, wseq);
    k_kvred<<<512, 256>>>(bseq);
    // 6. fused attention
    k_attn<<<dim3(64, 4, 4), 128>>>(qkv, temp, o);
    // 7. output projection on tensor cores (HMMA)
    k_mma<<<dim3(2, 256), 256, SMEM_MMA>>>(o, woutT_hi, woutT_lo, bout, o2, 256, 256);
    // 8. LayerNorm + residual, restore NCDHW
    k_lnres<<<32768, 256>>>(x, lng, lnb);
    // 9. depthwise conv
    k_dwconv<<<1024, 256>>>(dwk, dwb);
    // 10. pointwise conv + bias + final residual
    k_pwfin<<<dim3(128, 4, 4), 256>>>(pwk, pwb, out);
}

// round 7
// speedup vs baseline: 1.6756x; 1.3017x over previous
#include <cuda_runtime.h>
#include <cuda_bf16.h>
#include <math.h>
#include <stdint.h>

// Problem constants
#define BQ   4
#define CC   256
#define NHEAD 4
#define PP   64
#define NN   8192
#define SPA  8192

// ---------------- scratch (device globals) ----------------
__device__ __align__(128) __nv_bfloat16 g_t_hi[(size_t)BQ * NN * CC];
__device__ __align__(128) __nv_bfloat16 g_t_lo[(size_t)BQ * NN * CC];
__device__ float g_qkv [(size_t)BQ * NN * 3 * CC];
__device__ float g_cnpart[256 * 512];
__device__ float g_rnorm [BQ * 512];
__device__ float g_kvpart[2 * 16 * 8 * 4096];
__device__ float g_kvp   [2 * 16 * 4096];
__device__ __align__(128) __nv_bfloat16 g_o_hi[(size_t)BQ * NN * CC];
__device__ __align__(128) __nv_bfloat16 g_o_lo[(size_t)BQ * NN * CC];
__device__ float g_o2  [(size_t)BQ * NN * CC];
__device__ float g_mu  [BQ * NN];
__device__ float g_rs  [BQ * NN];
__device__ float g_y   [(size_t)BQ * CC * SPA];
__device__ __align__(128) __nv_bfloat16 g_dw_hi[(size_t)BQ * CC * SPA];
__device__ __align__(128) __nv_bfloat16 g_dw_lo[(size_t)BQ * CC * SPA];
// transposed bf16 hi/lo weights [N][K]
__device__ __align__(128) __nv_bfloat16 g_wqkvT_hi[768 * 256];
__device__ __align__(128) __nv_bfloat16 g_wqkvT_lo[768 * 256];
__device__ __align__(128) __nv_bfloat16 g_woutT_hi[256 * 256];
__device__ __align__(128) __nv_bfloat16 g_woutT_lo[256 * 256];
__device__ __align__(128) __nv_bfloat16 g_pwk_hi[256 * 256];
__device__ __align__(128) __nv_bfloat16 g_pwk_lo[256 * 256];

// ---------------- helpers ----------------
__device__ __forceinline__ uint32_t pack_bf16_hi(float a, float b) {
    __nv_bfloat16 ha = __float2bfloat16(a);
    __nv_bfloat16 hb = __float2bfloat16(b);
    return ((uint32_t)__bfloat16_as_ushort(hb) << 16) | __bfloat16_as_ushort(ha);
}
__device__ __forceinline__ uint32_t pack_bf16_lo(float a, float b) {
    __nv_bfloat16 ha = __float2bfloat16(a);
    __nv_bfloat16 hb = __float2bfloat16(b);
    __nv_bfloat16 la = __float2bfloat16(a - __bfloat162float(ha));
    __nv_bfloat16 lb = __float2bfloat16(b - __bfloat162float(hb));
    return ((uint32_t)__bfloat16_as_ushort(lb) << 16) | __bfloat16_as_ushort(la);
}

__device__ __forceinline__ void mma16816(float* d, const uint32_t* a, const uint32_t* b) {
    asm volatile(
        "mma.sync.aligned.m16n8k16.row.col.f32.bf16.bf16.f32 "
        "{%0,%1,%2,%3}, {%4,%5,%6,%7}, {%8,%9}, {%0,%1,%2,%3};"
        : "+f"(d[0]), "+f"(d[1]), "+f"(d[2]), "+f"(d[3])
        : "r"(a[0]), "r"(a[1]), "r"(a[2]), "r"(a[3]), "r"(b[0]), "r"(b[1]));
}

__device__ __forceinline__ uint32_t smem_u32(const void* p) {
    uint32_t a;
    asm("{ .reg .u64 t; cvta.to.shared.u64 t, %1; cvt.u32.u64 %0, t; }" : "=r"(a) : "l"(p));
    return a;
}
#define CP_ASYNC16(dst, src) \
    asm volatile("cp.async.cg.shared.global [%0], [%1], 16;" :: "r"(dst), "l"(src) : "memory")
#define CP_COMMIT() asm volatile("cp.async.commit_group;" ::: "memory")
#define CP_WAIT1()  asm volatile("cp.async.wait_group 1;" ::: "memory")
#define CP_WAIT0()  asm volatile("cp.async.wait_group 0;" ::: "memory")

#define RS 36                 // smem row stride in words (144B; 16B aligned; conflict-free frags)
#define TILE_W (128 * RS)     // words per 128-row tile

// ---------------- K0: transpose x (NCDHW) -> t_hi/lo [B,N,C] bf16 ----------------
__global__ void k_transpose(const float* __restrict__ x) {
    __shared__ float tile[64 * 65];
    int c0 = blockIdx.x * 64;
    int sp0 = blockIdx.y * 64;
    int b = blockIdx.z;
    int tid = threadIdx.x;
#pragma unroll
    for (int i = 0; i < 16; i++) {
        int idx = i * 256 + tid;
        int c = idx >> 6, s = idx & 63;
        tile[c * 65 + s] = x[(size_t)(b * 256 + c0 + c) * SPA + sp0 + s];
    }
    __syncthreads();
#pragma unroll
    for (int i = 0; i < 16; i++) {
        int idx = i * 256 + tid;
        int s = idx >> 6, c = idx & 63;
        int sp = sp0 + s;
        int d = sp >> 10, rem = sp & 1023, h = rem >> 5, w = rem & 31;
        int n = h * 256 + w * 8 + d;
        float v = tile[c * 65 + s];
        __nv_bfloat16 hi = __float2bfloat16(v);
        size_t gi = (size_t)(b * 8192 + n) * 256 + c0 + c;
        g_t_hi[gi] = hi;
        g_t_lo[gi] = __float2bfloat16(v - __bfloat162float(hi));
    }
}

// ---------------- weight prep: fp32 [K][N] -> bf16 hi/lo [N][K] ----------------
__global__ void k_wprep(const float* __restrict__ w, __nv_bfloat16* __restrict__ thi,
                        __nv_bfloat16* __restrict__ tlo, int K, int Nn) {
    int idx = blockIdx.x * 256 + threadIdx.x;
    if (idx >= K * Nn) return;
    int k = idx / Nn, n = idx - k * Nn;
    float a = w[idx];
    __nv_bfloat16 h = __float2bfloat16(a);
    tlo[n * K + k] = __float2bfloat16(a - __bfloat162float(h));
    thi[n * K + k] = h;
}
// no-transpose variant (pwk is already [co][ci] = [M][K])
__global__ void k_wprep_nt(const float* __restrict__ w, __nv_bfloat16* __restrict__ thi,
                           __nv_bfloat16* __restrict__ tlo, int total) {
    int idx = blockIdx.x * 256 + threadIdx.x;
    if (idx >= total) return;
    float a = w[idx];
    __nv_bfloat16 h = __float2bfloat16(a);
    thi[idx] = h;
    tlo[idx] = __float2bfloat16(a - __bfloat162float(h));
}

// ---------------- HMMA bf16-split GEMM, cp.async double-buffered ----------------
// A hi/lo bf16 [M][K]; B hi/lo bf16 [Ntot][K]. CTA tile 128x128, K-chunk 64.
__global__ void __launch_bounds__(256) k_mma(const __nv_bfloat16* __restrict__ Ahi,
                                             const __nv_bfloat16* __restrict__ Alo,
                                             const __nv_bfloat16* __restrict__ Bhi,
                                             const __nv_bfloat16* __restrict__ Blo,
                                             const float* __restrict__ bias,
                                             float* __restrict__ C, int K, int Ntot) {
    extern __shared__ __align__(16) uint32_t sm[];
    uint32_t sbase = smem_u32(sm);

    int tid = threadIdx.x;
    int wid = tid >> 5, lane = tid & 31;
    int wr = wid >> 2, wc = wid & 3;
    int row0 = blockIdx.y * 128;
    int col0 = blockIdx.x * 128;
    int lq = lane >> 2, lr = lane & 3;

    float acc[4][4][4] = {};
    int nch = K >> 6;

    // prefetch helper (expanded inline): stage tiles [Ahi|Alo|Bhi|Blo]
#define PREFETCH(CH, STG) do {                                                     \
        int _k0 = (CH) << 6;                                                       \
        uint32_t _so = sbase + (STG) * 4 * TILE_W * 4;                             \
        _Pragma("unroll")                                                          \
        for (int _i = 0; _i < 4; _i++) {                                           \
            int _idx = tid + _i * 256;                                             \
            int _r = _idx >> 3, _g = _idx & 7;                                     \
            uint32_t _d = _so + (_r * RS + _g * 4) * 4;                            \
            const __nv_bfloat16* _s = Ahi + (size_t)(row0 + _r) * K + _k0 + _g * 8;\
            CP_ASYNC16(_d, _s);                                                    \
            _d += TILE_W * 4;                                                      \
            _s = Alo + (size_t)(row0 + _r) * K + _k0 + _g * 8;                     \
            CP_ASYNC16(_d, _s);                                                    \
            _d += TILE_W * 4;                                                      \
            _s = Bhi + (size_t)(col0 + _r) * K + _k0 + _g * 8;                     \
            CP_ASYNC16(_d, _s);                                                    \
            _d += TILE_W * 4;                                                      \
            _s = Blo + (size_t)(col0 + _r) * K + _k0 + _g * 8;                     \
            CP_ASYNC16(_d, _s);                                                    \
        }                                                                          \
    } while (0)

    PREFETCH(0, 0);
    CP_COMMIT();

    for (int ch = 0; ch < nch; ch++) {
        if (ch + 1 < nch) {
            PREFETCH(ch + 1, (ch + 1) & 1);
            CP_COMMIT();
            CP_WAIT1();
        } else {
            CP_WAIT0();
        }
        __syncthreads();
        uint32_t* base = sm + (ch & 1) * 4 * TILE_W;
        uint32_t* sAhi = base;
        uint32_t* sAlo = base + TILE_W;
        uint32_t* sBhi = base + 2 * TILE_W;
        uint32_t* sBlo = base + 3 * TILE_W;
#pragma unroll
        for (int ks = 0; ks < 4; ks++) {
            int kw = ks * 8;
            uint32_t bh[4][2], bl[4][2];
#pragma unroll
            for (int nt = 0; nt < 4; nt++) {
                int n = wc * 32 + nt * 8 + lq;
                bh[nt][0] = sBhi[n * RS + kw + lr];
                bh[nt][1] = sBhi[n * RS + kw + lr + 4];
                bl[nt][0] = sBlo[n * RS + kw + lr];
                bl[nt][1] = sBlo[n * RS + kw + lr + 4];
            }
#pragma unroll
            for (int mt = 0; mt < 4; mt++) {
                int r = wr * 64 + mt * 16 + lq;
                uint32_t ah[4], al[4];
                ah[0] = sAhi[r * RS + kw + lr];
                ah[1] = sAhi[(r + 8) * RS + kw + lr];
                ah[2] = sAhi[r * RS + kw + lr + 4];
                ah[3] = sAhi[(r + 8) * RS + kw + lr + 4];
                al[0] = sAlo[r * RS + kw + lr];
                al[1] = sAlo[(r + 8) * RS + kw + lr];
                al[2] = sAlo[r * RS + kw + lr + 4];
                al[3] = sAlo[(r + 8) * RS + kw + lr + 4];
#pragma unroll
                for (int nt = 0; nt < 4; nt++) {
                    mma16816(acc[mt][nt], ah, bh[nt]);
                    mma16816(acc[mt][nt], ah, bl[nt]);
                    mma16816(acc[mt][nt], al, bh[nt]);
                }
            }
        }
        __syncthreads();
    }
#undef PREFETCH
    // epilogue
#pragma unroll
    for (int mt = 0; mt < 4; mt++) {
        int r = row0 + wr * 64 + mt * 16 + lq;
#pragma unroll
        for (int nt = 0; nt < 4; nt++) {
            int c = col0 + wc * 32 + nt * 8 + lr * 2;
            float b0 = bias ? bias[c] : 0.0f;
            float b1 = bias ? bias[c + 1] : 0.0f;
            float2 v0, v1;
            v0.x = acc[mt][nt][0] + b0;
            v0.y = acc[mt][nt][1] + b1;
            v1.x = acc[mt][nt][2] + b0;
            v1.y = acc[mt][nt][3] + b1;
            *(float2*)&C[(size_t)r * Ntot + c] = v0;
            *(float2*)&C[(size_t)(r + 8) * Ntot + c] = v1;
        }
    }
}
#define SMEM_MMA (8 * TILE_W * 4)

// ---------------- column L2 norms for q,k ----------------
__global__ void k_cnpart(const float* __restrict__ qkv) {
    int chunk = blockIdx.x;   // 64 chunks of 128 tokens
    int b = blockIdx.y;
    int tid = threadIdx.x;
    float s0 = 0.f, s1 = 0.f;
    int n0 = chunk * 128;
    for (int n = n0; n < n0 + 128; n++) {
        const float* row = qkv + (size_t)(b * 8192 + n) * 768;
        float v0 = row[tid];
        float v1 = row[256 + tid];
        s0 += v0 * v0;
        s1 += v1 * v1;
    }
    g_cnpart[(b * 64 + chunk) * 512 + tid] = s0;
    g_cnpart[(b * 64 + chunk) * 512 + 256 + tid] = s1;
}

__global__ void k_cnfin() {
    int idx = blockIdx.x * 256 + threadIdx.x;
    int b = idx >> 9, col = idx & 511;
    float s = 0.f;
#pragma unroll
    for (int ch = 0; ch < 64; ch++) s += g_cnpart[(b * 64 + ch) * 512 + col];
    g_rnorm[idx] = 1.0f / fmaxf(sqrtf(s), 1e-12f);
}

// ---------------- kp/vp projections (SIMT split-K) ----------------
__global__ void k_kvproj(const float* __restrict__ qkv, const float* __restrict__ wseq) {
    __shared__ float As[64 * 64];
    __shared__ float Bs[64 * 64];
    __shared__ float sc[64];
    int slice = blockIdx.x;
    int bh = blockIdx.y;
    int kind = blockIdx.z;
    int b = bh >> 2, h = bh & 3;
    int colbase = (kind == 0 ? 256 : 512) + h * 64;
    int tid = threadIdx.x;
    if (tid < 64) sc[tid] = (kind == 0) ? g_rnorm[b * 512 + 256 + h * 64 + tid] : 1.0f;
    __syncthreads();
    int tx = tid & 15, ty = tid >> 4;
    float acc[4][4] = {};
    int nbeg = slice * 1024;
    for (int n0 = nbeg; n0 < nbeg + 1024; n0 += 64) {
#pragma unroll
        for (int i = 0; i < 4; i++) {
            int v = tid + i * 256;
            int r = v >> 4, c4 = (v & 15) << 2;
            float4 av = *(const float4*)&qkv[(size_t)(b * 8192 + n0 + r) * 768 + colbase + c4];
            av.x *= sc[c4 + 0]; av.y *= sc[c4 + 1];
            av.z *= sc[c4 + 2]; av.w *= sc[c4 + 3];
            *(float4*)&As[r * 64 + c4] = av;
            *(float4*)&Bs[r * 64 + c4] = *(const float4*)&wseq[(size_t)(n0 + r) * 64 + c4];
        }
        __syncthreads();
#pragma unroll 16
        for (int nn = 0; nn < 64; nn++) {
            float4 bv = *(const float4*)&Bs[nn * 64 + tx * 4];
#pragma unroll
            for (int i = 0; i < 4; i++) {
                float a = As[nn * 64 + ty * 4 + i];
                acc[i][0] += a * bv.x;
                acc[i][1] += a * bv.y;
                acc[i][2] += a * bv.z;
                acc[i][3] += a * bv.w;
            }
        }
        __syncthreads();
    }
    float* dst = g_kvpart + (size_t)((kind * 16 + bh) * 8 + slice) * 4096;
#pragma unroll
    for (int i = 0; i < 4; i++)
#pragma unroll
        for (int j = 0; j < 4; j++)
            dst[(ty * 4 + i) * 64 + tx * 4 + j] = acc[i][j];
}

__global__ void k_kvred(const float* __restrict__ bseq) {
    int idx = blockIdx.x * 256 + threadIdx.x;
    int kb = idx >> 12;
    int ep = idx & 4095;
    float s = 0.f;
#pragma unroll
    for (int sl = 0; sl < 8; sl++) s += g_kvpart[(size_t)(kb * 8 + sl) * 4096 + ep];
    g_kvp[idx] = s + bseq[ep & 63];
}

// ---------------- fused attention (writes o as bf16 hi/lo) ----------------
__global__ void __launch_bounds__(128) k_attn(const float* __restrict__ qkv,
                                              const float* __restrict__ temp) {
    __shared__ float kpsm[4096];
    __shared__ float vpsm[4096];
    __shared__ float rnsm[64];
    int tid = threadIdx.x;
    int h = blockIdx.y, b = blockIdx.z;
    int bh = b * 4 + h;
    const float4* kp4 = (const float4*)(g_kvp + (size_t)bh * 4096);
    const float4* vp4 = (const float4*)(g_kvp + (size_t)(16 + bh) * 4096);
    for (int i = tid; i < 1024; i += 128) {
        ((float4*)kpsm)[i] = kp4[i];
        ((float4*)vpsm)[i] = vp4[i];
    }
    if (tid < 64) rnsm[tid] = g_rnorm[b * 512 + h * 64 + tid];
    __syncthreads();
    float tv = temp[h];
    int n = blockIdx.x * 128 + tid;
    const float* qrow = qkv + (size_t)(b * 8192 + n) * 768 + h * 64;

    float l[64];
#pragma unroll
    for (int p = 0; p < 64; p++) l[p] = 0.f;
    for (int e = 0; e < 64; e++) {
        float qe = qrow[e] * rnsm[e];
        const float4* krow = (const float4*)(kpsm + e * 64);
#pragma unroll
        for (int p4 = 0; p4 < 16; p4++) {
            float4 kv = krow[p4];
            l[p4 * 4 + 0] += qe * kv.x;
            l[p4 * 4 + 1] += qe * kv.y;
            l[p4 * 4 + 2] += qe * kv.z;
            l[p4 * 4 + 3] += qe * kv.w;
        }
    }
    float m = -1e30f;
#pragma unroll
    for (int p = 0; p < 64; p++) { l[p] *= tv; m = fmaxf(m, l[p]); }
    float s = 0.f;
#pragma unroll
    for (int p = 0; p < 64; p++) { l[p] = __expf(l[p] - m); s += l[p]; }
    float inv = 1.0f / s;

    size_t obase = (size_t)(b * 8192 + n) * 256 + h * 64;
    uint2* ohrow = (uint2*)(g_o_hi + obase);
    uint2* olrow = (uint2*)(g_o_lo + obase);
    for (int e4 = 0; e4 < 16; e4++) {
        float r[4];
#pragma unroll
        for (int ii = 0; ii < 4; ii++) {
            const float4* vrow = (const float4*)(vpsm + (e4 * 4 + ii) * 64);
            float a = 0.f;
#pragma unroll
            for (int p4 = 0; p4 < 16; p4++) {
                float4 vv = vrow[p4];
                a += l[p4 * 4 + 0] * vv.x + l[p4 * 4 + 1] * vv.y
                   + l[p4 * 4 + 2] * vv.z + l[p4 * 4 + 3] * vv.w;
            }
            r[ii] = a * inv;
        }
        uint2 vh, vl;
        vh.x = pack_bf16_hi(r[0], r[1]);
        vh.y = pack_bf16_hi(r[2], r[3]);
        vl.x = pack_bf16_lo(r[0], r[1]);
        vl.y = pack_bf16_lo(r[2], r[3]);
        ohrow[e4] = vh;
        olrow[e4] = vl;
    }
}

// ---------------- LayerNorm stats per token ----------------
__global__ void k_lnstat() {
    int tid = threadIdx.x;
    int warp = tid >> 5, lane = tid & 31;
    int t = blockIdx.x * 8 + warp;     // global token (b*8192+n)
    const float4* row = (const float4*)(g_o2 + (size_t)t * 256);
    float s = 0.f, sq = 0.f;
#pragma unroll
    for (int j = 0; j < 2; j++) {
        float4 v = row[j * 32 + lane];
        s  += v.x + v.y + v.z + v.w;
        sq += v.x * v.x + v.y * v.y + v.z * v.z + v.w * v.w;
    }
#pragma unroll
    for (int off = 16; off; off >>= 1) {
        s  += __shfl_xor_sync(0xffffffffu, s, off);
        sq += __shfl_xor_sync(0xffffffffu, sq, off);
    }
    if (lane == 0) {
        float mu = s * (1.0f / 256.0f);
        float var = sq * (1.0f / 256.0f) - mu * mu;
        g_mu[t] = mu;
        g_rs[t] = rsqrtf(var + 1e-5f);
    }
}

// ---------------- LN apply + residual + restore NCDHW (tiled transpose) ----------------
__global__ void k_lnapply(const float* __restrict__ x, const float* __restrict__ g,
                          const float* __restrict__ be) {
    __shared__ float tl[64 * 65];
    __shared__ float mus[64], rss[64];
    int c0 = blockIdx.x * 64;
    int sp0 = blockIdx.y * 64;
    int b = blockIdx.z;
    int tid = threadIdx.x;
    if (tid < 64) {
        int sp = sp0 + tid;
        int d = sp >> 10, rem = sp & 1023, h = rem >> 5, w = rem & 31;
        int n = h * 256 + w * 8 + d;
        mus[tid] = g_mu[b * 8192 + n];
        rss[tid] = g_rs[b * 8192 + n];
    }
#pragma unroll
    for (int i = 0; i < 16; i++) {
        int idx = i * 256 + tid;
        int s = idx >> 6, c = idx & 63;
        int sp = sp0 + s;
        int d = sp >> 10, rem = sp & 1023, h = rem >> 5, w = rem & 31;
        int n = h * 256 + w * 8 + d;
        tl[s * 65 + c] = g_o2[(size_t)(b * 8192 + n) * 256 + c0 + c];
    }
    __syncthreads();
#pragma unroll
    for (int i = 0; i < 16; i++) {
        int idx = i * 256 + tid;
        int c = idx >> 6, s = idx & 63;
        float gg = g[c0 + c], bb = be[c0 + c];
        float r = (tl[s * 65 + c] - mus[s]) * rss[s] * gg + bb;
        size_t gi = (size_t)(b * 256 + c0 + c) * SPA + sp0 + s;
        g_y[gi] = x[gi] + r;
    }
}

// ---------------- depthwise 3x3x3 SAME conv (bf16 hi/lo output) ----------------
__global__ void k_dwconv(const float* __restrict__ dwk, const float* __restrict__ dwb) {
    __shared__ float tile[10 * 34 * 34];
    __shared__ float wk[27];
    int bc = blockIdx.x;
    int c = bc & 255;
    int tid = threadIdx.x;
    if (tid < 27) wk[tid] = dwk[c * 27 + tid];
    const float* src = g_y + (size_t)bc * SPA;
    for (int i = tid; i < 11560; i += 256) {
        int dz = i / 1156;
        int rem = i - dz * 1156;
        int hy = rem / 34;
        int wx = rem - hy * 34;
        int d = dz - 1, hh = hy - 1, w = wx - 1;
        float val = 0.f;
        if (d >= 0 && d < 8 && hh >= 0 && hh < 32 && w >= 0 && w < 32)
            val = src[d * 1024 + hh * 32 + w];
        tile[i] = val;
    }
    __syncthreads();
    float bias = dwb[c];
    for (int i = tid; i < 8192; i += 256) {
        int d = i >> 10;
        int r = i & 1023;
        int hh = r >> 5, w = r & 31;
        float acc = 0.f;
#pragma unroll
        for (int kd = 0; kd < 3; kd++)
#pragma unroll
            for (int kh = 0; kh < 3; kh++)
#pragma unroll
                for (int kw = 0; kw < 3; kw++)
                    acc += wk[kd * 9 + kh * 3 + kw]
                         * tile[(d + kd) * 1156 + (hh + kh) * 34 + (w + kw)];
        float v = acc + bias;
        __nv_bfloat16 hi = __float2bfloat16(v);
        g_dw_hi[(size_t)bc * SPA + i] = hi;
        g_dw_lo[(size_t)bc * SPA + i] = __float2bfloat16(v - __bfloat162float(hi));
    }
}

// ---------------- pointwise conv on HMMA + bias + final residual ----------------
// out[co][sp] = y + pwb[co] + sum_ci pwk[co][ci]*dw[ci][sp]. Tile 128co x 128sp, K=256.
__global__ void __launch_bounds__(256) k_pwfin(const float* __restrict__ pwb,
                                               float* __restrict__ out) {
    extern __shared__ __align__(16) uint32_t sm[];
    uint32_t* sAhi = sm;               // pwk tiles [co][ciword]
    uint32_t* sAlo = sAhi + TILE_W;
    uint32_t* sBhi = sAlo + TILE_W;    // dw tiles transposed [sp][ciword]
    uint32_t* sBlo = sBhi + TILE_W;

    int tid = threadIdx.x;
    int wid = tid >> 5, lane = tid & 31;
    int wr = wid >> 2, wc = wid & 3;
    int sp0 = blockIdx.x * 128;
    int co0 = blockIdx.y * 128;
    int b = blockIdx.z;
    int lq = lane >> 2, lr = lane & 3;

    float acc[4][4][4] = {};

    for (int ci0 = 0; ci0 < 256; ci0 += 64) {
        // A: pwk hi/lo [co0..+128][ci0..+64] — direct K-major copy
#pragma unroll
        for (int i = 0; i < 4; i++) {
            int idx = tid + i * 256;
            int r = idx >> 3, gq = idx & 7;
            *(uint4*)&sAhi[r * RS + gq * 4] =
                *(const uint4*)&g_pwk_hi[(co0 + r) * 256 + ci0 + gq * 8];
            *(uint4*)&sAlo[r * RS + gq * 4] =
                *(const uint4*)&g_pwk_lo[(co0 + r) * 256 + ci0 + gq * 8];
        }
        // B: dw [ci][sp] -> smem [sp][ciword] via byte_perm pair packing
#pragma unroll
        for (int jl = 0; jl < 4; jl++) {
            int j = jl * 8 + wid;                   // ci word 0..31
            size_t rbase = (size_t)(b * 256 + ci0 + 2 * j) * SPA + sp0;
#pragma unroll
            for (int sh = 0; sh < 2; sh++) {
                int slp = (sh * 32 + lane) * 2;     // local sp (even)
                uint32_t u0 = *(const uint32_t*)(g_dw_hi + rbase + slp);
                uint32_t u1 = *(const uint32_t*)(g_dw_hi + rbase + SPA + slp);
                sBhi[slp * RS + j]       = __byte_perm(u0, u1, 0x5410);
                sBhi[(slp + 1) * RS + j] = __byte_perm(u0, u1, 0x7632);
                u0 = *(const uint32_t*)(g_dw_lo + rbase + slp);
                u1 = *(const uint32_t*)(g_dw_lo + rbase + SPA + slp);
                sBlo[slp * RS + j]       = __byte_perm(u0, u1, 0x5410);
                sBlo[(slp + 1) * RS + j] = __byte_perm(u0, u1, 0x7632);
            }
        }
        __syncthreads();
#pragma unroll
        for (int ks = 0; ks < 4; ks++) {
            int kw = ks * 8;
            uint32_t bh[4][2], bl[4][2];
#pragma unroll
            for (int nt = 0; nt < 4; nt++) {
                int n = wc * 32 + nt * 8 + lq;
                bh[nt][0] = sBhi[n * RS + kw + lr];
                bh[nt][1] = sBhi[n * RS + kw + lr + 4];
                bl[nt][0] = sBlo[n * RS + kw + lr];
                bl[nt][1] = sBlo[n * RS + kw + lr + 4];
            }
#pragma unroll
            for (int mt = 0; mt < 4; mt++) {
                int r = wr * 64 + mt * 16 + lq;
                uint32_t ah[4], al[4];
                ah[0] = sAhi[r * RS + kw + lr];
                ah[1] = sAhi[(r + 8) * RS + kw + lr];
                ah[2] = sAhi[r * RS + kw + lr + 4];
                ah[3] = sAhi[(r + 8) * RS + kw + lr + 4];
                al[0] = sAlo[r * RS + kw + lr];
                al[1] = sAlo[(r + 8) * RS + kw + lr];
                al[2] = sAlo[r * RS + kw + lr + 4];
                al[3] = sAlo[(r + 8) * RS + kw + lr + 4];
#pragma unroll
                for (int nt = 0; nt < 4; nt++) {
                    mma16816(acc[mt][nt], ah, bh[nt]);
                    mma16816(acc[mt][nt], ah, bl[nt]);
                    mma16816(acc[mt][nt], al, bh[nt]);
                }
            }
        }
        __syncthreads();
    }
    // epilogue: out = y + pwb[co] + acc
#pragma unroll
    for (int mt = 0; mt < 4; mt++) {
        int r = co0 + wr * 64 + mt * 16 + lq;
        float bb0 = pwb[r], bb1 = pwb[r + 8];
#pragma unroll
        for (int nt = 0; nt < 4; nt++) {
            int c = sp0 + wc * 32 + nt * 8 + lr * 2;
            size_t i0 = (size_t)(b * 256 + r) * SPA + c;
            size_t i1 = (size_t)(b * 256 + r + 8) * SPA + c;
            float2 y0 = *(const float2*)&g_y[i0];
            float2 y1 = *(const float2*)&g_y[i1];
            float2 v0, v1;
            v0.x = acc[mt][nt][0] + bb0 + y0.x;
            v0.y = acc[mt][nt][1] + bb0 + y0.y;
            v1.x = acc[mt][nt][2] + bb1 + y1.x;
            v1.y = acc[mt][nt][3] + bb1 + y1.y;
            *(float2*)&out[i0] = v0;
            *(float2*)&out[i1] = v1;
        }
    }
}
#define SMEM_PW (4 * TILE_W * 4)

// ---------------- launch ----------------
extern "C" void kernel_launch(void* const* d_in, const int* in_sizes, int n_in,
                              void* d_out, int out_size) {
    (void)in_sizes; (void)n_in; (void)out_size;
    const float* x    = (const float*)d_in[0];
    const float* wqkv = (const float*)d_in[1];
    const float* wseq = (const float*)d_in[2];
    const float* bseq = (const float*)d_in[3];
    const float* temp = (const float*)d_in[4];
    const float* wout = (const float*)d_in[5];
    const float* bout = (const float*)d_in[6];
    const float* lng  = (const float*)d_in[7];
    const float* lnb  = (const float*)d_in[8];
    const float* dwk  = (const float*)d_in[9];
    const float* dwb  = (const float*)d_in[10];
    const float* pwk  = (const float*)d_in[11];
    const float* pwb  = (const float*)d_in[12];
    float* out = (float*)d_out;

    float *qkv, *o2;
    __nv_bfloat16 *t_hi, *t_lo, *o_hi, *o_lo;
    __nv_bfloat16 *wqkvT_hi, *wqkvT_lo, *woutT_hi, *woutT_lo, *pwk_hi, *pwk_lo;
    cudaGetSymbolAddress((void**)&qkv, g_qkv);
    cudaGetSymbolAddress((void**)&o2,  g_o2);
    cudaGetSymbolAddress((void**)&t_hi, g_t_hi);
    cudaGetSymbolAddress((void**)&t_lo, g_t_lo);
    cudaGetSymbolAddress((void**)&o_hi, g_o_hi);
    cudaGetSymbolAddress((void**)&o_lo, g_o_lo);
    cudaGetSymbolAddress((void**)&wqkvT_hi, g_wqkvT_hi);
    cudaGetSymbolAddress((void**)&wqkvT_lo, g_wqkvT_lo);
    cudaGetSymbolAddress((void**)&woutT_hi, g_woutT_hi);
    cudaGetSymbolAddress((void**)&woutT_lo, g_woutT_lo);
    cudaGetSymbolAddress((void**)&pwk_hi, g_pwk_hi);
    cudaGetSymbolAddress((void**)&pwk_lo, g_pwk_lo);

    cudaFuncSetAttribute(k_mma, cudaFuncAttributeMaxDynamicSharedMemorySize, SMEM_MMA);
    cudaFuncSetAttribute(k_pwfin, cudaFuncAttributeMaxDynamicSharedMemorySize, SMEM_PW);

    // 1. transpose to token-major bf16 hi/lo
    k_transpose<<<dim3(4, 128, 4), 256>>>(x);
    // 2. weight prep
    k_wprep<<<768, 256>>>(wqkv, wqkvT_hi, wqkvT_lo, 256, 768);
    k_wprep<<<256, 256>>>(wout, woutT_hi, woutT_lo, 256, 256);
    k_wprep_nt<<<256, 256>>>(pwk, pwk_hi, pwk_lo, 256 * 256);
    // 3. QKV GEMM (HMMA, cp.async pipelined)
    k_mma<<<dim3(6, 256), 256, SMEM_MMA>>>(t_hi, t_lo, wqkvT_hi, wqkvT_lo, nullptr, qkv, 256, 768);
    // 4. column L2 norms
    k_cnpart<<<dim3(64, 4), 256>>>(qkv);
    k_cnfin<<<8, 256>>>();
    // 5. kp/vp projections + reduce
    k_kvproj<<<dim3(8, 16, 2), 256>>>(qkv, wseq);
    k_kvred<<<512, 256>>>(bseq);
    // 6. fused attention (bf16 hi/lo output)
    k_attn<<<dim3(64, 4, 4), 128>>>(qkv, temp);
    // 7. output projection (HMMA)
    k_mma<<<dim3(2, 256), 256, SMEM_MMA>>>(o_hi, o_lo, woutT_hi, woutT_lo, bout, o2, 256, 256);
    // 8. LayerNorm stats + apply/residual/transpose
    k_lnstat<<<4096, 256>>>();
    k_lnapply<<<dim3(4, 128, 4), 256>>>(x, lng, lnb);
    // 9. depthwise conv (bf16 hi/lo out)
    k_dwconv<<<1024, 256>>>(dwk, dwb);
    // 10. pointwise conv (HMMA) + bias + final residual
    k_pwfin<<<dim3(64, 2, 4), 256, SMEM_PW>>>(pwb, out);
}

// round 9
// speedup vs baseline: 1.7607x; 1.0508x over previous
#include <cuda_runtime.h>
#include <cuda_bf16.h>
#include <math.h>
#include <stdint.h>

// Problem constants
#define BQ   4
#define CC   256
#define NHEAD 4
#define PP   64
#define NN   8192
#define SPA  8192

// ---------------- scratch (device globals) ----------------
__device__ __align__(128) __nv_bfloat16 g_t_hi[(size_t)BQ * NN * CC];
__device__ __align__(128) __nv_bfloat16 g_t_lo[(size_t)BQ * NN * CC];
__device__ float g_qkv [(size_t)BQ * NN * 3 * CC];
__device__ float g_cnpart[256 * 512];
__device__ float g_rnorm [BQ * 512];
__device__ float g_kvpart[2 * 16 * 16 * 4096];
__device__ float g_kvp   [2 * 16 * 4096];
__device__ __align__(128) __nv_bfloat16 g_o_hi[(size_t)BQ * NN * CC];
__device__ __align__(128) __nv_bfloat16 g_o_lo[(size_t)BQ * NN * CC];
__device__ float g_o2  [(size_t)BQ * NN * CC];
__device__ float g_mu  [BQ * NN];
__device__ float g_rs  [BQ * NN];
__device__ float g_y   [(size_t)BQ * CC * SPA];
__device__ __align__(128) __nv_bfloat16 g_dw_hi[(size_t)BQ * CC * SPA];
__device__ __align__(128) __nv_bfloat16 g_dw_lo[(size_t)BQ * CC * SPA];
// transposed bf16 hi/lo weights [N][K]
__device__ __align__(128) __nv_bfloat16 g_wqkvT_hi[768 * 256];
__device__ __align__(128) __nv_bfloat16 g_wqkvT_lo[768 * 256];
__device__ __align__(128) __nv_bfloat16 g_woutT_hi[256 * 256];
__device__ __align__(128) __nv_bfloat16 g_woutT_lo[256 * 256];
__device__ __align__(128) __nv_bfloat16 g_pwk_hi[256 * 256];
__device__ __align__(128) __nv_bfloat16 g_pwk_lo[256 * 256];
__device__ __align__(128) __nv_bfloat16 g_wsT_hi[64 * 8192];
__device__ __align__(128) __nv_bfloat16 g_wsT_lo[64 * 8192];

// ---------------- helpers ----------------
__device__ __forceinline__ uint32_t pack_bf16_hi(float a, float b) {
    __nv_bfloat16 ha = __float2bfloat16(a);
    __nv_bfloat16 hb = __float2bfloat16(b);
    return ((uint32_t)__bfloat16_as_ushort(hb) << 16) | __bfloat16_as_ushort(ha);
}
__device__ __forceinline__ uint32_t pack_bf16_lo(float a, float b) {
    __nv_bfloat16 ha = __float2bfloat16(a);
    __nv_bfloat16 hb = __float2bfloat16(b);
    __nv_bfloat16 la = __float2bfloat16(a - __bfloat162float(ha));
    __nv_bfloat16 lb = __float2bfloat16(b - __bfloat162float(hb));
    return ((uint32_t)__bfloat16_as_ushort(lb) << 16) | __bfloat16_as_ushort(la);
}

__device__ __forceinline__ void mma16816(float* d, const uint32_t* a, const uint32_t* b) {
    asm volatile(
        "mma.sync.aligned.m16n8k16.row.col.f32.bf16.bf16.f32 "
        "{%0,%1,%2,%3}, {%4,%5,%6,%7}, {%8,%9}, {%0,%1,%2,%3};"
        : "+f"(d[0]), "+f"(d[1]), "+f"(d[2]), "+f"(d[3])
        : "r"(a[0]), "r"(a[1]), "r"(a[2]), "r"(a[3]), "r"(b[0]), "r"(b[1]));
}

__device__ __forceinline__ uint32_t smem_u32(const void* p) {
    uint32_t a;
    asm("{ .reg .u64 t; cvta.to.shared.u64 t, %1; cvt.u32.u64 %0, t; }" : "=r"(a) : "l"(p));
    return a;
}
#define CP_ASYNC16(dst, src) \
    asm volatile("cp.async.cg.shared.global [%0], [%1], 16;" :: "r"(dst), "l"(src) : "memory")
#define CP_COMMIT() asm volatile("cp.async.commit_group;" ::: "memory")
#define CP_WAIT1()  asm volatile("cp.async.wait_group 1;" ::: "memory")
#define CP_WAIT0()  asm volatile("cp.async.wait_group 0;" ::: "memory")

#define RS 36                 // smem row stride in words (144B; 16B aligned; conflict-free frags)
#define TILE_W (128 * RS)     // words per 128-row tile

// ---------------- K0: transpose x (NCDHW) -> t_hi/lo [B,N,C] bf16 ----------------
__global__ void k_transpose(const float* __restrict__ x) {
    __shared__ float tile[64 * 65];
    int c0 = blockIdx.x * 64;
    int sp0 = blockIdx.y * 64;
    int b = blockIdx.z;
    int tid = threadIdx.x;
#pragma unroll
    for (int i = 0; i < 16; i++) {
        int idx = i * 256 + tid;
        int c = idx >> 6, s = idx & 63;
        tile[c * 65 + s] = x[(size_t)(b * 256 + c0 + c) * SPA + sp0 + s];
    }
    __syncthreads();
#pragma unroll
    for (int i = 0; i < 16; i++) {
        int idx = i * 256 + tid;
        int s = idx >> 6, c = idx & 63;
        int sp = sp0 + s;
        int d = sp >> 10, rem = sp & 1023, h = rem >> 5, w = rem & 31;
        int n = h * 256 + w * 8 + d;
        float v = tile[c * 65 + s];
        __nv_bfloat16 hi = __float2bfloat16(v);
        size_t gi = (size_t)(b * 8192 + n) * 256 + c0 + c;
        g_t_hi[gi] = hi;
        g_t_lo[gi] = __float2bfloat16(v - __bfloat162float(hi));
    }
}

// ---------------- weight prep: fp32 [K][N] -> bf16 hi/lo [N][K] ----------------
__global__ void k_wprep(const float* __restrict__ w, __nv_bfloat16* __restrict__ thi,
                        __nv_bfloat16* __restrict__ tlo, int K, int Nn) {
    int idx = blockIdx.x * 256 + threadIdx.x;
    if (idx >= K * Nn) return;
    int k = idx / Nn, n = idx - k * Nn;
    float a = w[idx];
    __nv_bfloat16 h = __float2bfloat16(a);
    tlo[n * K + k] = __float2bfloat16(a - __bfloat162float(h));
    thi[n * K + k] = h;
}
// no-transpose variant (pwk is already [co][ci] = [M][K])
__global__ void k_wprep_nt(const float* __restrict__ w, __nv_bfloat16* __restrict__ thi,
                           __nv_bfloat16* __restrict__ tlo, int total) {
    int idx = blockIdx.x * 256 + threadIdx.x;
    if (idx >= total) return;
    float a = w[idx];
    __nv_bfloat16 h = __float2bfloat16(a);
    thi[idx] = h;
    tlo[idx] = __float2bfloat16(a - __bfloat162float(h));
}

// ---------------- HMMA bf16-split GEMM, cp.async double-buffered ----------------
// A hi/lo bf16 [M][K]; B hi/lo bf16 [Ntot][K]. CTA tile 128x128, K-chunk 64.
__global__ void __launch_bounds__(256) k_mma(const __nv_bfloat16* __restrict__ Ahi,
                                             const __nv_bfloat16* __restrict__ Alo,
                                             const __nv_bfloat16* __restrict__ Bhi,
                                             const __nv_bfloat16* __restrict__ Blo,
                                             const float* __restrict__ bias,
                                             float* __restrict__ C, int K, int Ntot) {
    extern __shared__ __align__(16) uint32_t sm[];
    uint32_t sbase = smem_u32(sm);

    int tid = threadIdx.x;
    int wid = tid >> 5, lane = tid & 31;
    int wr = wid >> 2, wc = wid & 3;
    int row0 = blockIdx.y * 128;
    int col0 = blockIdx.x * 128;
    int lq = lane >> 2, lr = lane & 3;

    float acc[4][4][4] = {};
    int nch = K >> 6;

    // prefetch helper (expanded inline): stage tiles [Ahi|Alo|Bhi|Blo]
#define PREFETCH(CH, STG) do {                                                     \
        int _k0 = (CH) << 6;                                                       \
        uint32_t _so = sbase + (STG) * 4 * TILE_W * 4;                             \
        _Pragma("unroll")                                                          \
        for (int _i = 0; _i < 4; _i++) {                                           \
            int _idx = tid + _i * 256;                                             \
            int _r = _idx >> 3, _g = _idx & 7;                                     \
            uint32_t _d = _so + (_r * RS + _g * 4) * 4;                            \
            const __nv_bfloat16* _s = Ahi + (size_t)(row0 + _r) * K + _k0 + _g * 8;\
            CP_ASYNC16(_d, _s);                                                    \
            _d += TILE_W * 4;                                                      \
            _s = Alo + (size_t)(row0 + _r) * K + _k0 + _g * 8;                     \
            CP_ASYNC16(_d, _s);                                                    \
            _d += TILE_W * 4;                                                      \
            _s = Bhi + (size_t)(col0 + _r) * K + _k0 + _g * 8;                     \
            CP_ASYNC16(_d, _s);                                                    \
            _d += TILE_W * 4;                                                      \
            _s = Blo + (size_t)(col0 + _r) * K + _k0 + _g * 8;                     \
            CP_ASYNC16(_d, _s);                                                    \
        }                                                                          \
    } while (0)

    PREFETCH(0, 0);
    CP_COMMIT();

    for (int ch = 0; ch < nch; ch++) {
        if (ch + 1 < nch) {
            PREFETCH(ch + 1, (ch + 1) & 1);
            CP_COMMIT();
            CP_WAIT1();
        } else {
            CP_WAIT0();
        }
        __syncthreads();
        uint32_t* base = sm + (ch & 1) * 4 * TILE_W;
        uint32_t* sAhi = base;
        uint32_t* sAlo = base + TILE_W;
        uint32_t* sBhi = base + 2 * TILE_W;
        uint32_t* sBlo = base + 3 * TILE_W;
#pragma unroll
        for (int ks = 0; ks < 4; ks++) {
            int kw = ks * 8;
            uint32_t bh[4][2], bl[4][2];
#pragma unroll
            for (int nt = 0; nt < 4; nt++) {
                int n = wc * 32 + nt * 8 + lq;
                bh[nt][0] = sBhi[n * RS + kw + lr];
                bh[nt][1] = sBhi[n * RS + kw + lr + 4];
                bl[nt][0] = sBlo[n * RS + kw + lr];
                bl[nt][1] = sBlo[n * RS + kw + lr + 4];
            }
#pragma unroll
            for (int mt = 0; mt < 4; mt++) {
                int r = wr * 64 + mt * 16 + lq;
                uint32_t ah[4], al[4];
                ah[0] = sAhi[r * RS + kw + lr];
                ah[1] = sAhi[(r + 8) * RS + kw + lr];
                ah[2] = sAhi[r * RS + kw + lr + 4];
                ah[3] = sAhi[(r + 8) * RS + kw + lr + 4];
                al[0] = sAlo[r * RS + kw + lr];
                al[1] = sAlo[(r + 8) * RS + kw + lr];
                al[2] = sAlo[r * RS + kw + lr + 4];
                al[3] = sAlo[(r + 8) * RS + kw + lr + 4];
#pragma unroll
                for (int nt = 0; nt < 4; nt++) {
                    mma16816(acc[mt][nt], ah, bh[nt]);
                    mma16816(acc[mt][nt], ah, bl[nt]);
                    mma16816(acc[mt][nt], al, bh[nt]);
                }
            }
        }
        __syncthreads();
    }
#undef PREFETCH
    // epilogue
#pragma unroll
    for (int mt = 0; mt < 4; mt++) {
        int r = row0 + wr * 64 + mt * 16 + lq;
#pragma unroll
        for (int nt = 0; nt < 4; nt++) {
            int c = col0 + wc * 32 + nt * 8 + lr * 2;
            float b0 = bias ? bias[c] : 0.0f;
            float b1 = bias ? bias[c + 1] : 0.0f;
            float2 v0, v1;
            v0.x = acc[mt][nt][0] + b0;
            v0.y = acc[mt][nt][1] + b1;
            v1.x = acc[mt][nt][2] + b0;
            v1.y = acc[mt][nt][3] + b1;
            *(float2*)&C[(size_t)r * Ntot + c] = v0;
            *(float2*)&C[(size_t)(r + 8) * Ntot + c] = v1;
        }
    }
}
#define SMEM_MMA (8 * TILE_W * 4)

// ---------------- column L2 norms for q,k ----------------
__global__ void k_cnpart(const float* __restrict__ qkv) {
    int chunk = blockIdx.x;   // 64 chunks of 128 tokens
    int b = blockIdx.y;
    int tid = threadIdx.x;
    float s0 = 0.f, s1 = 0.f;
    int n0 = chunk * 128;
    for (int n = n0; n < n0 + 128; n++) {
        const float* row = qkv + (size_t)(b * 8192 + n) * 768;
        float v0 = row[tid];
        float v1 = row[256 + tid];
        s0 += v0 * v0;
        s1 += v1 * v1;
    }
    g_cnpart[(b * 64 + chunk) * 512 + tid] = s0;
    g_cnpart[(b * 64 + chunk) * 512 + 256 + tid] = s1;
}

__global__ void k_cnfin() {
    int idx = blockIdx.x * 256 + threadIdx.x;
    int b = idx >> 9, col = idx & 511;
    float s = 0.f;
#pragma unroll
    for (int ch = 0; ch < 64; ch++) s += g_cnpart[(b * 64 + ch) * 512 + col];
    g_rnorm[idx] = 1.0f / fmaxf(sqrtf(s), 1e-12f);
}

// ---------------- kp/vp projections on HMMA ----------------
// out[e][p] = sum_n qkv[n][colbase+e] * wseq[n][p]  (normalization applied in kvred)
// grid (16 K-slices, 16 bh, 2 kind), 128 threads. K-slice = 512 tokens, chunk = 64.
#define SMEM_KV (64 * 65 * 4 + 4 * 64 * RS * 4)
__global__ void __launch_bounds__(128) k_kvproj(const float* __restrict__ qkv,
                                                const __nv_bfloat16* __restrict__ wsThi,
                                                const __nv_bfloat16* __restrict__ wsTlo) {
    extern __shared__ __align__(16) char smraw[];
    float* sF = (float*)smraw;                       // fp32 stage [n][e], stride 65
    uint32_t* sAhi = (uint32_t*)(smraw + 64 * 65 * 4);
    uint32_t* sAlo = sAhi + 64 * RS;
    uint32_t* sBhi = sAlo + 64 * RS;
    uint32_t* sBlo = sBhi + 64 * RS;

    int slice = blockIdx.x;
    int bh = blockIdx.y;
    int kind = blockIdx.z;
    int b = bh >> 2, h = bh & 3;
    int colbase = (kind == 0 ? 256 : 512) + h * 64;
    int tid = threadIdx.x;
    int wid = tid >> 5, lane = tid & 31;
    int wr = wid >> 1, wc = wid & 1;        // 2x2 warp grid, warp tile 32x32
    int lq = lane >> 2, lr = lane & 3;
    int wa = lane & 7, wb = lane >> 3;      // conflict-free convert mapping

    float acc[2][4][4] = {};

    int nbeg = slice * 512;
    for (int ch = 0; ch < 8; ch++) {
        int n0 = nbeg + ch * 64;
        // stage qkv tile [64n][64e] fp32 (coalesced loads, scalar smem stores)
#pragma unroll
        for (int i = 0; i < 8; i++) {
            int idx = tid + i * 128;
            int r = idx >> 4, c4 = idx & 15;
            float4 v = *(const float4*)&qkv[(size_t)(b * 8192 + n0 + r) * 768 + colbase + c4 * 4];
            float* dst = &sF[r * 65 + c4 * 4];
            dst[0] = v.x; dst[1] = v.y; dst[2] = v.z; dst[3] = v.w;
        }
        // B frag: wseq^T hi/lo [p][n] K-major — direct copy
#pragma unroll
        for (int i = 0; i < 4; i++) {
            int idx = tid + i * 128;
            int r = idx >> 3, q = idx & 7;
            *(uint4*)&sBhi[r * RS + q * 4] = *(const uint4*)&wsThi[(size_t)r * 8192 + n0 + q * 8];
            *(uint4*)&sBlo[r * RS + q * 4] = *(const uint4*)&wsTlo[(size_t)r * 8192 + n0 + q * 8];
        }
        __syncthreads();
        // convert-transpose fp32 [n][e] -> bf16x2 frags [e][n-word]
#pragma unroll
        for (int ia = 0; ia < 2; ia++) {
            int e = wid * 16 + 8 * ia + wa;
#pragma unroll
            for (int inp = 0; inp < 8; inp++) {
                int np = 4 * inp + wb;
                float v0 = sF[(2 * np) * 65 + e];
                float v1 = sF[(2 * np + 1) * 65 + e];
                sAhi[e * RS + np] = pack_bf16_hi(v0, v1);
                sAlo[e * RS + np] = pack_bf16_lo(v0, v1);
            }
        }
        __syncthreads();
#pragma unroll
        for (int ks = 0; ks < 4; ks++) {
            int kw = ks * 8;
            uint32_t bhf[4][2], blf[4][2];
#pragma unroll
            for (int nt = 0; nt < 4; nt++) {
                int nrow = wc * 32 + nt * 8 + lq;
                bhf[nt][0] = sBhi[nrow * RS + kw + lr];
                bhf[nt][1] = sBhi[nrow * RS + kw + lr + 4];
                blf[nt][0] = sBlo[nrow * RS + kw + lr];
                blf[nt][1] = sBlo[nrow * RS + kw + lr + 4];
            }
#pragma unroll
            for (int mt = 0; mt < 2; mt++) {
                int r = wr * 32 + mt * 16 + lq;
                uint32_t ah[4], al[4];
                ah[0] = sAhi[r * RS + kw + lr];
                ah[1] = sAhi[(r + 8) * RS + kw + lr];
                ah[2] = sAhi[r * RS + kw + lr + 4];
                ah[3] = sAhi[(r + 8) * RS + kw + lr + 4];
                al[0] = sAlo[r * RS + kw + lr];
                al[1] = sAlo[(r + 8) * RS + kw + lr];
                al[2] = sAlo[r * RS + kw + lr + 4];
                al[3] = sAlo[(r + 8) * RS + kw + lr + 4];
#pragma unroll
                for (int nt = 0; nt < 4; nt++) {
                    mma16816(acc[mt][nt], ah, bhf[nt]);
                    mma16816(acc[mt][nt], ah, blf[nt]);
                    mma16816(acc[mt][nt], al, bhf[nt]);
                }
            }
        }
        __syncthreads();
    }
    // store partial [64e][64p]
    float* dst = g_kvpart + (size_t)((kind * 16 + bh) * 16 + slice) * 4096;
#pragma unroll
    for (int mt = 0; mt < 2; mt++) {
        int e = wr * 32 + mt * 16 + lq;
#pragma unroll
        for (int nt = 0; nt < 4; nt++) {
            int p = wc * 32 + nt * 8 + lr * 2;
            *(float2*)&dst[e * 64 + p] = make_float2(acc[mt][nt][0], acc[mt][nt][1]);
            *(float2*)&dst[(e + 8) * 64 + p] = make_float2(acc[mt][nt][2], acc[mt][nt][3]);
        }
    }
}

__global__ void k_kvred(const float* __restrict__ bseq) {
    int idx = blockIdx.x * 256 + threadIdx.x;   // 131072 total
    int kb = idx >> 12;                          // kind*16+bh
    int ep = idx & 4095;
    float s = 0.f;
#pragma unroll
    for (int sl = 0; sl < 16; sl++) s += g_kvpart[(size_t)(kb * 16 + sl) * 4096 + ep];
    int kind = kb >> 4, bh = kb & 15;
    int b = bh >> 2, h = bh & 3;
    if (kind == 0) s *= g_rnorm[b * 512 + 256 + h * 64 + (ep >> 6)];
    g_kvp[idx] = s + bseq[ep & 63];
}

// ---------------- fused attention (writes o as bf16 hi/lo) ----------------
__global__ void __launch_bounds__(128) k_attn(const float* __restrict__ qkv,
                                              const float* __restrict__ temp) {
    __shared__ float kpsm[4096];
    __shared__ float vpsm[4096];
    __shared__ float rnsm[64];
    int tid = threadIdx.x;
    int h = blockIdx.y, b = blockIdx.z;
    int bh = b * 4 + h;
    const float4* kp4 = (const float4*)(g_kvp + (size_t)bh * 4096);
    const float4* vp4 = (const float4*)(g_kvp + (size_t)(16 + bh) * 4096);
    for (int i = tid; i < 1024; i += 128) {
        ((float4*)kpsm)[i] = kp4[i];
        ((float4*)vpsm)[i] = vp4[i];
    }
    if (tid < 64) rnsm[tid] = g_rnorm[b * 512 + h * 64 + tid];
    __syncthreads();
    float tv = temp[h];
    int n = blockIdx.x * 128 + tid;
    const float* qrow = qkv + (size_t)(b * 8192 + n) * 768 + h * 64;

    float l[64];
#pragma unroll
    for (int p = 0; p < 64; p++) l[p] = 0.f;
    for (int e = 0; e < 64; e++) {
        float qe = qrow[e] * rnsm[e];
        const float4* krow = (const float4*)(kpsm + e * 64);
#pragma unroll
        for (int p4 = 0; p4 < 16; p4++) {
            float4 kv = krow[p4];
            l[p4 * 4 + 0] += qe * kv.x;
            l[p4 * 4 + 1] += qe * kv.y;
            l[p4 * 4 + 2] += qe * kv.z;
            l[p4 * 4 + 3] += qe * kv.w;
        }
    }
    float m = -1e30f;
#pragma unroll
    for (int p = 0; p < 64; p++) { l[p] *= tv; m = fmaxf(m, l[p]); }
    float s = 0.f;
#pragma unroll
    for (int p = 0; p < 64; p++) { l[p] = __expf(l[p] - m); s += l[p]; }
    float inv = 1.0f / s;

    size_t obase = (size_t)(b * 8192 + n) * 256 + h * 64;
    uint2* ohrow = (uint2*)(g_o_hi + obase);
    uint2* olrow = (uint2*)(g_o_lo + obase);
    for (int e4 = 0; e4 < 16; e4++) {
        float r[4];
#pragma unroll
        for (int ii = 0; ii < 4; ii++) {
            const float4* vrow = (const float4*)(vpsm + (e4 * 4 + ii) * 64);
            float a = 0.f;
#pragma unroll
            for (int p4 = 0; p4 < 16; p4++) {
                float4 vv = vrow[p4];
                a += l[p4 * 4 + 0] * vv.x + l[p4 * 4 + 1] * vv.y
                   + l[p4 * 4 + 2] * vv.z + l[p4 * 4 + 3] * vv.w;
            }
            r[ii] = a * inv;
        }
        uint2 vh, vl;
        vh.x = pack_bf16_hi(r[0], r[1]);
        vh.y = pack_bf16_hi(r[2], r[3]);
        vl.x = pack_bf16_lo(r[0], r[1]);
        vl.y = pack_bf16_lo(r[2], r[3]);
        ohrow[e4] = vh;
        olrow[e4] = vl;
    }
}

// ---------------- LayerNorm stats per token ----------------
__global__ void k_lnstat() {
    int tid = threadIdx.x;
    int warp = tid >> 5, lane = tid & 31;
    int t = blockIdx.x * 8 + warp;     // global token (b*8192+n)
    const float4* row = (const float4*)(g_o2 + (size_t)t * 256);
    float s = 0.f, sq = 0.f;
#pragma unroll
    for (int j = 0; j < 2; j++) {
        float4 v = row[j * 32 + lane];
        s  += v.x + v.y + v.z + v.w;
        sq += v.x * v.x + v.y * v.y + v.z * v.z + v.w * v.w;
    }
#pragma unroll
    for (int off = 16; off; off >>= 1) {
        s  += __shfl_xor_sync(0xffffffffu, s, off);
        sq += __shfl_xor_sync(0xffffffffu, sq, off);
    }
    if (lane == 0) {
        float mu = s * (1.0f / 256.0f);
        float var = sq * (1.0f / 256.0f) - mu * mu;
        g_mu[t] = mu;
        g_rs[t] = rsqrtf(var + 1e-5f);
    }
}

// ---------------- LN apply + residual + restore NCDHW (tiled transpose) ----------------
__global__ void k_lnapply(const float* __restrict__ x, const float* __restrict__ g,
                          const float* __restrict__ be) {
    __shared__ float tl[64 * 65];
    __shared__ float mus[64], rss[64];
    int c0 = blockIdx.x * 64;
    int sp0 = blockIdx.y * 64;
    int b = blockIdx.z;
    int tid = threadIdx.x;
    if (tid < 64) {
        int sp = sp0 + tid;
        int d = sp >> 10, rem = sp & 1023, h = rem >> 5, w = rem & 31;
        int n = h * 256 + w * 8 + d;
        mus[tid] = g_mu[b * 8192 + n];
        rss[tid] = g_rs[b * 8192 + n];
    }
#pragma unroll
    for (int i = 0; i < 16; i++) {
        int idx = i * 256 + tid;
        int s = idx >> 6, c = idx & 63;
        int sp = sp0 + s;
        int d = sp >> 10, rem = sp & 1023, h = rem >> 5, w = rem & 31;
        int n = h * 256 + w * 8 + d;
        tl[s * 65 + c] = g_o2[(size_t)(b * 8192 + n) * 256 + c0 + c];
    }
    __syncthreads();
#pragma unroll
    for (int i = 0; i < 16; i++) {
        int idx = i * 256 + tid;
        int c = idx >> 6, s = idx & 63;
        float gg = g[c0 + c], bb = be[c0 + c];
        float r = (tl[s * 65 + c] - mus[s]) * rss[s] * gg + bb;
        size_t gi = (size_t)(b * 256 + c0 + c) * SPA + sp0 + s;
        g_y[gi] = x[gi] + r;
    }
}

// ---------------- depthwise 3x3x3 SAME conv (bf16 hi/lo output) ----------------
__global__ void k_dwconv(const float* __restrict__ dwk, const float* __restrict__ dwb) {
    __shared__ float tile[10 * 34 * 34];
    __shared__ float wk[27];
    int bc = blockIdx.x;
    int c = bc & 255;
    int tid = threadIdx.x;
    if (tid < 27) wk[tid] = dwk[c * 27 + tid];
    const float* src = g_y + (size_t)bc * SPA;
    for (int i = tid; i < 11560; i += 256) {
        int dz = i / 1156;
        int rem = i - dz * 1156;
        int hy = rem / 34;
        int wx = rem - hy * 34;
        int d = dz - 1, hh = hy - 1, w = wx - 1;
        float val = 0.f;
        if (d >= 0 && d < 8 && hh >= 0 && hh < 32 && w >= 0 && w < 32)
            val = src[d * 1024 + hh * 32 + w];
        tile[i] = val;
    }
    __syncthreads();
    float bias = dwb[c];
    for (int i = tid; i < 8192; i += 256) {
        int d = i >> 10;
        int r = i & 1023;
        int hh = r >> 5, w = r & 31;
        float acc = 0.f;
#pragma unroll
        for (int kd = 0; kd < 3; kd++)
#pragma unroll
            for (int kh = 0; kh < 3; kh++)
#pragma unroll
                for (int kw = 0; kw < 3; kw++)
                    acc += wk[kd * 9 + kh * 3 + kw]
                         * tile[(d + kd) * 1156 + (hh + kh) * 34 + (w + kw)];
        float v = acc + bias;
        __nv_bfloat16 hi = __float2bfloat16(v);
        g_dw_hi[(size_t)bc * SPA + i] = hi;
        g_dw_lo[(size_t)bc * SPA + i] = __float2bfloat16(v - __bfloat162float(hi));
    }
}

// ---------------- pointwise conv on HMMA + bias + final residual ----------------
// out[co][sp] = y + pwb[co] + sum_ci pwk[co][ci]*dw[ci][sp]. Tile 128co x 128sp, K=256.
__global__ void __launch_bounds__(256) k_pwfin(const float* __restrict__ pwb,
                                               float* __restrict__ out) {
    extern __shared__ __align__(16) uint32_t sm[];
    uint32_t* sAhi = sm;               // pwk tiles [co][ciword]
    uint32_t* sAlo = sAhi + TILE_W;
    uint32_t* sBhi = sAlo + TILE_W;    // dw tiles transposed [sp][ciword]
    uint32_t* sBlo = sBhi + TILE_W;

    int tid = threadIdx.x;
    int wid = tid >> 5, lane = tid & 31;
    int wr = wid >> 2, wc = wid & 3;
    int sp0 = blockIdx.x * 128;
    int co0 = blockIdx.y * 128;
    int b = blockIdx.z;
    int lq = lane >> 2, lr = lane & 3;

    float acc[4][4][4] = {};

    for (int ci0 = 0; ci0 < 256; ci0 += 64) {
        // A: pwk hi/lo [co0..+128][ci0..+64] — direct K-major copy
#pragma unroll
        for (int i = 0; i < 4; i++) {
            int idx = tid + i * 256;
            int r = idx >> 3, gq = idx & 7;
            *(uint4*)&sAhi[r * RS + gq * 4] =
                *(const uint4*)&g_pwk_hi[(co0 + r) * 256 + ci0 + gq * 8];
            *(uint4*)&sAlo[r * RS + gq * 4] =
                *(const uint4*)&g_pwk_lo[(co0 + r) * 256 + ci0 + gq * 8];
        }
        // B: dw [ci][sp] -> smem [sp][ciword] via byte_perm pair packing
#pragma unroll
        for (int jl = 0; jl < 4; jl++) {
            int j = jl * 8 + wid;                   // ci word 0..31
            size_t rbase = (size_t)(b * 256 + ci0 + 2 * j) * SPA + sp0;
#pragma unroll
            for (int sh = 0; sh < 2; sh++) {
                int slp = (sh * 32 + lane) * 2;     // local sp (even)
                uint32_t u0 = *(const uint32_t*)(g_dw_hi + rbase + slp);
                uint32_t u1 = *(const uint32_t*)(g_dw_hi + rbase + SPA + slp);
                sBhi[slp * RS + j]       = __byte_perm(u0, u1, 0x5410);
                sBhi[(slp + 1) * RS + j] = __byte_perm(u0, u1, 0x7632);
                u0 = *(const uint32_t*)(g_dw_lo + rbase + slp);
                u1 = *(const uint32_t*)(g_dw_lo + rbase + SPA + slp);
                sBlo[slp * RS + j]       = __byte_perm(u0, u1, 0x5410);
                sBlo[(slp + 1) * RS + j] = __byte_perm(u0, u1, 0x7632);
            }
        }
        __syncthreads();
#pragma unroll
        for (int ks = 0; ks < 4; ks++) {
            int kw = ks * 8;
            uint32_t bh[4][2], bl[4][2];
#pragma unroll
            for (int nt = 0; nt < 4; nt++) {
                int n = wc * 32 + nt * 8 + lq;
                bh[nt][0] = sBhi[n * RS + kw + lr];
                bh[nt][1] = sBhi[n * RS + kw + lr + 4];
                bl[nt][0] = sBlo[n * RS + kw + lr];
                bl[nt][1] = sBlo[n * RS + kw + lr + 4];
            }
#pragma unroll
            for (int mt = 0; mt < 4; mt++) {
                int r = wr * 64 + mt * 16 + lq;
                uint32_t ah[4], al[4];
                ah[0] = sAhi[r * RS + kw + lr];
                ah[1] = sAhi[(r + 8) * RS + kw + lr];
                ah[2] = sAhi[r * RS + kw + lr + 4];
                ah[3] = sAhi[(r + 8) * RS + kw + lr + 4];
                al[0] = sAlo[r * RS + kw + lr];
                al[1] = sAlo[(r + 8) * RS + kw + lr];
                al[2] = sAlo[r * RS + kw + lr + 4];
                al[3] = sAlo[(r + 8) * RS + kw + lr + 4];
#pragma unroll
                for (int nt = 0; nt < 4; nt++) {
                    mma16816(acc[mt][nt], ah, bh[nt]);
                    mma16816(acc[mt][nt], ah, bl[nt]);
                    mma16816(acc[mt][nt], al, bh[nt]);
                }
            }
        }
        __syncthreads();
    }
    // epilogue: out = y + pwb[co] + acc
#pragma unroll
    for (int mt = 0; mt < 4; mt++) {
        int r = co0 + wr * 64 + mt * 16 + lq;
        float bb0 = pwb[r], bb1 = pwb[r + 8];
#pragma unroll
        for (int nt = 0; nt < 4; nt++) {
            int c = sp0 + wc * 32 + nt * 8 + lr * 2;
            size_t i0 = (size_t)(b * 256 + r) * SPA + c;
            size_t i1 = (size_t)(b * 256 + r + 8) * SPA + c;
            float2 y0 = *(const float2*)&g_y[i0];
            float2 y1 = *(const float2*)&g_y[i1];
            float2 v0, v1;
            v0.x = acc[mt][nt][0] + bb0 + y0.x;
            v0.y = acc[mt][nt][1] + bb0 + y0.y;
            v1.x = acc[mt][nt][2] + bb1 + y1.x;
            v1.y = acc[mt][nt][3] + bb1 + y1.y;
            *(float2*)&out[i0] = v0;
            *(float2*)&out[i1] = v1;
        }
    }
}
#define SMEM_PW (4 * TILE_W * 4)

// ---------------- launch ----------------
extern "C" void kernel_launch(void* const* d_in, const int* in_sizes, int n_in,
                              void* d_out, int out_size) {
    (void)in_sizes; (void)n_in; (void)out_size;
    const float* x    = (const float*)d_in[0];
    const float* wqkv = (const float*)d_in[1];
    const float* wseq = (const float*)d_in[2];
    const float* bseq = (const float*)d_in[3];
    const float* temp = (const float*)d_in[4];
    const float* wout = (const float*)d_in[5];
    const float* bout = (const float*)d_in[6];
    const float* lng  = (const float*)d_in[7];
    const float* lnb  = (const float*)d_in[8];
    const float* dwk  = (const float*)d_in[9];
    const float* dwb  = (const float*)d_in[10];
    const float* pwk  = (const float*)d_in[11];
    const float* pwb  = (const float*)d_in[12];
    float* out = (float*)d_out;

    float *qkv, *o2;
    __nv_bfloat16 *t_hi, *t_lo, *o_hi, *o_lo;
    __nv_bfloat16 *wqkvT_hi, *wqkvT_lo, *woutT_hi, *woutT_lo, *pwk_hi, *pwk_lo;
    __nv_bfloat16 *wsT_hi, *wsT_lo;
    cudaGetSymbolAddress((void**)&qkv, g_qkv);
    cudaGetSymbolAddress((void**)&o2,  g_o2);
    cudaGetSymbolAddress((void**)&t_hi, g_t_hi);
    cudaGetSymbolAddress((void**)&t_lo, g_t_lo);
    cudaGetSymbolAddress((void**)&o_hi, g_o_hi);
    cudaGetSymbolAddress((void**)&o_lo, g_o_lo);
    cudaGetSymbolAddress((void**)&wqkvT_hi, g_wqkvT_hi);
    cudaGetSymbolAddress((void**)&wqkvT_lo, g_wqkvT_lo);
    cudaGetSymbolAddress((void**)&woutT_hi, g_woutT_hi);
    cudaGetSymbolAddress((void**)&woutT_lo, g_woutT_lo);
    cudaGetSymbolAddress((void**)&pwk_hi, g_pwk_hi);
    cudaGetSymbolAddress((void**)&pwk_lo, g_pwk_lo);
    cudaGetSymbolAddress((void**)&wsT_hi, g_wsT_hi);
    cudaGetSymbolAddress((void**)&wsT_lo, g_wsT_lo);

    cudaFuncSetAttribute(k_mma, cudaFuncAttributeMaxDynamicSharedMemorySize, SMEM_MMA);
    cudaFuncSetAttribute(k_pwfin, cudaFuncAttributeMaxDynamicSharedMemorySize, SMEM_PW);
    cudaFuncSetAttribute(k_kvproj, cudaFuncAttributeMaxDynamicSharedMemorySize, SMEM_KV);

    // 1. transpose to token-major bf16 hi/lo
    k_transpose<<<dim3(4, 128, 4), 256>>>(x);
    // 2. weight prep
    k_wprep<<<768, 256>>>(wqkv, wqkvT_hi, wqkvT_lo, 256, 768);
    k_wprep<<<256, 256>>>(wout, woutT_hi, woutT_lo, 256, 256);
    k_wprep<<<2048, 256>>>(wseq, wsT_hi, wsT_lo, 8192, 64);
    k_wprep_nt<<<256, 256>>>(pwk, pwk_hi, pwk_lo, 256 * 256);
    // 3. QKV GEMM (HMMA, cp.async pipelined)
    k_mma<<<dim3(6, 256), 256, SMEM_MMA>>>(t_hi, t_lo, wqkvT_hi, wqkvT_lo, nullptr, qkv, 256, 768);
    // 4. column L2 norms
    k_cnpart<<<dim3(64, 4), 256>>>(qkv);
    k_cnfin<<<8, 256>>>();
    // 5. kp/vp projections (HMMA) + reduce w/ norm+bias
    k_kvproj<<<dim3(16, 16, 2), 128, SMEM_KV>>>(qkv, wsT_hi, wsT_lo);
    k_kvred<<<512, 256>>>(bseq);
    // 6. fused attention (bf16 hi/lo output)
    k_attn<<<dim3(64, 4, 4), 128>>>(qkv, temp);
    // 7. output projection (HMMA)
    k_mma<<<dim3(2, 256), 256, SMEM_MMA>>>(o_hi, o_lo, woutT_hi, woutT_lo, bout, o2, 256, 256);
    // 8. LayerNorm stats + apply/residual/transpose
    k_lnstat<<<4096, 256>>>();
    k_lnapply<<<dim3(4, 128, 4), 256>>>(x, lng, lnb);
    // 9. depthwise conv (bf16 hi/lo out)
    k_dwconv<<<1024, 256>>>(dwk, dwb);
    // 10. pointwise conv (HMMA) + bias + final residual
    k_pwfin<<<dim3(64, 2, 4), 256, SMEM_PW>>>(pwb, out);
}

// round 10
// speedup vs baseline: 1.8457x; 1.0483x over previous
#include <cuda_runtime.h>
#include <cuda_bf16.h>
#include <math.h>
#include <stdint.h>

// Problem constants
#define BQ   4
#define CC   256
#define NHEAD 4
#define PP   64
#define NN   8192
#define SPA  8192

// ---------------- scratch (device globals) ----------------
__device__ __align__(128) __nv_bfloat16 g_t_hi[(size_t)BQ * NN * CC];
__device__ __align__(128) __nv_bfloat16 g_t_lo[(size_t)BQ * NN * CC];
__device__ float g_qkv [(size_t)BQ * NN * 3 * CC];
__device__ float g_cnpart[256 * 512];
__device__ float g_rnorm [BQ * 512];
__device__ float g_kvpart[2 * 16 * 16 * 4096];
__device__ float g_kvp   [2 * 16 * 4096];
__device__ __align__(128) __nv_bfloat16 g_o_hi[(size_t)BQ * NN * CC];
__device__ __align__(128) __nv_bfloat16 g_o_lo[(size_t)BQ * NN * CC];
__device__ float g_o2  [(size_t)BQ * NN * CC];
__device__ float g_mu  [BQ * NN];
__device__ float g_rs  [BQ * NN];
__device__ float g_y   [(size_t)BQ * CC * SPA];
__device__ __align__(128) __nv_bfloat16 g_dw_hi[(size_t)BQ * CC * SPA];
__device__ __align__(128) __nv_bfloat16 g_dw_lo[(size_t)BQ * CC * SPA];
// transposed bf16 hi/lo weights [N][K]
__device__ __align__(128) __nv_bfloat16 g_wqkvT_hi[768 * 256];
__device__ __align__(128) __nv_bfloat16 g_wqkvT_lo[768 * 256];
__device__ __align__(128) __nv_bfloat16 g_woutT_hi[256 * 256];
__device__ __align__(128) __nv_bfloat16 g_woutT_lo[256 * 256];
__device__ __align__(128) __nv_bfloat16 g_pwk_hi[256 * 256];
__device__ __align__(128) __nv_bfloat16 g_pwk_lo[256 * 256];
__device__ __align__(128) __nv_bfloat16 g_wsT_hi[64 * 8192];
__device__ __align__(128) __nv_bfloat16 g_wsT_lo[64 * 8192];

// ---------------- helpers ----------------
__device__ __forceinline__ uint32_t pack_bf16_hi(float a, float b) {
    __nv_bfloat16 ha = __float2bfloat16(a);
    __nv_bfloat16 hb = __float2bfloat16(b);
    return ((uint32_t)__bfloat16_as_ushort(hb) << 16) | __bfloat16_as_ushort(ha);
}
__device__ __forceinline__ uint32_t pack_bf16_lo(float a, float b) {
    __nv_bfloat16 ha = __float2bfloat16(a);
    __nv_bfloat16 hb = __float2bfloat16(b);
    __nv_bfloat16 la = __float2bfloat16(a - __bfloat162float(ha));
    __nv_bfloat16 lb = __float2bfloat16(b - __bfloat162float(hb));
    return ((uint32_t)__bfloat16_as_ushort(lb) << 16) | __bfloat16_as_ushort(la);
}

__device__ __forceinline__ void mma16816(float* d, const uint32_t* a, const uint32_t* b) {
    asm volatile(
        "mma.sync.aligned.m16n8k16.row.col.f32.bf16.bf16.f32 "
        "{%0,%1,%2,%3}, {%4,%5,%6,%7}, {%8,%9}, {%0,%1,%2,%3};"
        : "+f"(d[0]), "+f"(d[1]), "+f"(d[2]), "+f"(d[3])
        : "r"(a[0]), "r"(a[1]), "r"(a[2]), "r"(a[3]), "r"(b[0]), "r"(b[1]));
}

__device__ __forceinline__ uint32_t smem_u32(const void* p) {
    uint32_t a;
    asm("{ .reg .u64 t; cvta.to.shared.u64 t, %1; cvt.u32.u64 %0, t; }" : "=r"(a) : "l"(p));
    return a;
}
#define CP_ASYNC16(dst, src) \
    asm volatile("cp.async.cg.shared.global [%0], [%1], 16;" :: "r"(dst), "l"(src) : "memory")
#define CP_COMMIT() asm volatile("cp.async.commit_group;" ::: "memory")
#define CP_WAIT1()  asm volatile("cp.async.wait_group 1;" ::: "memory")
#define CP_WAIT0()  asm volatile("cp.async.wait_group 0;" ::: "memory")

#define RS 36                 // smem row stride in words (pwfin/kvproj frag tiles)
#define TILE_W (128 * RS)
#define RS2 20                // k_mma chunk-32 row stride in words (16 data + 4 pad)
#define TW2 (128 * RS2)

// ---------------- K0: transpose x (NCDHW) -> t_hi/lo [B,N,C] bf16 ----------------
__global__ void k_transpose(const float* __restrict__ x) {
    __shared__ float tile[64 * 65];
    int c0 = blockIdx.x * 64;
    int sp0 = blockIdx.y * 64;
    int b = blockIdx.z;
    int tid = threadIdx.x;
#pragma unroll
    for (int i = 0; i < 16; i++) {
        int idx = i * 256 + tid;
        int c = idx >> 6, s = idx & 63;
        tile[c * 65 + s] = x[(size_t)(b * 256 + c0 + c) * SPA + sp0 + s];
    }
    __syncthreads();
#pragma unroll
    for (int i = 0; i < 16; i++) {
        int idx = i * 256 + tid;
        int s = idx >> 6, c = idx & 63;
        int sp = sp0 + s;
        int d = sp >> 10, rem = sp & 1023, h = rem >> 5, w = rem & 31;
        int n = h * 256 + w * 8 + d;
        float v = tile[c * 65 + s];
        __nv_bfloat16 hi = __float2bfloat16(v);
        size_t gi = (size_t)(b * 8192 + n) * 256 + c0 + c;
        g_t_hi[gi] = hi;
        g_t_lo[gi] = __float2bfloat16(v - __bfloat162float(hi));
    }
}

// ---------------- weight prep: fp32 [K][N] -> bf16 hi/lo [N][K], tiled transpose ----------------
// grid (Nn/64, K/64), 256 threads.
__global__ void k_wtprep(const float* __restrict__ w, __nv_bfloat16* __restrict__ thi,
                         __nv_bfloat16* __restrict__ tlo, int K, int Nn) {
    __shared__ float sm[64 * 65];
    int n0 = blockIdx.x * 64;
    int k0 = blockIdx.y * 64;
    int tid = threadIdx.x;
#pragma unroll
    for (int i = 0; i < 16; i++) {
        int idx = i * 256 + tid;
        int r = idx >> 6, c = idx & 63;   // r = k row, c = n col
        sm[r * 65 + c] = w[(size_t)(k0 + r) * Nn + n0 + c];
    }
    __syncthreads();
#pragma unroll
    for (int i = 0; i < 16; i++) {
        int idx = i * 256 + tid;
        int r = idx >> 6, c = idx & 63;   // r = n row, c = k col
        float a = sm[c * 65 + r];
        __nv_bfloat16 h = __float2bfloat16(a);
        size_t gi = (size_t)(n0 + r) * K + k0 + c;
        thi[gi] = h;
        tlo[gi] = __float2bfloat16(a - __bfloat162float(h));
    }
}
// no-transpose variant (pwk is already [co][ci] = [M][K])
__global__ void k_wprep_nt(const float* __restrict__ w, __nv_bfloat16* __restrict__ thi,
                           __nv_bfloat16* __restrict__ tlo, int total) {
    int idx = blockIdx.x * 256 + threadIdx.x;
    if (idx >= total) return;
    float a = w[idx];
    __nv_bfloat16 h = __float2bfloat16(a);
    thi[idx] = h;
    tlo[idx] = __float2bfloat16(a - __bfloat162float(h));
}

// ---------------- HMMA bf16-split GEMM, cp.async 2-stage, 2 CTAs/SM ----------------
// A hi/lo bf16 [M][K]; B hi/lo bf16 [Ntot][K]. CTA tile 128x128, K-chunk 32.
__global__ void __launch_bounds__(256, 2) k_mma(const __nv_bfloat16* __restrict__ Ahi,
                                                const __nv_bfloat16* __restrict__ Alo,
                                                const __nv_bfloat16* __restrict__ Bhi,
                                                const __nv_bfloat16* __restrict__ Blo,
                                                const float* __restrict__ bias,
                                                float* __restrict__ C, int K, int Ntot) {
    extern __shared__ __align__(16) uint32_t sm[];
    uint32_t sbase = smem_u32(sm);

    int tid = threadIdx.x;
    int wid = tid >> 5, lane = tid & 31;
    int wr = wid >> 2, wc = wid & 3;
    int row0 = blockIdx.y * 128;
    int col0 = blockIdx.x * 128;
    int lq = lane >> 2, lr = lane & 3;

    float acc[4][4][4] = {};
    int nch = K >> 5;

    // stage tiles [Ahi|Alo|Bhi|Blo], chunk = 32 K-elems = 4 x 16B groups per row
#define PREFETCH(CH, STG) do {                                                     \
        int _k0 = (CH) << 5;                                                       \
        uint32_t _so = sbase + (STG) * 4 * TW2 * 4;                                \
        _Pragma("unroll")                                                          \
        for (int _i = 0; _i < 2; _i++) {                                           \
            int _idx = tid + _i * 256;                                             \
            int _r = _idx >> 2, _g = _idx & 3;                                     \
            uint32_t _d = _so + (_r * RS2 + _g * 4) * 4;                           \
            const __nv_bfloat16* _s = Ahi + (size_t)(row0 + _r) * K + _k0 + _g * 8;\
            CP_ASYNC16(_d, _s);                                                    \
            _d += TW2 * 4;                                                         \
            _s = Alo + (size_t)(row0 + _r) * K + _k0 + _g * 8;                     \
            CP_ASYNC16(_d, _s);                                                    \
            _d += TW2 * 4;                                                         \
            _s = Bhi + (size_t)(col0 + _r) * K + _k0 + _g * 8;                     \
            CP_ASYNC16(_d, _s);                                                    \
            _d += TW2 * 4;                                                         \
            _s = Blo + (size_t)(col0 + _r) * K + _k0 + _g * 8;                     \
            CP_ASYNC16(_d, _s);                                                    \
        }                                                                          \
    } while (0)

    PREFETCH(0, 0);
    CP_COMMIT();

    for (int ch = 0; ch < nch; ch++) {
        if (ch + 1 < nch) {
            PREFETCH(ch + 1, (ch + 1) & 1);
            CP_COMMIT();
            CP_WAIT1();
        } else {
            CP_WAIT0();
        }
        __syncthreads();
        uint32_t* base = sm + (ch & 1) * 4 * TW2;
        uint32_t* sAhi = base;
        uint32_t* sAlo = base + TW2;
        uint32_t* sBhi = base + 2 * TW2;
        uint32_t* sBlo = base + 3 * TW2;
#pragma unroll
        for (int ks = 0; ks < 2; ks++) {
            int kw = ks * 8;
            uint32_t bh[4][2], bl[4][2];
#pragma unroll
            for (int nt = 0; nt < 4; nt++) {
                int n = wc * 32 + nt * 8 + lq;
                bh[nt][0] = sBhi[n * RS2 + kw + lr];
                bh[nt][1] = sBhi[n * RS2 + kw + lr + 4];
                bl[nt][0] = sBlo[n * RS2 + kw + lr];
                bl[nt][1] = sBlo[n * RS2 + kw + lr + 4];
            }
#pragma unroll
            for (int mt = 0; mt < 4; mt++) {
                int r = wr * 64 + mt * 16 + lq;
                uint32_t ah[4], al[4];
                ah[0] = sAhi[r * RS2 + kw + lr];
                ah[1] = sAhi[(r + 8) * RS2 + kw + lr];
                ah[2] = sAhi[r * RS2 + kw + lr + 4];
                ah[3] = sAhi[(r + 8) * RS2 + kw + lr + 4];
                al[0] = sAlo[r * RS2 + kw + lr];
                al[1] = sAlo[(r + 8) * RS2 + kw + lr];
                al[2] = sAlo[r * RS2 + kw + lr + 4];
                al[3] = sAlo[(r + 8) * RS2 + kw + lr + 4];
#pragma unroll
                for (int nt = 0; nt < 4; nt++) {
                    mma16816(acc[mt][nt], ah, bh[nt]);
                    mma16816(acc[mt][nt], ah, bl[nt]);
                    mma16816(acc[mt][nt], al, bh[nt]);
                }
            }
        }
        __syncthreads();
    }
#undef PREFETCH
    // epilogue
#pragma unroll
    for (int mt = 0; mt < 4; mt++) {
        int r = row0 + wr * 64 + mt * 16 + lq;
#pragma unroll
        for (int nt = 0; nt < 4; nt++) {
            int c = col0 + wc * 32 + nt * 8 + lr * 2;
            float b0 = bias ? bias[c] : 0.0f;
            float b1 = bias ? bias[c + 1] : 0.0f;
            float2 v0, v1;
            v0.x = acc[mt][nt][0] + b0;
            v0.y = acc[mt][nt][1] + b1;
            v1.x = acc[mt][nt][2] + b0;
            v1.y = acc[mt][nt][3] + b1;
            *(float2*)&C[(size_t)r * Ntot + c] = v0;
            *(float2*)&C[(size_t)(r + 8) * Ntot + c] = v1;
        }
    }
}
#define SMEM_MMA (8 * TW2 * 4)

// ---------------- column L2 norms for q,k ----------------
__global__ void k_cnpart(const float* __restrict__ qkv) {
    int chunk = blockIdx.x;   // 64 chunks of 128 tokens
    int b = blockIdx.y;
    int tid = threadIdx.x;
    float s0 = 0.f, s1 = 0.f;
    int n0 = chunk * 128;
    for (int n = n0; n < n0 + 128; n++) {
        const float* row = qkv + (size_t)(b * 8192 + n) * 768;
        float v0 = row[tid];
        float v1 = row[256 + tid];
        s0 += v0 * v0;
        s1 += v1 * v1;
    }
    g_cnpart[(b * 64 + chunk) * 512 + tid] = s0;
    g_cnpart[(b * 64 + chunk) * 512 + 256 + tid] = s1;
}

__global__ void k_cnfin() {
    int idx = blockIdx.x * 256 + threadIdx.x;
    int b = idx >> 9, col = idx & 511;
    float s = 0.f;
#pragma unroll
    for (int ch = 0; ch < 64; ch++) s += g_cnpart[(b * 64 + ch) * 512 + col];
    g_rnorm[idx] = 1.0f / fmaxf(sqrtf(s), 1e-12f);
}

// ---------------- kp/vp projections on HMMA ----------------
// out[e][p] = sum_n qkv[n][colbase+e] * wseq[n][p]  (normalization applied in kvred)
#define SMEM_KV (64 * 65 * 4 + 4 * 64 * RS * 4)
__global__ void __launch_bounds__(128) k_kvproj(const float* __restrict__ qkv,
                                                const __nv_bfloat16* __restrict__ wsThi,
                                                const __nv_bfloat16* __restrict__ wsTlo) {
    extern __shared__ __align__(16) char smraw[];
    float* sF = (float*)smraw;                       // fp32 stage [n][e], stride 65
    uint32_t* sAhi = (uint32_t*)(smraw + 64 * 65 * 4);
    uint32_t* sAlo = sAhi + 64 * RS;
    uint32_t* sBhi = sAlo + 64 * RS;
    uint32_t* sBlo = sBhi + 64 * RS;

    int slice = blockIdx.x;
    int bh = blockIdx.y;
    int kind = blockIdx.z;
    int b = bh >> 2, h = bh & 3;
    int colbase = (kind == 0 ? 256 : 512) + h * 64;
    int tid = threadIdx.x;
    int wid = tid >> 5, lane = tid & 31;
    int wr = wid >> 1, wc = wid & 1;        // 2x2 warp grid, warp tile 32x32
    int lq = lane >> 2, lr = lane & 3;
    int wa = lane & 7, wb = lane >> 3;      // conflict-free convert mapping

    float acc[2][4][4] = {};

    int nbeg = slice * 512;
    for (int ch = 0; ch < 8; ch++) {
        int n0 = nbeg + ch * 64;
#pragma unroll
        for (int i = 0; i < 8; i++) {
            int idx = tid + i * 128;
            int r = idx >> 4, c4 = idx & 15;
            float4 v = *(const float4*)&qkv[(size_t)(b * 8192 + n0 + r) * 768 + colbase + c4 * 4];
            float* dst = &sF[r * 65 + c4 * 4];
            dst[0] = v.x; dst[1] = v.y; dst[2] = v.z; dst[3] = v.w;
        }
#pragma unroll
        for (int i = 0; i < 4; i++) {
            int idx = tid + i * 128;
            int r = idx >> 3, q = idx & 7;
            *(uint4*)&sBhi[r * RS + q * 4] = *(const uint4*)&wsThi[(size_t)r * 8192 + n0 + q * 8];
            *(uint4*)&sBlo[r * RS + q * 4] = *(const uint4*)&wsTlo[(size_t)r * 8192 + n0 + q * 8];
        }
        __syncthreads();
#pragma unroll
        for (int ia = 0; ia < 2; ia++) {
            int e = wid * 16 + 8 * ia + wa;
#pragma unroll
            for (int inp = 0; inp < 8; inp++) {
                int np = 4 * inp + wb;
                float v0 = sF[(2 * np) * 65 + e];
                float v1 = sF[(2 * np + 1) * 65 + e];
                sAhi[e * RS + np] = pack_bf16_hi(v0, v1);
                sAlo[e * RS + np] = pack_bf16_lo(v0, v1);
            }
        }
        __syncthreads();
#pragma unroll
        for (int ks = 0; ks < 4; ks++) {
            int kw = ks * 8;
            uint32_t bhf[4][2], blf[4][2];
#pragma unroll
            for (int nt = 0; nt < 4; nt++) {
                int nrow = wc * 32 + nt * 8 + lq;
                bhf[nt][0] = sBhi[nrow * RS + kw + lr];
                bhf[nt][1] = sBhi[nrow * RS + kw + lr + 4];
                blf[nt][0] = sBlo[nrow * RS + kw + lr];
                blf[nt][1] = sBlo[nrow * RS + kw + lr + 4];
            }
#pragma unroll
            for (int mt = 0; mt < 2; mt++) {
                int r = wr * 32 + mt * 16 + lq;
                uint32_t ah[4], al[4];
                ah[0] = sAhi[r * RS + kw + lr];
                ah[1] = sAhi[(r + 8) * RS + kw + lr];
                ah[2] = sAhi[r * RS + kw + lr + 4];
                ah[3] = sAhi[(r + 8) * RS + kw + lr + 4];
                al[0] = sAlo[r * RS + kw + lr];
                al[1] = sAlo[(r + 8) * RS + kw + lr];
                al[2] = sAlo[r * RS + kw + lr + 4];
                al[3] = sAlo[(r + 8) * RS + kw + lr + 4];
#pragma unroll
                for (int nt = 0; nt < 4; nt++) {
                    mma16816(acc[mt][nt], ah, bhf[nt]);
                    mma16816(acc[mt][nt], ah, blf[nt]);
                    mma16816(acc[mt][nt], al, bhf[nt]);
                }
            }
        }
        __syncthreads();
    }
    float* dst = g_kvpart + (size_t)((kind * 16 + bh) * 16 + slice) * 4096;
#pragma unroll
    for (int mt = 0; mt < 2; mt++) {
        int e = wr * 32 + mt * 16 + lq;
#pragma unroll
        for (int nt = 0; nt < 4; nt++) {
            int p = wc * 32 + nt * 8 + lr * 2;
            *(float2*)&dst[e * 64 + p] = make_float2(acc[mt][nt][0], acc[mt][nt][1]);
            *(float2*)&dst[(e + 8) * 64 + p] = make_float2(acc[mt][nt][2], acc[mt][nt][3]);
        }
    }
}

__global__ void k_kvred(const float* __restrict__ bseq) {
    int idx = blockIdx.x * 256 + threadIdx.x;   // 131072 total
    int kb = idx >> 12;                          // kind*16+bh
    int ep = idx & 4095;
    float s = 0.f;
#pragma unroll
    for (int sl = 0; sl < 16; sl++) s += g_kvpart[(size_t)(kb * 16 + sl) * 4096 + ep];
    int kind = kb >> 4, bh = kb & 15;
    int b = bh >> 2, h = bh & 3;
    if (kind == 0) s *= g_rnorm[b * 512 + 256 + h * 64 + (ep >> 6)];
    g_kvp[idx] = s + bseq[ep & 63];
}

// ---------------- fused attention (writes o as bf16 hi/lo) ----------------
__global__ void __launch_bounds__(128) k_attn(const float* __restrict__ qkv,
                                              const float* __restrict__ temp) {
    __shared__ float kpsm[4096];
    __shared__ float vpsm[4096];
    __shared__ float rnsm[64];
    int tid = threadIdx.x;
    int h = blockIdx.y, b = blockIdx.z;
    int bh = b * 4 + h;
    const float4* kp4 = (const float4*)(g_kvp + (size_t)bh * 4096);
    const float4* vp4 = (const float4*)(g_kvp + (size_t)(16 + bh) * 4096);
    for (int i = tid; i < 1024; i += 128) {
        ((float4*)kpsm)[i] = kp4[i];
        ((float4*)vpsm)[i] = vp4[i];
    }
    if (tid < 64) rnsm[tid] = g_rnorm[b * 512 + h * 64 + tid];
    __syncthreads();
    float tv = temp[h];
    int n = blockIdx.x * 128 + tid;
    const float* qrow = qkv + (size_t)(b * 8192 + n) * 768 + h * 64;

    float l[64];
#pragma unroll
    for (int p = 0; p < 64; p++) l[p] = 0.f;
    for (int e = 0; e < 64; e++) {
        float qe = qrow[e] * rnsm[e];
        const float4* krow = (const float4*)(kpsm + e * 64);
#pragma unroll
        for (int p4 = 0; p4 < 16; p4++) {
            float4 kv = krow[p4];
            l[p4 * 4 + 0] += qe * kv.x;
            l[p4 * 4 + 1] += qe * kv.y;
            l[p4 * 4 + 2] += qe * kv.z;
            l[p4 * 4 + 3] += qe * kv.w;
        }
    }
    float m = -1e30f;
#pragma unroll
    for (int p = 0; p < 64; p++) { l[p] *= tv; m = fmaxf(m, l[p]); }
    float s = 0.f;
#pragma unroll
    for (int p = 0; p < 64; p++) { l[p] = __expf(l[p] - m); s += l[p]; }
    float inv = 1.0f / s;

    size_t obase = (size_t)(b * 8192 + n) * 256 + h * 64;
    uint2* ohrow = (uint2*)(g_o_hi + obase);
    uint2* olrow = (uint2*)(g_o_lo + obase);
    for (int e4 = 0; e4 < 16; e4++) {
        float r[4];
#pragma unroll
        for (int ii = 0; ii < 4; ii++) {
            const float4* vrow = (const float4*)(vpsm + (e4 * 4 + ii) * 64);
            float a = 0.f;
#pragma unroll
            for (int p4 = 0; p4 < 16; p4++) {
                float4 vv = vrow[p4];
                a += l[p4 * 4 + 0] * vv.x + l[p4 * 4 + 1] * vv.y
                   + l[p4 * 4 + 2] * vv.z + l[p4 * 4 + 3] * vv.w;
            }
            r[ii] = a * inv;
        }
        uint2 vh, vl;
        vh.x = pack_bf16_hi(r[0], r[1]);
        vh.y = pack_bf16_hi(r[2], r[3]);
        vl.x = pack_bf16_lo(r[0], r[1]);
        vl.y = pack_bf16_lo(r[2], r[3]);
        ohrow[e4] = vh;
        olrow[e4] = vl;
    }
}

// ---------------- LayerNorm stats per token ----------------
__global__ void k_lnstat() {
    int tid = threadIdx.x;
    int warp = tid >> 5, lane = tid & 31;
    int t = blockIdx.x * 8 + warp;     // global token (b*8192+n)
    const float4* row = (const float4*)(g_o2 + (size_t)t * 256);
    float s = 0.f, sq = 0.f;
#pragma unroll
    for (int j = 0; j < 2; j++) {
        float4 v = row[j * 32 + lane];
        s  += v.x + v.y + v.z + v.w;
        sq += v.x * v.x + v.y * v.y + v.z * v.z + v.w * v.w;
    }
#pragma unroll
    for (int off = 16; off; off >>= 1) {
        s  += __shfl_xor_sync(0xffffffffu, s, off);
        sq += __shfl_xor_sync(0xffffffffu, sq, off);
    }
    if (lane == 0) {
        float mu = s * (1.0f / 256.0f);
        float var = sq * (1.0f / 256.0f) - mu * mu;
        g_mu[t] = mu;
        g_rs[t] = rsqrtf(var + 1e-5f);
    }
}

// ---------------- LN apply + residual + restore NCDHW (tiled transpose) ----------------
__global__ void k_lnapply(const float* __restrict__ x, const float* __restrict__ g,
                          const float* __restrict__ be) {
    __shared__ float tl[64 * 65];
    __shared__ float mus[64], rss[64];
    int c0 = blockIdx.x * 64;
    int sp0 = blockIdx.y * 64;
    int b = blockIdx.z;
    int tid = threadIdx.x;
    if (tid < 64) {
        int sp = sp0 + tid;
        int d = sp >> 10, rem = sp & 1023, h = rem >> 5, w = rem & 31;
        int n = h * 256 + w * 8 + d;
        mus[tid] = g_mu[b * 8192 + n];
        rss[tid] = g_rs[b * 8192 + n];
    }
#pragma unroll
    for (int i = 0; i < 16; i++) {
        int idx = i * 256 + tid;
        int s = idx >> 6, c = idx & 63;
        int sp = sp0 + s;
        int d = sp >> 10, rem = sp & 1023, h = rem >> 5, w = rem & 31;
        int n = h * 256 + w * 8 + d;
        tl[s * 65 + c] = g_o2[(size_t)(b * 8192 + n) * 256 + c0 + c];
    }
    __syncthreads();
#pragma unroll
    for (int i = 0; i < 16; i++) {
        int idx = i * 256 + tid;
        int c = idx >> 6, s = idx & 63;
        float gg = g[c0 + c], bb = be[c0 + c];
        float r = (tl[s * 65 + c] - mus[s]) * rss[s] * gg + bb;
        size_t gi = (size_t)(b * 256 + c0 + c) * SPA + sp0 + s;
        g_y[gi] = x[gi] + r;
    }
}

// ---------------- depthwise 3x3x3 SAME conv (bf16 hi/lo output) ----------------
__global__ void k_dwconv(const float* __restrict__ dwk, const float* __restrict__ dwb) {
    __shared__ float tile[10 * 34 * 34];
    __shared__ float wk[27];
    int bc = blockIdx.x;
    int c = bc & 255;
    int tid = threadIdx.x;
    if (tid < 27) wk[tid] = dwk[c * 27 + tid];
    const float* src = g_y + (size_t)bc * SPA;
    for (int i = tid; i < 11560; i += 256) {
        int dz = i / 1156;
        int rem = i - dz * 1156;
        int hy = rem / 34;
        int wx = rem - hy * 34;
        int d = dz - 1, hh = hy - 1, w = wx - 1;
        float val = 0.f;
        if (d >= 0 && d < 8 && hh >= 0 && hh < 32 && w >= 0 && w < 32)
            val = src[d * 1024 + hh * 32 + w];
        tile[i] = val;
    }
    __syncthreads();
    float bias = dwb[c];
    for (int i = tid; i < 8192; i += 256) {
        int d = i >> 10;
        int r = i & 1023;
        int hh = r >> 5, w = r & 31;
        float acc = 0.f;
#pragma unroll
        for (int kd = 0; kd < 3; kd++)
#pragma unroll
            for (int kh = 0; kh < 3; kh++)
#pragma unroll
                for (int kw = 0; kw < 3; kw++)
                    acc += wk[kd * 9 + kh * 3 + kw]
                         * tile[(d + kd) * 1156 + (hh + kh) * 34 + (w + kw)];
        float v = acc + bias;
        __nv_bfloat16 hi = __float2bfloat16(v);
        g_dw_hi[(size_t)bc * SPA + i] = hi;
        g_dw_lo[(size_t)bc * SPA + i] = __float2bfloat16(v - __bfloat162float(hi));
    }
}

// ---------------- pointwise conv on HMMA + bias + final residual ----------------
__global__ void __launch_bounds__(256, 2) k_pwfin(const float* __restrict__ pwb,
                                                  float* __restrict__ out) {
    extern __shared__ __align__(16) uint32_t sm[];
    uint32_t* sAhi = sm;               // pwk tiles [co][ciword]
    uint32_t* sAlo = sAhi + TILE_W;
    uint32_t* sBhi = sAlo + TILE_W;    // dw tiles transposed [sp][ciword]
    uint32_t* sBlo = sBhi + TILE_W;

    int tid = threadIdx.x;
    int wid = tid >> 5, lane = tid & 31;
    int wr = wid >> 2, wc = wid & 3;
    int sp0 = blockIdx.x * 128;
    int co0 = blockIdx.y * 128;
    int b = blockIdx.z;
    int lq = lane >> 2, lr = lane & 3;

    float acc[4][4][4] = {};

    for (int ci0 = 0; ci0 < 256; ci0 += 64) {
#pragma unroll
        for (int i = 0; i < 4; i++) {
            int idx = tid + i * 256;
            int r = idx >> 3, gq = idx & 7;
            *(uint4*)&sAhi[r * RS + gq * 4] =
                *(const uint4*)&g_pwk_hi[(co0 + r) * 256 + ci0 + gq * 8];
            *(uint4*)&sAlo[r * RS + gq * 4] =
                *(const uint4*)&g_pwk_lo[(co0 + r) * 256 + ci0 + gq * 8];
        }
#pragma unroll
        for (int jl = 0; jl < 4; jl++) {
            int j = jl * 8 + wid;                   // ci word 0..31
            size_t rbase = (size_t)(b * 256 + ci0 + 2 * j) * SPA + sp0;
#pragma unroll
            for (int sh = 0; sh < 2; sh++) {
                int slp = (sh * 32 + lane) * 2;     // local sp (even)
                uint32_t u0 = *(const uint32_t*)(g_dw_hi + rbase + slp);
                uint32_t u1 = *(const uint32_t*)(g_dw_hi + rbase + SPA + slp);
                sBhi[slp * RS + j]       = __byte_perm(u0, u1, 0x5410);
                sBhi[(slp + 1) * RS + j] = __byte_perm(u0, u1, 0x7632);
                u0 = *(const uint32_t*)(g_dw_lo + rbase + slp);
                u1 = *(const uint32_t*)(g_dw_lo + rbase + SPA + slp);
                sBlo[slp * RS + j]       = __byte_perm(u0, u1, 0x5410);
                sBlo[(slp + 1) * RS + j] = __byte_perm(u0, u1, 0x7632);
            }
        }
        __syncthreads();
#pragma unroll
        for (int ks = 0; ks < 4; ks++) {
            int kw = ks * 8;
            uint32_t bh[4][2], bl[4][2];
#pragma unroll
            for (int nt = 0; nt < 4; nt++) {
                int n = wc * 32 + nt * 8 + lq;
                bh[nt][0] = sBhi[n * RS + kw + lr];
                bh[nt][1] = sBhi[n * RS + kw + lr + 4];
                bl[nt][0] = sBlo[n * RS + kw + lr];
                bl[nt][1] = sBlo[n * RS + kw + lr + 4];
            }
#pragma unroll
            for (int mt = 0; mt < 4; mt++) {
                int r = wr * 64 + mt * 16 + lq;
                uint32_t ah[4], al[4];
                ah[0] = sAhi[r * RS + kw + lr];
                ah[1] = sAhi[(r + 8) * RS + kw + lr];
                ah[2] = sAhi[r * RS + kw + lr + 4];
                ah[3] = sAhi[(r + 8) * RS + kw + lr + 4];
                al[0] = sAlo[r * RS + kw + lr];
                al[1] = sAlo[(r + 8) * RS + kw + lr];
                al[2] = sAlo[r * RS + kw + lr + 4];
                al[3] = sAlo[(r + 8) * RS + kw + lr + 4];
#pragma unroll
                for (int nt = 0; nt < 4; nt++) {
                    mma16816(acc[mt][nt], ah, bh[nt]);
                    mma16816(acc[mt][nt], ah, bl[nt]);
                    mma16816(acc[mt][nt], al, bh[nt]);
                }
            }
        }
        __syncthreads();
    }
    // epilogue: out = y + pwb[co] + acc
#pragma unroll
    for (int mt = 0; mt < 4; mt++) {
        int r = co0 + wr * 64 + mt * 16 + lq;
        float bb0 = pwb[r], bb1 = pwb[r + 8];
#pragma unroll
        for (int nt = 0; nt < 4; nt++) {
            int c = sp0 + wc * 32 + nt * 8 + lr * 2;
            size_t i0 = (size_t)(b * 256 + r) * SPA + c;
            size_t i1 = (size_t)(b * 256 + r + 8) * SPA + c;
            float2 y0 = *(const float2*)&g_y[i0];
            float2 y1 = *(const float2*)&g_y[i1];
            float2 v0, v1;
            v0.x = acc[mt][nt][0] + bb0 + y0.x;
            v0.y = acc[mt][nt][1] + bb0 + y0.y;
            v1.x = acc[mt][nt][2] + bb1 + y1.x;
            v1.y = acc[mt][nt][3] + bb1 + y1.y;
            *(float2*)&out[i0] = v0;
            *(float2*)&out[i1] = v1;
        }
    }
}
#define SMEM_PW (4 * TILE_W * 4)

// ---------------- launch ----------------
extern "C" void kernel_launch(void* const* d_in, const int* in_sizes, int n_in,
                              void* d_out, int out_size) {
    (void)in_sizes; (void)n_in; (void)out_size;
    const float* x    = (const float*)d_in[0];
    const float* wqkv = (const float*)d_in[1];
    const float* wseq = (const float*)d_in[2];
    const float* bseq = (const float*)d_in[3];
    const float* temp = (const float*)d_in[4];
    const float* wout = (const float*)d_in[5];
    const float* bout = (const float*)d_in[6];
    const float* lng  = (const float*)d_in[7];
    const float* lnb  = (const float*)d_in[8];
    const float* dwk  = (const float*)d_in[9];
    const float* dwb  = (const float*)d_in[10];
    const float* pwk  = (const float*)d_in[11];
    const float* pwb  = (const float*)d_in[12];
    float* out = (float*)d_out;

    float *qkv, *o2;
    __nv_bfloat16 *t_hi, *t_lo, *o_hi, *o_lo;
    __nv_bfloat16 *wqkvT_hi, *wqkvT_lo, *woutT_hi, *woutT_lo, *pwk_hi, *pwk_lo;
    __nv_bfloat16 *wsT_hi, *wsT_lo;
    cudaGetSymbolAddress((void**)&qkv, g_qkv);
    cudaGetSymbolAddress((void**)&o2,  g_o2);
    cudaGetSymbolAddress((void**)&t_hi, g_t_hi);
    cudaGetSymbolAddress((void**)&t_lo, g_t_lo);
    cudaGetSymbolAddress((void**)&o_hi, g_o_hi);
    cudaGetSymbolAddress((void**)&o_lo, g_o_lo);
    cudaGetSymbolAddress((void**)&wqkvT_hi, g_wqkvT_hi);
    cudaGetSymbolAddress((void**)&wqkvT_lo, g_wqkvT_lo);
    cudaGetSymbolAddress((void**)&woutT_hi, g_woutT_hi);
    cudaGetSymbolAddress((void**)&woutT_lo, g_woutT_lo);
    cudaGetSymbolAddress((void**)&pwk_hi, g_pwk_hi);
    cudaGetSymbolAddress((void**)&pwk_lo, g_pwk_lo);
    cudaGetSymbolAddress((void**)&wsT_hi, g_wsT_hi);
    cudaGetSymbolAddress((void**)&wsT_lo, g_wsT_lo);

    cudaFuncSetAttribute(k_mma, cudaFuncAttributeMaxDynamicSharedMemorySize, SMEM_MMA);
    cudaFuncSetAttribute(k_pwfin, cudaFuncAttributeMaxDynamicSharedMemorySize, SMEM_PW);
    cudaFuncSetAttribute(k_kvproj, cudaFuncAttributeMaxDynamicSharedMemorySize, SMEM_KV);

    // 1. transpose to token-major bf16 hi/lo
    k_transpose<<<dim3(4, 128, 4), 256>>>(x);
    // 2. weight prep (tiled transposes + direct split)
    k_wtprep<<<dim3(12, 4), 256>>>(wqkv, wqkvT_hi, wqkvT_lo, 256, 768);
    k_wtprep<<<dim3(4, 4), 256>>>(wout, woutT_hi, woutT_lo, 256, 256);
    k_wtprep<<<dim3(1, 128), 256>>>(wseq, wsT_hi, wsT_lo, 8192, 64);
    k_wprep_nt<<<256, 256>>>(pwk, pwk_hi, pwk_lo, 256 * 256);
    // 3. QKV GEMM (HMMA, cp.async pipelined, 2 CTA/SM)
    k_mma<<<dim3(6, 256), 256, SMEM_MMA>>>(t_hi, t_lo, wqkvT_hi, wqkvT_lo, nullptr, qkv, 256, 768);
    // 4. column L2 norms
    k_cnpart<<<dim3(64, 4), 256>>>(qkv);
    k_cnfin<<<8, 256>>>();
    // 5. kp/vp projections (HMMA) + reduce w/ norm+bias
    k_kvproj<<<dim3(16, 16, 2), 128, SMEM_KV>>>(qkv, wsT_hi, wsT_lo);
    k_kvred<<<512, 256>>>(bseq);
    // 6. fused attention (bf16 hi/lo output)
    k_attn<<<dim3(64, 4, 4), 128>>>(qkv, temp);
    // 7. output projection (HMMA)
    k_mma<<<dim3(2, 256), 256, SMEM_MMA>>>(o_hi, o_lo, woutT_hi, woutT_lo, bout, o2, 256, 256);
    // 8. LayerNorm stats + apply/residual/transpose
    k_lnstat<<<4096, 256>>>();
    k_lnapply<<<dim3(4, 128, 4), 256>>>(x, lng, lnb);
    // 9. depthwise conv (bf16 hi/lo out)
    k_dwconv<<<1024, 256>>>(dwk, dwb);
    // 10. pointwise conv (HMMA) + bias + final residual
    k_pwfin<<<dim3(64, 2, 4), 256, SMEM_PW>>>(pwb, out);
}

// round 12
// speedup vs baseline: 2.1926x; 1.1879x over previous
#include <cuda_runtime.h>
#include <cuda_bf16.h>
#include <math.h>
#include <stdint.h>

// Problem constants
#define BQ   4
#define CC   256
#define NHEAD 4
#define PP   64
#define NN   8192
#define SPA  8192

// ---------------- scratch (device globals) ----------------
__device__ __align__(128) __nv_bfloat16 g_t_hi[(size_t)BQ * NN * CC];
__device__ __align__(128) __nv_bfloat16 g_t_lo[(size_t)BQ * NN * CC];
__device__ float g_qkv [(size_t)BQ * NN * 3 * CC];
__device__ float g_cnpart[256 * 512];
__device__ float g_rnorm [BQ * 512];
__device__ float g_kvpart[2 * 16 * 16 * 4096];
// attention operand tiles (bf16 hi/lo): kpT [p][e] (norms folded), vp [e][p]
__device__ __align__(128) __nv_bfloat16 g_kpT_hi[16 * 4096];
__device__ __align__(128) __nv_bfloat16 g_kpT_lo[16 * 4096];
__device__ __align__(128) __nv_bfloat16 g_vp_hi [16 * 4096];
__device__ __align__(128) __nv_bfloat16 g_vp_lo [16 * 4096];
__device__ __align__(128) __nv_bfloat16 g_o_hi[(size_t)BQ * NN * CC];
__device__ __align__(128) __nv_bfloat16 g_o_lo[(size_t)BQ * NN * CC];
__device__ float g_o2  [(size_t)BQ * NN * CC];
__device__ float g_mu  [BQ * NN];
__device__ float g_rs  [BQ * NN];
__device__ float g_y   [(size_t)BQ * CC * SPA];
__device__ __align__(128) __nv_bfloat16 g_dw_hi[(size_t)BQ * CC * SPA];
__device__ __align__(128) __nv_bfloat16 g_dw_lo[(size_t)BQ * CC * SPA];
// transposed bf16 hi/lo weights [N][K]
__device__ __align__(128) __nv_bfloat16 g_wqkvT_hi[768 * 256];
__device__ __align__(128) __nv_bfloat16 g_wqkvT_lo[768 * 256];
__device__ __align__(128) __nv_bfloat16 g_woutT_hi[256 * 256];
__device__ __align__(128) __nv_bfloat16 g_woutT_lo[256 * 256];
__device__ __align__(128) __nv_bfloat16 g_pwk_hi[256 * 256];
__device__ __align__(128) __nv_bfloat16 g_pwk_lo[256 * 256];
__device__ __align__(128) __nv_bfloat16 g_wsT_hi[64 * 8192];
__device__ __align__(128) __nv_bfloat16 g_wsT_lo[64 * 8192];

// ---------------- helpers ----------------
__device__ __forceinline__ uint32_t pack_bf16_hi(float a, float b) {
    __nv_bfloat16 ha = __float2bfloat16(a);
    __nv_bfloat16 hb = __float2bfloat16(b);
    return ((uint32_t)__bfloat16_as_ushort(hb) << 16) | __bfloat16_as_ushort(ha);
}
__device__ __forceinline__ uint32_t pack_bf16_lo(float a, float b) {
    __nv_bfloat16 ha = __float2bfloat16(a);
    __nv_bfloat16 hb = __float2bfloat16(b);
    __nv_bfloat16 la = __float2bfloat16(a - __bfloat162float(ha));
    __nv_bfloat16 lb = __float2bfloat16(b - __bfloat162float(hb));
    return ((uint32_t)__bfloat16_as_ushort(lb) << 16) | __bfloat16_as_ushort(la);
}

__device__ __forceinline__ void mma16816(float* d, const uint32_t* a, const uint32_t* b) {
    asm volatile(
        "mma.sync.aligned.m16n8k16.row.col.f32.bf16.bf16.f32 "
        "{%0,%1,%2,%3}, {%4,%5,%6,%7}, {%8,%9}, {%0,%1,%2,%3};"
        : "+f"(d[0]), "+f"(d[1]), "+f"(d[2]), "+f"(d[3])
        : "r"(a[0]), "r"(a[1]), "r"(a[2]), "r"(a[3]), "r"(b[0]), "r"(b[1]));
}

__device__ __forceinline__ uint32_t smem_u32(const void* p) {
    uint32_t a;
    asm("{ .reg .u64 t; cvta.to.shared.u64 t, %1; cvt.u32.u64 %0, t; }" : "=r"(a) : "l"(p));
    return a;
}
#define CP_ASYNC16(dst, src) \
    asm volatile("cp.async.cg.shared.global [%0], [%1], 16;" :: "r"(dst), "l"(src) : "memory")
#define CP_COMMIT() asm volatile("cp.async.commit_group;" ::: "memory")
#define CP_WAIT1()  asm volatile("cp.async.wait_group 1;" ::: "memory")
#define CP_WAIT0()  asm volatile("cp.async.wait_group 0;" ::: "memory")

#define RS 36                 // smem row stride in words (frag tiles)
#define TILE_W (128 * RS)
#define RS2 20                // k_mma chunk-32 row stride in words
#define TW2 (128 * RS2)

// ---------------- K0: transpose x (NCDHW) -> t_hi/lo [B,N,C] bf16 ----------------
__global__ void k_transpose(const float* __restrict__ x) {
    __shared__ float tile[64 * 65];
    int c0 = blockIdx.x * 64;
    int sp0 = blockIdx.y * 64;
    int b = blockIdx.z;
    int tid = threadIdx.x;
#pragma unroll
    for (int i = 0; i < 16; i++) {
        int idx = i * 256 + tid;
        int c = idx >> 6, s = idx & 63;
        tile[c * 65 + s] = x[(size_t)(b * 256 + c0 + c) * SPA + sp0 + s];
    }
    __syncthreads();
#pragma unroll
    for (int i = 0; i < 16; i++) {
        int idx = i * 256 + tid;
        int s = idx >> 6, c = idx & 63;
        int sp = sp0 + s;
        int d = sp >> 10, rem = sp & 1023, h = rem >> 5, w = rem & 31;
        int n = h * 256 + w * 8 + d;
        float v = tile[c * 65 + s];
        __nv_bfloat16 hi = __float2bfloat16(v);
        size_t gi = (size_t)(b * 8192 + n) * 256 + c0 + c;
        g_t_hi[gi] = hi;
        g_t_lo[gi] = __float2bfloat16(v - __bfloat162float(hi));
    }
}

// ---------------- weight prep: fp32 [K][N] -> bf16 hi/lo [N][K], tiled transpose ----------------
__global__ void k_wtprep(const float* __restrict__ w, __nv_bfloat16* __restrict__ thi,
                         __nv_bfloat16* __restrict__ tlo, int K, int Nn) {
    __shared__ float sm[64 * 65];
    int n0 = blockIdx.x * 64;
    int k0 = blockIdx.y * 64;
    int tid = threadIdx.x;
#pragma unroll
    for (int i = 0; i < 16; i++) {
        int idx = i * 256 + tid;
        int r = idx >> 6, c = idx & 63;
        sm[r * 65 + c] = w[(size_t)(k0 + r) * Nn + n0 + c];
    }
    __syncthreads();
#pragma unroll
    for (int i = 0; i < 16; i++) {
        int idx = i * 256 + tid;
        int r = idx >> 6, c = idx & 63;
        float a = sm[c * 65 + r];
        __nv_bfloat16 h = __float2bfloat16(a);
        size_t gi = (size_t)(n0 + r) * K + k0 + c;
        thi[gi] = h;
        tlo[gi] = __float2bfloat16(a - __bfloat162float(h));
    }
}
__global__ void k_wprep_nt(const float* __restrict__ w, __nv_bfloat16* __restrict__ thi,
                           __nv_bfloat16* __restrict__ tlo, int total) {
    int idx = blockIdx.x * 256 + threadIdx.x;
    if (idx >= total) return;
    float a = w[idx];
    __nv_bfloat16 h = __float2bfloat16(a);
    thi[idx] = h;
    tlo[idx] = __float2bfloat16(a - __bfloat162float(h));
}

// ---------------- HMMA bf16-split GEMM, cp.async 2-stage, 2 CTAs/SM ----------------
__global__ void __launch_bounds__(256, 2) k_mma(const __nv_bfloat16* __restrict__ Ahi,
                                                const __nv_bfloat16* __restrict__ Alo,
                                                const __nv_bfloat16* __restrict__ Bhi,
                                                const __nv_bfloat16* __restrict__ Blo,
                                                const float* __restrict__ bias,
                                                float* __restrict__ C, int K, int Ntot) {
    extern __shared__ __align__(16) uint32_t sm[];
    uint32_t sbase = smem_u32(sm);

    int tid = threadIdx.x;
    int wid = tid >> 5, lane = tid & 31;
    int wr = wid >> 2, wc = wid & 3;
    int row0 = blockIdx.y * 128;
    int col0 = blockIdx.x * 128;
    int lq = lane >> 2, lr = lane & 3;

    float acc[4][4][4] = {};
    int nch = K >> 5;

#define PREFETCH(CH, STG) do {                                                     \
        int _k0 = (CH) << 5;                                                       \
        uint32_t _so = sbase + (STG) * 4 * TW2 * 4;                                \
        _Pragma("unroll")                                                          \
        for (int _i = 0; _i < 2; _i++) {                                           \
            int _idx = tid + _i * 256;                                             \
            int _r = _idx >> 2, _g = _idx & 3;                                     \
            uint32_t _d = _so + (_r * RS2 + _g * 4) * 4;                           \
            const __nv_bfloat16* _s = Ahi + (size_t)(row0 + _r) * K + _k0 + _g * 8;\
            CP_ASYNC16(_d, _s);                                                    \
            _d += TW2 * 4;                                                         \
            _s = Alo + (size_t)(row0 + _r) * K + _k0 + _g * 8;                     \
            CP_ASYNC16(_d, _s);                                                    \
            _d += TW2 * 4;                                                         \
            _s = Bhi + (size_t)(col0 + _r) * K + _k0 + _g * 8;                     \
            CP_ASYNC16(_d, _s);                                                    \
            _d += TW2 * 4;                                                         \
            _s = Blo + (size_t)(col0 + _r) * K + _k0 + _g * 8;                     \
            CP_ASYNC16(_d, _s);                                                    \
        }                                                                          \
    } while (0)

    PREFETCH(0, 0);
    CP_COMMIT();

    for (int ch = 0; ch < nch; ch++) {
        if (ch + 1 < nch) {
            PREFETCH(ch + 1, (ch + 1) & 1);
            CP_COMMIT();
            CP_WAIT1();
        } else {
            CP_WAIT0();
        }
        __syncthreads();
        uint32_t* base = sm + (ch & 1) * 4 * TW2;
        uint32_t* sAhi = base;
        uint32_t* sAlo = base + TW2;
        uint32_t* sBhi = base + 2 * TW2;
        uint32_t* sBlo = base + 3 * TW2;
#pragma unroll
        for (int ks = 0; ks < 2; ks++) {
            int kw = ks * 8;
            uint32_t bh[4][2], bl[4][2];
#pragma unroll
            for (int nt = 0; nt < 4; nt++) {
                int n = wc * 32 + nt * 8 + lq;
                bh[nt][0] = sBhi[n * RS2 + kw + lr];
                bh[nt][1] = sBhi[n * RS2 + kw + lr + 4];
                bl[nt][0] = sBlo[n * RS2 + kw + lr];
                bl[nt][1] = sBlo[n * RS2 + kw + lr + 4];
            }
#pragma unroll
            for (int mt = 0; mt < 4; mt++) {
                int r = wr * 64 + mt * 16 + lq;
                uint32_t ah[4], al[4];
                ah[0] = sAhi[r * RS2 + kw + lr];
                ah[1] = sAhi[(r + 8) * RS2 + kw + lr];
                ah[2] = sAhi[r * RS2 + kw + lr + 4];
                ah[3] = sAhi[(r + 8) * RS2 + kw + lr + 4];
                al[0] = sAlo[r * RS2 + kw + lr];
                al[1] = sAlo[(r + 8) * RS2 + kw + lr];
                al[2] = sAlo[r * RS2 + kw + lr + 4];
                al[3] = sAlo[(r + 8) * RS2 + kw + lr + 4];
#pragma unroll
                for (int nt = 0; nt < 4; nt++) {
                    mma16816(acc[mt][nt], ah, bh[nt]);
                    mma16816(acc[mt][nt], ah, bl[nt]);
                    mma16816(acc[mt][nt], al, bh[nt]);
                }
            }
        }
        __syncthreads();
    }
#undef PREFETCH
#pragma unroll
    for (int mt = 0; mt < 4; mt++) {
        int r = row0 + wr * 64 + mt * 16 + lq;
#pragma unroll
        for (int nt = 0; nt < 4; nt++) {
            int c = col0 + wc * 32 + nt * 8 + lr * 2;
            float b0 = bias ? bias[c] : 0.0f;
            float b1 = bias ? bias[c + 1] : 0.0f;
            float2 v0, v1;
            v0.x = acc[mt][nt][0] + b0;
            v0.y = acc[mt][nt][1] + b1;
            v1.x = acc[mt][nt][2] + b0;
            v1.y = acc[mt][nt][3] + b1;
            *(float2*)&C[(size_t)r * Ntot + c] = v0;
            *(float2*)&C[(size_t)(r + 8) * Ntot + c] = v1;
        }
    }
}
#define SMEM_MMA (8 * TW2 * 4)

// ---------------- column L2 norms for q,k ----------------
__global__ void k_cnpart(const float* __restrict__ qkv) {
    int chunk = blockIdx.x;
    int b = blockIdx.y;
    int tid = threadIdx.x;
    float s0 = 0.f, s1 = 0.f;
    int n0 = chunk * 128;
    for (int n = n0; n < n0 + 128; n++) {
        const float* row = qkv + (size_t)(b * 8192 + n) * 768;
        float v0 = row[tid];
        float v1 = row[256 + tid];
        s0 += v0 * v0;
        s1 += v1 * v1;
    }
    g_cnpart[(b * 64 + chunk) * 512 + tid] = s0;
    g_cnpart[(b * 64 + chunk) * 512 + 256 + tid] = s1;
}

__global__ void k_cnfin() {
    int idx = blockIdx.x * 256 + threadIdx.x;
    int b = idx >> 9, col = idx & 511;
    float s = 0.f;
#pragma unroll
    for (int ch = 0; ch < 64; ch++) s += g_cnpart[(b * 64 + ch) * 512 + col];
    g_rnorm[idx] = 1.0f / fmaxf(sqrtf(s), 1e-12f);
}

// ---------------- kp/vp projections on HMMA ----------------
#define SMEM_KV (64 * 65 * 4 + 4 * 64 * RS * 4)
__global__ void __launch_bounds__(128) k_kvproj(const float* __restrict__ qkv,
                                                const __nv_bfloat16* __restrict__ wsThi,
                                                const __nv_bfloat16* __restrict__ wsTlo) {
    extern __shared__ __align__(16) char smraw[];
    float* sF = (float*)smraw;
    uint32_t* sAhi = (uint32_t*)(smraw + 64 * 65 * 4);
    uint32_t* sAlo = sAhi + 64 * RS;
    uint32_t* sBhi = sAlo + 64 * RS;
    uint32_t* sBlo = sBhi + 64 * RS;

    int slice = blockIdx.x;
    int bh = blockIdx.y;
    int kind = blockIdx.z;
    int b = bh >> 2, h = bh & 3;
    int colbase = (kind == 0 ? 256 : 512) + h * 64;
    int tid = threadIdx.x;
    int wid = tid >> 5, lane = tid & 31;
    int wr = wid >> 1, wc = wid & 1;
    int lq = lane >> 2, lr = lane & 3;
    int wa = lane & 7, wb = lane >> 3;

    float acc[2][4][4] = {};

    int nbeg = slice * 512;
    for (int ch = 0; ch < 8; ch++) {
        int n0 = nbeg + ch * 64;
#pragma unroll
        for (int i = 0; i < 8; i++) {
            int idx = tid + i * 128;
            int r = idx >> 4, c4 = idx & 15;
            float4 v = *(const float4*)&qkv[(size_t)(b * 8192 + n0 + r) * 768 + colbase + c4 * 4];
            float* dst = &sF[r * 65 + c4 * 4];
            dst[0] = v.x; dst[1] = v.y; dst[2] = v.z; dst[3] = v.w;
        }
#pragma unroll
        for (int i = 0; i < 4; i++) {
            int idx = tid + i * 128;
            int r = idx >> 3, q = idx & 7;
            *(uint4*)&sBhi[r * RS + q * 4] = *(const uint4*)&wsThi[(size_t)r * 8192 + n0 + q * 8];
            *(uint4*)&sBlo[r * RS + q * 4] = *(const uint4*)&wsTlo[(size_t)r * 8192 + n0 + q * 8];
        }
        __syncthreads();
#pragma unroll
        for (int ia = 0; ia < 2; ia++) {
            int e = wid * 16 + 8 * ia + wa;
#pragma unroll
            for (int inp = 0; inp < 8; inp++) {
                int np = 4 * inp + wb;
                float v0 = sF[(2 * np) * 65 + e];
                float v1 = sF[(2 * np + 1) * 65 + e];
                sAhi[e * RS + np] = pack_bf16_hi(v0, v1);
                sAlo[e * RS + np] = pack_bf16_lo(v0, v1);
            }
        }
        __syncthreads();
#pragma unroll
        for (int ks = 0; ks < 4; ks++) {
            int kw = ks * 8;
            uint32_t bhf[4][2], blf[4][2];
#pragma unroll
            for (int nt = 0; nt < 4; nt++) {
                int nrow = wc * 32 + nt * 8 + lq;
                bhf[nt][0] = sBhi[nrow * RS + kw + lr];
                bhf[nt][1] = sBhi[nrow * RS + kw + lr + 4];
                blf[nt][0] = sBlo[nrow * RS + kw + lr];
                blf[nt][1] = sBlo[nrow * RS + kw + lr + 4];
            }
#pragma unroll
            for (int mt = 0; mt < 2; mt++) {
                int r = wr * 32 + mt * 16 + lq;
                uint32_t ah[4], al[4];
                ah[0] = sAhi[r * RS + kw + lr];
                ah[1] = sAhi[(r + 8) * RS + kw + lr];
                ah[2] = sAhi[r * RS + kw + lr + 4];
                ah[3] = sAhi[(r + 8) * RS + kw + lr + 4];
                al[0] = sAlo[r * RS + kw + lr];
                al[1] = sAlo[(r + 8) * RS + kw + lr];
                al[2] = sAlo[r * RS + kw + lr + 4];
                al[3] = sAlo[(r + 8) * RS + kw + lr + 4];
#pragma unroll
                for (int nt = 0; nt < 4; nt++) {
                    mma16816(acc[mt][nt], ah, bhf[nt]);
                    mma16816(acc[mt][nt], ah, blf[nt]);
                    mma16816(acc[mt][nt], al, bhf[nt]);
                }
            }
        }
        __syncthreads();
    }
    float* dst = g_kvpart + (size_t)((kind * 16 + bh) * 16 + slice) * 4096;
#pragma unroll
    for (int mt = 0; mt < 2; mt++) {
        int e = wr * 32 + mt * 16 + lq;
#pragma unroll
        for (int nt = 0; nt < 4; nt++) {
            int p = wc * 32 + nt * 8 + lr * 2;
            *(float2*)&dst[e * 64 + p] = make_float2(acc[mt][nt][0], acc[mt][nt][1]);
            *(float2*)&dst[(e + 8) * 64 + p] = make_float2(acc[mt][nt][2], acc[mt][nt][3]);
        }
    }
}

// reduce + bias + fold norms; emit kpT (scaled, transposed) and vp as bf16 hi/lo
__global__ void k_kvred(const float* __restrict__ bseq) {
    int idx = blockIdx.x * 256 + threadIdx.x;   // 131072 total
    int kb = idx >> 12;                          // kind*16+bh
    int ep = idx & 4095;
    float s = 0.f;
#pragma unroll
    for (int sl = 0; sl < 16; sl++) s += g_kvpart[(size_t)(kb * 16 + sl) * 4096 + ep];
    int kind = kb >> 4, bh = kb & 15;
    int b = bh >> 2, h = bh & 3;
    int e = ep >> 6, p = ep & 63;
    if (kind == 0) {
        // kp value = rn_k[e]*proj + bias; fold q-norm rn_q[e]; store transposed [p][e]
        float v = s * g_rnorm[b * 512 + 256 + h * 64 + e] + bseq[p];
        v *= g_rnorm[b * 512 + h * 64 + e];
        __nv_bfloat16 hi = __float2bfloat16(v);
        g_kpT_hi[bh * 4096 + p * 64 + e] = hi;
        g_kpT_lo[bh * 4096 + p * 64 + e] = __float2bfloat16(v - __bfloat162float(hi));
    } else {
        float v = s + bseq[p];
        __nv_bfloat16 hi = __float2bfloat16(v);
        g_vp_hi[bh * 4096 + ep] = hi;
        g_vp_lo[bh * 4096 + ep] = __float2bfloat16(v - __bfloat162float(hi));
    }
}

// ---------------- fused attention on HMMA ----------------
// Per CTA: 128 tokens of one (b,h). MMA1 (q@kpT) -> in-register softmax
// (accumulator layout == next A-fragment layout) -> MMA2 (probs@vp).
#define SMEM_AT ((128 * RS * 2 + 64 * RS * 4) * 4)
__global__ void __launch_bounds__(128) k_attn(const float* __restrict__ qkv,
                                              const float* __restrict__ temp) {
    extern __shared__ __align__(16) uint32_t sm[];
    uint32_t* sQhi = sm;
    uint32_t* sQlo = sm + 128 * RS;
    uint32_t* sKhi = sm + 256 * RS;
    uint32_t* sKlo = sKhi + 64 * RS;
    uint32_t* sVhi = sKlo + 64 * RS;
    uint32_t* sVlo = sVhi + 64 * RS;

    int tid = threadIdx.x;
    int wid = tid >> 5, lane = tid & 31;
    int lq = lane >> 2, lr = lane & 3;
    int h = blockIdx.y, b = blockIdx.z;
    int bh = b * 4 + h;
    int tok0 = blockIdx.x * 128;

    // load kpT/vp bf16 frag tiles (64 rows x 64 bf16 = 8 uint4 per row)
    {
        const uint4* skh = (const uint4*)(g_kpT_hi + (size_t)bh * 4096);
        const uint4* skl = (const uint4*)(g_kpT_lo + (size_t)bh * 4096);
        const uint4* svh = (const uint4*)(g_vp_hi + (size_t)bh * 4096);
        const uint4* svl = (const uint4*)(g_vp_lo + (size_t)bh * 4096);
#pragma unroll
        for (int i = 0; i < 4; i++) {
            int idx = tid + i * 128;
            int r = idx >> 3, q = idx & 7;
            *(uint4*)&sKhi[r * RS + q * 4] = skh[idx];
            *(uint4*)&sKlo[r * RS + q * 4] = skl[idx];
            *(uint4*)&sVhi[r * RS + q * 4] = svh[idx];
            *(uint4*)&sVlo[r * RS + q * 4] = svl[idx];
        }
    }
    // load q tile fp32 -> bf16 hi/lo A frags [tok][e-word]
#pragma unroll
    for (int i = 0; i < 16; i++) {
        int idx = tid + i * 128;
        int r = idx >> 4, c4 = idx & 15;
        float4 v = *(const float4*)&qkv[(size_t)(b * 8192 + tok0 + r) * 768 + h * 64 + c4 * 4];
        sQhi[r * RS + c4 * 2]     = pack_bf16_hi(v.x, v.y);
        sQhi[r * RS + c4 * 2 + 1] = pack_bf16_hi(v.z, v.w);
        sQlo[r * RS + c4 * 2]     = pack_bf16_lo(v.x, v.y);
        sQlo[r * RS + c4 * 2 + 1] = pack_bf16_lo(v.z, v.w);
    }
    __syncthreads();
    float tv = temp[h];

    // --- MMA1: logits [128 tok x 64 p], warp tile 32x64 ---
    float acc1[2][8][4] = {};
#pragma unroll
    for (int ks = 0; ks < 4; ks++) {
        int kw = ks * 8;
        uint32_t qh[2][4], ql2[2][4];
#pragma unroll
        for (int mt = 0; mt < 2; mt++) {
            int r = wid * 32 + mt * 16 + lq;
            qh[mt][0]  = sQhi[r * RS + kw + lr];
            qh[mt][1]  = sQhi[(r + 8) * RS + kw + lr];
            qh[mt][2]  = sQhi[r * RS + kw + lr + 4];
            qh[mt][3]  = sQhi[(r + 8) * RS + kw + lr + 4];
            ql2[mt][0] = sQlo[r * RS + kw + lr];
            ql2[mt][1] = sQlo[(r + 8) * RS + kw + lr];
            ql2[mt][2] = sQlo[r * RS + kw + lr + 4];
            ql2[mt][3] = sQlo[(r + 8) * RS + kw + lr + 4];
        }
#pragma unroll
        for (int nt = 0; nt < 8; nt++) {
            int n = nt * 8 + lq;
            uint32_t bh2[2], bl2[2];
            bh2[0] = sKhi[n * RS + kw + lr];
            bh2[1] = sKhi[n * RS + kw + lr + 4];
            bl2[0] = sKlo[n * RS + kw + lr];
            bl2[1] = sKlo[n * RS + kw + lr + 4];
#pragma unroll
            for (int mt = 0; mt < 2; mt++) {
                mma16816(acc1[mt][nt], qh[mt], bh2);
                mma16816(acc1[mt][nt], qh[mt], bl2);
                mma16816(acc1[mt][nt], ql2[mt], bh2);
            }
        }
    }

    // --- softmax in registers; repack probs as A-frags ---
    uint32_t pa_hi[2][4][4], pa_lo[2][4][4];
#pragma unroll
    for (int mt = 0; mt < 2; mt++) {
#pragma unroll
        for (int nt = 0; nt < 8; nt++)
#pragma unroll
            for (int j = 0; j < 4; j++) acc1[mt][nt][j] *= tv;
        float m0 = -1e30f, m1 = -1e30f;
#pragma unroll
        for (int nt = 0; nt < 8; nt++) {
            m0 = fmaxf(m0, fmaxf(acc1[mt][nt][0], acc1[mt][nt][1]));
            m1 = fmaxf(m1, fmaxf(acc1[mt][nt][2], acc1[mt][nt][3]));
        }
        m0 = fmaxf(m0, __shfl_xor_sync(0xffffffffu, m0, 1));
        m0 = fmaxf(m0, __shfl_xor_sync(0xffffffffu, m0, 2));
        m1 = fmaxf(m1, __shfl_xor_sync(0xffffffffu, m1, 1));
        m1 = fmaxf(m1, __shfl_xor_sync(0xffffffffu, m1, 2));
        float s0 = 0.f, s1 = 0.f;
#pragma unroll
        for (int nt = 0; nt < 8; nt++) {
            acc1[mt][nt][0] = __expf(acc1[mt][nt][0] - m0);
            acc1[mt][nt][1] = __expf(acc1[mt][nt][1] - m0);
            acc1[mt][nt][2] = __expf(acc1[mt][nt][2] - m1);
            acc1[mt][nt][3] = __expf(acc1[mt][nt][3] - m1);
            s0 += acc1[mt][nt][0] + acc1[mt][nt][1];
            s1 += acc1[mt][nt][2] + acc1[mt][nt][3];
        }
        s0 += __shfl_xor_sync(0xffffffffu, s0, 1);
        s0 += __shfl_xor_sync(0xffffffffu, s0, 2);
        s1 += __shfl_xor_sync(0xffffffffu, s1, 1);
        s1 += __shfl_xor_sync(0xffffffffu, s1, 2);
        float i0 = 1.0f / s0, i1 = 1.0f / s1;
#pragma unroll
        for (int nt = 0; nt < 8; nt++) {
            acc1[mt][nt][0] *= i0; acc1[mt][nt][1] *= i0;
            acc1[mt][nt][2] *= i1; acc1[mt][nt][3] *= i1;
        }
        // accumulator layout == A-fragment layout (K=p): pack hi/lo
#pragma unroll
        for (int ks = 0; ks < 4; ks++) {
            pa_hi[mt][ks][0] = pack_bf16_hi(acc1[mt][2*ks][0],   acc1[mt][2*ks][1]);
            pa_hi[mt][ks][1] = pack_bf16_hi(acc1[mt][2*ks][2],   acc1[mt][2*ks][3]);
            pa_hi[mt][ks][2] = pack_bf16_hi(acc1[mt][2*ks+1][0], acc1[mt][2*ks+1][1]);
            pa_hi[mt][ks][3] = pack_bf16_hi(acc1[mt][2*ks+1][2], acc1[mt][2*ks+1][3]);
            pa_lo[mt][ks][0] = pack_bf16_lo(acc1[mt][2*ks][0],   acc1[mt][2*ks][1]);
            pa_lo[mt][ks][1] = pack_bf16_lo(acc1[mt][2*ks][2],   acc1[mt][2*ks][3]);
            pa_lo[mt][ks][2] = pack_bf16_lo(acc1[mt][2*ks+1][0], acc1[mt][2*ks+1][1]);
            pa_lo[mt][ks][3] = pack_bf16_lo(acc1[mt][2*ks+1][2], acc1[mt][2*ks+1][3]);
        }
    }

    // --- MMA2: o [128 tok x 64 e] = probs @ vp ---
    float acc2[2][8][4] = {};
#pragma unroll
    for (int ks = 0; ks < 4; ks++) {
        int kw = ks * 8;
#pragma unroll
        for (int nt = 0; nt < 8; nt++) {
            int n = nt * 8 + lq;
            uint32_t bh2[2], bl2[2];
            bh2[0] = sVhi[n * RS + kw + lr];
            bh2[1] = sVhi[n * RS + kw + lr + 4];
            bl2[0] = sVlo[n * RS + kw + lr];
            bl2[1] = sVlo[n * RS + kw + lr + 4];
#pragma unroll
            for (int mt = 0; mt < 2; mt++) {
                mma16816(acc2[mt][nt], pa_hi[mt][ks], bh2);
                mma16816(acc2[mt][nt], pa_hi[mt][ks], bl2);
                mma16816(acc2[mt][nt], pa_lo[mt][ks], bh2);
            }
        }
    }

    // --- epilogue: write o as bf16 hi/lo ---
#pragma unroll
    for (int mt = 0; mt < 2; mt++) {
        int r0 = wid * 32 + mt * 16 + lq;
#pragma unroll
        for (int nt = 0; nt < 8; nt++) {
            int e = nt * 8 + lr * 2;
            size_t off0 = (size_t)(b * 8192 + tok0 + r0) * 256 + h * 64 + e;
            size_t off1 = (size_t)(b * 8192 + tok0 + r0 + 8) * 256 + h * 64 + e;
            *(uint32_t*)(g_o_hi + off0) = pack_bf16_hi(acc2[mt][nt][0], acc2[mt][nt][1]);
            *(uint32_t*)(g_o_lo + off0) = pack_bf16_lo(acc2[mt][nt][0], acc2[mt][nt][1]);
            *(uint32_t*)(g_o_hi + off1) = pack_bf16_hi(acc2[mt][nt][2], acc2[mt][nt][3]);
            *(uint32_t*)(g_o_lo + off1) = pack_bf16_lo(acc2[mt][nt][2], acc2[mt][nt][3]);
        }
    }
}

// ---------------- LayerNorm stats per token ----------------
__global__ void k_lnstat() {
    int tid = threadIdx.x;
    int warp = tid >> 5, lane = tid & 31;
    int t = blockIdx.x * 8 + warp;
    const float4* row = (const float4*)(g_o2 + (size_t)t * 256);
    float s = 0.f, sq = 0.f;
#pragma unroll
    for (int j = 0; j < 2; j++) {
        float4 v = row[j * 32 + lane];
        s  += v.x + v.y + v.z + v.w;
        sq += v.x * v.x + v.y * v.y + v.z * v.z + v.w * v.w;
    }
#pragma unroll
    for (int off = 16; off; off >>= 1) {
        s  += __shfl_xor_sync(0xffffffffu, s, off);
        sq += __shfl_xor_sync(0xffffffffu, sq, off);
    }
    if (lane == 0) {
        float mu = s * (1.0f / 256.0f);
        float var = sq * (1.0f / 256.0f) - mu * mu;
        g_mu[t] = mu;
        g_rs[t] = rsqrtf(var + 1e-5f);
    }
}

// ---------------- LN apply + residual + restore NCDHW ----------------
__global__ void k_lnapply(const float* __restrict__ x, const float* __restrict__ g,
                          const float* __restrict__ be) {
    __shared__ float tl[64 * 65];
    __shared__ float mus[64], rss[64];
    int c0 = blockIdx.x * 64;
    int sp0 = blockIdx.y * 64;
    int b = blockIdx.z;
    int tid = threadIdx.x;
    if (tid < 64) {
        int sp = sp0 + tid;
        int d = sp >> 10, rem = sp & 1023, h = rem >> 5, w = rem & 31;
        int n = h * 256 + w * 8 + d;
        mus[tid] = g_mu[b * 8192 + n];
        rss[tid] = g_rs[b * 8192 + n];
    }
#pragma unroll
    for (int i = 0; i < 16; i++) {
        int idx = i * 256 + tid;
        int s = idx >> 6, c = idx & 63;
        int sp = sp0 + s;
        int d = sp >> 10, rem = sp & 1023, h = rem >> 5, w = rem & 31;
        int n = h * 256 + w * 8 + d;
        tl[s * 65 + c] = g_o2[(size_t)(b * 8192 + n) * 256 + c0 + c];
    }
    __syncthreads();
#pragma unroll
    for (int i = 0; i < 16; i++) {
        int idx = i * 256 + tid;
        int c = idx >> 6, s = idx & 63;
        float gg = g[c0 + c], bb = be[c0 + c];
        float r = (tl[s * 65 + c] - mus[s]) * rss[s] * gg + bb;
        size_t gi = (size_t)(b * 256 + c0 + c) * SPA + sp0 + s;
        g_y[gi] = x[gi] + r;
    }
}

// ---------------- depthwise 3x3x3 SAME conv (bf16 hi/lo output) ----------------
__global__ void k_dwconv(const float* __restrict__ dwk, const float* __restrict__ dwb) {
    __shared__ float tile[10 * 34 * 34];
    __shared__ float wk[27];
    int bc = blockIdx.x;
    int c = bc & 255;
    int tid = threadIdx.x;
    if (tid < 27) wk[tid] = dwk[c * 27 + tid];
    const float* src = g_y + (size_t)bc * SPA;
    for (int i = tid; i < 11560; i += 256) {
        int dz = i / 1156;
        int rem = i - dz * 1156;
        int hy = rem / 34;
        int wx = rem - hy * 34;
        int d = dz - 1, hh = hy - 1, w = wx - 1;
        float val = 0.f;
        if (d >= 0 && d < 8 && hh >= 0 && hh < 32 && w >= 0 && w < 32)
            val = src[d * 1024 + hh * 32 + w];
        tile[i] = val;
    }
    __syncthreads();
    float bias = dwb[c];
    for (int i = tid; i < 8192; i += 256) {
        int d = i >> 10;
        int r = i & 1023;
        int hh = r >> 5, w = r & 31;
        float acc = 0.f;
#pragma unroll
        for (int kd = 0; kd < 3; kd++)
#pragma unroll
            for (int kh = 0; kh < 3; kh++)
#pragma unroll
                for (int kw = 0; kw < 3; kw++)
                    acc += wk[kd * 9 + kh * 3 + kw]
                         * tile[(d + kd) * 1156 + (hh + kh) * 34 + (w + kw)];
        float v = acc + bias;
        __nv_bfloat16 hi = __float2bfloat16(v);
        g_dw_hi[(size_t)bc * SPA + i] = hi;
        g_dw_lo[(size_t)bc * SPA + i] = __float2bfloat16(v - __bfloat162float(hi));
    }
}

// ---------------- pointwise conv on HMMA + bias + final residual ----------------
__global__ void __launch_bounds__(256, 2) k_pwfin(const float* __restrict__ pwb,
                                                  float* __restrict__ out) {
    extern __shared__ __align__(16) uint32_t sm[];
    uint32_t* sAhi = sm;
    uint32_t* sAlo = sAhi + TILE_W;
    uint32_t* sBhi = sAlo + TILE_W;
    uint32_t* sBlo = sBhi + TILE_W;

    int tid = threadIdx.x;
    int wid = tid >> 5, lane = tid & 31;
    int wr = wid >> 2, wc = wid & 3;
    int sp0 = blockIdx.x * 128;
    int co0 = blockIdx.y * 128;
    int b = blockIdx.z;
    int lq = lane >> 2, lr = lane & 3;

    float acc[4][4][4] = {};

    for (int ci0 = 0; ci0 < 256; ci0 += 64) {
#pragma unroll
        for (int i = 0; i < 4; i++) {
            int idx = tid + i * 256;
            int r = idx >> 3, gq = idx & 7;
            *(uint4*)&sAhi[r * RS + gq * 4] =
                *(const uint4*)&g_pwk_hi[(co0 + r) * 256 + ci0 + gq * 8];
            *(uint4*)&sAlo[r * RS + gq * 4] =
                *(const uint4*)&g_pwk_lo[(co0 + r) * 256 + ci0 + gq * 8];
        }
#pragma unroll
        for (int jl = 0; jl < 4; jl++) {
            int j = jl * 8 + wid;
            size_t rbase = (size_t)(b * 256 + ci0 + 2 * j) * SPA + sp0;
#pragma unroll
            for (int sh = 0; sh < 2; sh++) {
                int slp = (sh * 32 + lane) * 2;
                uint32_t u0 = *(const uint32_t*)(g_dw_hi + rbase + slp);
                uint32_t u1 = *(const uint32_t*)(g_dw_hi + rbase + SPA + slp);
                sBhi[slp * RS + j]       = __byte_perm(u0, u1, 0x5410);
                sBhi[(slp + 1) * RS + j] = __byte_perm(u0, u1, 0x7632);
                u0 = *(const uint32_t*)(g_dw_lo + rbase + slp);
                u1 = *(const uint32_t*)(g_dw_lo + rbase + SPA + slp);
                sBlo[slp * RS + j]       = __byte_perm(u0, u1, 0x5410);
                sBlo[(slp + 1) * RS + j] = __byte_perm(u0, u1, 0x7632);
            }
        }
        __syncthreads();
#pragma unroll
        for (int ks = 0; ks < 4; ks++) {
            int kw = ks * 8;
            uint32_t bh[4][2], bl[4][2];
#pragma unroll
            for (int nt = 0; nt < 4; nt++) {
                int n = wc * 32 + nt * 8 + lq;
                bh[nt][0] = sBhi[n * RS + kw + lr];
                bh[nt][1] = sBhi[n * RS + kw + lr + 4];
                bl[nt][0] = sBlo[n * RS + kw + lr];
                bl[nt][1] = sBlo[n * RS + kw + lr + 4];
            }
#pragma unroll
            for (int mt = 0; mt < 4; mt++) {
                int r = wr * 64 + mt * 16 + lq;
                uint32_t ah[4], al[4];
                ah[0] = sAhi[r * RS + kw + lr];
                ah[1] = sAhi[(r + 8) * RS + kw + lr];
                ah[2] = sAhi[r * RS + kw + lr + 4];
                ah[3] = sAhi[(r + 8) * RS + kw + lr + 4];
                al[0] = sAlo[r * RS + kw + lr];
                al[1] = sAlo[(r + 8) * RS + kw + lr];
                al[2] = sAlo[r * RS + kw + lr + 4];
                al[3] = sAlo[(r + 8) * RS + kw + lr + 4];
#pragma unroll
                for (int nt = 0; nt < 4; nt++) {
                    mma16816(acc[mt][nt], ah, bh[nt]);
                    mma16816(acc[mt][nt], ah, bl[nt]);
                    mma16816(acc[mt][nt], al, bh[nt]);
                }
            }
        }
        __syncthreads();
    }
#pragma unroll
    for (int mt = 0; mt < 4; mt++) {
        int r = co0 + wr * 64 + mt * 16 + lq;
        float bb0 = pwb[r], bb1 = pwb[r + 8];
#pragma unroll
        for (int nt = 0; nt < 4; nt++) {
            int c = sp0 + wc * 32 + nt * 8 + lr * 2;
            size_t i0 = (size_t)(b * 256 + r) * SPA + c;
            size_t i1 = (size_t)(b * 256 + r + 8) * SPA + c;
            float2 y0 = *(const float2*)&g_y[i0];
            float2 y1 = *(const float2*)&g_y[i1];
            float2 v0, v1;
            v0.x = acc[mt][nt][0] + bb0 + y0.x;
            v0.y = acc[mt][nt][1] + bb0 + y0.y;
            v1.x = acc[mt][nt][2] + bb1 + y1.x;
            v1.y = acc[mt][nt][3] + bb1 + y1.y;
            *(float2*)&out[i0] = v0;
            *(float2*)&out[i1] = v1;
        }
    }
}
#define SMEM_PW (4 * TILE_W * 4)

// ---------------- launch ----------------
extern "C" void kernel_launch(void* const* d_in, const int* in_sizes, int n_in,
                              void* d_out, int out_size) {
    (void)in_sizes; (void)n_in; (void)out_size;
    const float* x    = (const float*)d_in[0];
    const float* wqkv = (const float*)d_in[1];
    const float* wseq = (const float*)d_in[2];
    const float* bseq = (const float*)d_in[3];
    const float* temp = (const float*)d_in[4];
    const float* wout = (const float*)d_in[5];
    const float* bout = (const float*)d_in[6];
    const float* lng  = (const float*)d_in[7];
    const float* lnb  = (const float*)d_in[8];
    const float* dwk  = (const float*)d_in[9];
    const float* dwb  = (const float*)d_in[10];
    const float* pwk  = (const float*)d_in[11];
    const float* pwb  = (const float*)d_in[12];
    float* out = (float*)d_out;

    float *qkv, *o2;
    __nv_bfloat16 *t_hi, *t_lo, *o_hi, *o_lo;
    __nv_bfloat16 *wqkvT_hi, *wqkvT_lo, *woutT_hi, *woutT_lo, *pwk_hi, *pwk_lo;
    __nv_bfloat16 *wsT_hi, *wsT_lo;
    cudaGetSymbolAddress((void**)&qkv, g_qkv);
    cudaGetSymbolAddress((void**)&o2,  g_o2);
    cudaGetSymbolAddress((void**)&t_hi, g_t_hi);
    cudaGetSymbolAddress((void**)&t_lo, g_t_lo);
    cudaGetSymbolAddress((void**)&o_hi, g_o_hi);
    cudaGetSymbolAddress((void**)&o_lo, g_o_lo);
    cudaGetSymbolAddress((void**)&wqkvT_hi, g_wqkvT_hi);
    cudaGetSymbolAddress((void**)&wqkvT_lo, g_wqkvT_lo);
    cudaGetSymbolAddress((void**)&woutT_hi, g_woutT_hi);
    cudaGetSymbolAddress((void**)&woutT_lo, g_woutT_lo);
    cudaGetSymbolAddress((void**)&pwk_hi, g_pwk_hi);
    cudaGetSymbolAddress((void**)&pwk_lo, g_pwk_lo);
    cudaGetSymbolAddress((void**)&wsT_hi, g_wsT_hi);
    cudaGetSymbolAddress((void**)&wsT_lo, g_wsT_lo);

    cudaFuncSetAttribute(k_mma, cudaFuncAttributeMaxDynamicSharedMemorySize, SMEM_MMA);
    cudaFuncSetAttribute(k_pwfin, cudaFuncAttributeMaxDynamicSharedMemorySize, SMEM_PW);
    cudaFuncSetAttribute(k_kvproj, cudaFuncAttributeMaxDynamicSharedMemorySize, SMEM_KV);
    cudaFuncSetAttribute(k_attn, cudaFuncAttributeMaxDynamicSharedMemorySize, SMEM_AT);

    // 1. transpose to token-major bf16 hi/lo
    k_transpose<<<dim3(4, 128, 4), 256>>>(x);
    // 2. weight prep
    k_wtprep<<<dim3(12, 4), 256>>>(wqkv, wqkvT_hi, wqkvT_lo, 256, 768);
    k_wtprep<<<dim3(4, 4), 256>>>(wout, woutT_hi, woutT_lo, 256, 256);
    k_wtprep<<<dim3(1, 128), 256>>>(wseq, wsT_hi, wsT_lo, 8192, 64);
    k_wprep_nt<<<256, 256>>>(pwk, pwk_hi, pwk_lo, 256 * 256);
    // 3. QKV GEMM (HMMA, cp.async pipelined, 2 CTA/SM)
    k_mma<<<dim3(6, 256), 256, SMEM_MMA>>>(t_hi, t_lo, wqkvT_hi, wqkvT_lo, nullptr, qkv, 256, 768);
    // 4. column L2 norms
    k_cnpart<<<dim3(64, 4), 256>>>(qkv);
    k_cnfin<<<8, 256>>>();
    // 5. kp/vp projections (HMMA) + reduce w/ norms+bias -> bf16 attn operands
    k_kvproj<<<dim3(16, 16, 2), 128, SMEM_KV>>>(qkv, wsT_hi, wsT_lo);
    k_kvred<<<512, 256>>>(bseq);
    // 6. fused attention (HMMA, in-register softmax)
    k_attn<<<dim3(64, 4, 4), 128, SMEM_AT>>>(qkv, temp);
    // 7. output projection (HMMA)
    k_mma<<<dim3(2, 256), 256, SMEM_MMA>>>(o_hi, o_lo, woutT_hi, woutT_lo, bout, o2, 256, 256);
    // 8. LayerNorm stats + apply/residual/transpose
    k_lnstat<<<4096, 256>>>();
    k_lnapply<<<dim3(4, 128, 4), 256>>>(x, lng, lnb);
    // 9. depthwise conv (bf16 hi/lo out)
    k_dwconv<<<1024, 256>>>(dwk, dwb);
    // 10. pointwise conv (HMMA) + bias + final residual
    k_pwfin<<<dim3(64, 2, 4), 256, SMEM_PW>>>(pwb, out);
}

// round 13
// speedup vs baseline: 2.2429x; 1.0230x over previous
#include <cuda_runtime.h>
#include <cuda_bf16.h>
#include <math.h>
#include <stdint.h>

// Problem constants
#define BQ   4
#define CC   256
#define NHEAD 4
#define PP   64
#define NN   8192
#define SPA  8192

// ---------------- scratch (device globals) ----------------
__device__ __align__(128) __nv_bfloat16 g_t_hi[(size_t)BQ * NN * CC];
__device__ __align__(128) __nv_bfloat16 g_t_lo[(size_t)BQ * NN * CC];
__device__ float g_qkv [(size_t)BQ * NN * 3 * CC];
__device__ float g_cnpart[256 * 512];
__device__ float g_rnorm [BQ * 512];
__device__ float g_kvpart[2 * 16 * 16 * 4096];
// attention operand tiles (bf16 hi/lo): kpT [p][e] (norms folded), vp [e][p]
__device__ __align__(128) __nv_bfloat16 g_kpT_hi[16 * 4096];
__device__ __align__(128) __nv_bfloat16 g_kpT_lo[16 * 4096];
__device__ __align__(128) __nv_bfloat16 g_vp_hi [16 * 4096];
__device__ __align__(128) __nv_bfloat16 g_vp_lo [16 * 4096];
__device__ __align__(128) __nv_bfloat16 g_o_hi[(size_t)BQ * NN * CC];
__device__ __align__(128) __nv_bfloat16 g_o_lo[(size_t)BQ * NN * CC];
__device__ float g_o2  [(size_t)BQ * NN * CC];
__device__ float g_mu  [BQ * NN];
__device__ float g_rs  [BQ * NN];
__device__ float g_y   [(size_t)BQ * CC * SPA];
__device__ __align__(128) __nv_bfloat16 g_dw_hi[(size_t)BQ * CC * SPA];
__device__ __align__(128) __nv_bfloat16 g_dw_lo[(size_t)BQ * CC * SPA];
// transposed bf16 hi/lo weights [N][K]
__device__ __align__(128) __nv_bfloat16 g_wqkvT_hi[768 * 256];
__device__ __align__(128) __nv_bfloat16 g_wqkvT_lo[768 * 256];
__device__ __align__(128) __nv_bfloat16 g_woutT_hi[256 * 256];
__device__ __align__(128) __nv_bfloat16 g_woutT_lo[256 * 256];
__device__ __align__(128) __nv_bfloat16 g_pwk_hi[256 * 256];
__device__ __align__(128) __nv_bfloat16 g_pwk_lo[256 * 256];
__device__ __align__(128) __nv_bfloat16 g_wsT_hi[64 * 8192];
__device__ __align__(128) __nv_bfloat16 g_wsT_lo[64 * 8192];

// ---------------- helpers ----------------
__device__ __forceinline__ uint32_t pack_bf16_hi(float a, float b) {
    __nv_bfloat16 ha = __float2bfloat16(a);
    __nv_bfloat16 hb = __float2bfloat16(b);
    return ((uint32_t)__bfloat16_as_ushort(hb) << 16) | __bfloat16_as_ushort(ha);
}
__device__ __forceinline__ uint32_t pack_bf16_lo(float a, float b) {
    __nv_bfloat16 ha = __float2bfloat16(a);
    __nv_bfloat16 hb = __float2bfloat16(b);
    __nv_bfloat16 la = __float2bfloat16(a - __bfloat162float(ha));
    __nv_bfloat16 lb = __float2bfloat16(b - __bfloat162float(hb));
    return ((uint32_t)__bfloat16_as_ushort(lb) << 16) | __bfloat16_as_ushort(la);
}

__device__ __forceinline__ void mma16816(float* d, const uint32_t* a, const uint32_t* b) {
    asm volatile(
        "mma.sync.aligned.m16n8k16.row.col.f32.bf16.bf16.f32 "
        "{%0,%1,%2,%3}, {%4,%5,%6,%7}, {%8,%9}, {%0,%1,%2,%3};"
        : "+f"(d[0]), "+f"(d[1]), "+f"(d[2]), "+f"(d[3])
        : "r"(a[0]), "r"(a[1]), "r"(a[2]), "r"(a[3]), "r"(b[0]), "r"(b[1]));
}

__device__ __forceinline__ uint32_t smem_u32(const void* p) {
    uint32_t a;
    asm("{ .reg .u64 t; cvta.to.shared.u64 t, %1; cvt.u32.u64 %0, t; }" : "=r"(a) : "l"(p));
    return a;
}
#define CP_ASYNC16(dst, src) \
    asm volatile("cp.async.cg.shared.global [%0], [%1], 16;" :: "r"(dst), "l"(src) : "memory")
#define CP_COMMIT() asm volatile("cp.async.commit_group;" ::: "memory")
#define CP_WAIT1()  asm volatile("cp.async.wait_group 1;" ::: "memory")
#define CP_WAIT0()  asm volatile("cp.async.wait_group 0;" ::: "memory")

#define RS 36                 // smem row stride in words (frag tiles)
#define TILE_W (128 * RS)
#define RS2 20                // k_mma chunk-32 row stride in words
#define TW2 (128 * RS2)

// ---------------- K0: transpose x (NCDHW) -> t_hi/lo [B,N,C] bf16 ----------------
__global__ void k_transpose(const float* __restrict__ x) {
    __shared__ float tile[64 * 65];
    int c0 = blockIdx.x * 64;
    int sp0 = blockIdx.y * 64;
    int b = blockIdx.z;
    int tid = threadIdx.x;
#pragma unroll
    for (int i = 0; i < 16; i++) {
        int idx = i * 256 + tid;
        int c = idx >> 6, s = idx & 63;
        tile[c * 65 + s] = x[(size_t)(b * 256 + c0 + c) * SPA + sp0 + s];
    }
    __syncthreads();
    // packed stores: each thread writes 2 adjacent channels as one uint32
#pragma unroll
    for (int i = 0; i < 8; i++) {
        int idx = i * 256 + tid;           // 2048 total: 64 s x 32 c-pairs
        int s = idx >> 5, c2 = idx & 31;
        int c = c2 * 2;
        int sp = sp0 + s;
        int d = sp >> 10, rem = sp & 1023, h = rem >> 5, w = rem & 31;
        int n = h * 256 + w * 8 + d;
        float v0 = tile[c * 65 + s];
        float v1 = tile[(c + 1) * 65 + s];
        size_t gi = (size_t)(b * 8192 + n) * 256 + c0 + c;
        *(uint32_t*)(g_t_hi + gi) = pack_bf16_hi(v0, v1);
        *(uint32_t*)(g_t_lo + gi) = pack_bf16_lo(v0, v1);
    }
}

// ---------------- merged weight prep: 3 transposing segments in one launch ----------------
// blocks [0,48): wqkv (K=256,Nn=768); [48,64): wout (256,256); [64,192): wseq (8192,64)
__global__ void k_wtprep_all(const float* __restrict__ wqkv,
                             const float* __restrict__ wout,
                             const float* __restrict__ wseq) {
    __shared__ float sm[64 * 65];
    int bid = blockIdx.x;
    const float* w;
    __nv_bfloat16 *thi, *tlo;
    int K, Nn, gx, gy;
    if (bid < 48) {
        w = wqkv; thi = g_wqkvT_hi; tlo = g_wqkvT_lo;
        K = 256; Nn = 768; gx = bid % 12; gy = bid / 12;
    } else if (bid < 64) {
        int b2 = bid - 48;
        w = wout; thi = g_woutT_hi; tlo = g_woutT_lo;
        K = 256; Nn = 256; gx = b2 & 3; gy = b2 >> 2;
    } else {
        int b3 = bid - 64;
        w = wseq; thi = g_wsT_hi; tlo = g_wsT_lo;
        K = 8192; Nn = 64; gx = 0; gy = b3;
    }
    int n0 = gx * 64;
    int k0 = gy * 64;
    int tid = threadIdx.x;
#pragma unroll
    for (int i = 0; i < 16; i++) {
        int idx = i * 256 + tid;
        int r = idx >> 6, c = idx & 63;
        sm[r * 65 + c] = w[(size_t)(k0 + r) * Nn + n0 + c];
    }
    __syncthreads();
#pragma unroll
    for (int i = 0; i < 16; i++) {
        int idx = i * 256 + tid;
        int r = idx >> 6, c = idx & 63;
        float a = sm[c * 65 + r];
        __nv_bfloat16 h = __float2bfloat16(a);
        size_t gi = (size_t)(n0 + r) * K + k0 + c;
        thi[gi] = h;
        tlo[gi] = __float2bfloat16(a - __bfloat162float(h));
    }
}
__global__ void k_wprep_nt(const float* __restrict__ w, __nv_bfloat16* __restrict__ thi,
                           __nv_bfloat16* __restrict__ tlo, int total) {
    int idx = blockIdx.x * 256 + threadIdx.x;
    if (idx >= total) return;
    float a = w[idx];
    __nv_bfloat16 h = __float2bfloat16(a);
    thi[idx] = h;
    tlo[idx] = __float2bfloat16(a - __bfloat162float(h));
}

// ---------------- HMMA bf16-split GEMM, cp.async 2-stage, 2 CTAs/SM ----------------
__global__ void __launch_bounds__(256, 2) k_mma(const __nv_bfloat16* __restrict__ Ahi,
                                                const __nv_bfloat16* __restrict__ Alo,
                                                const __nv_bfloat16* __restrict__ Bhi,
                                                const __nv_bfloat16* __restrict__ Blo,
                                                const float* __restrict__ bias,
                                                float* __restrict__ C, int K, int Ntot) {
    extern __shared__ __align__(16) uint32_t sm[];
    uint32_t sbase = smem_u32(sm);

    int tid = threadIdx.x;
    int wid = tid >> 5, lane = tid & 31;
    int wr = wid >> 2, wc = wid & 3;
    int row0 = blockIdx.y * 128;
    int col0 = blockIdx.x * 128;
    int lq = lane >> 2, lr = lane & 3;

    float acc[4][4][4] = {};
    int nch = K >> 5;

#define PREFETCH(CH, STG) do {                                                     \
        int _k0 = (CH) << 5;                                                       \
        uint32_t _so = sbase + (STG) * 4 * TW2 * 4;                                \
        _Pragma("unroll")                                                          \
        for (int _i = 0; _i < 2; _i++) {                                           \
            int _idx = tid + _i * 256;                                             \
            int _r = _idx >> 2, _g = _idx & 3;                                     \
            uint32_t _d = _so + (_r * RS2 + _g * 4) * 4;                           \
            const __nv_bfloat16* _s = Ahi + (size_t)(row0 + _r) * K + _k0 + _g * 8;\
            CP_ASYNC16(_d, _s);                                                    \
            _d += TW2 * 4;                                                         \
            _s = Alo + (size_t)(row0 + _r) * K + _k0 + _g * 8;                     \
            CP_ASYNC16(_d, _s);                                                    \
            _d += TW2 * 4;                                                         \
            _s = Bhi + (size_t)(col0 + _r) * K + _k0 + _g * 8;                     \
            CP_ASYNC16(_d, _s);                                                    \
            _d += TW2 * 4;                                                         \
            _s = Blo + (size_t)(col0 + _r) * K + _k0 + _g * 8;                     \
            CP_ASYNC16(_d, _s);                                                    \
        }                                                                          \
    } while (0)

    PREFETCH(0, 0);
    CP_COMMIT();

    for (int ch = 0; ch < nch; ch++) {
        if (ch + 1 < nch) {
            PREFETCH(ch + 1, (ch + 1) & 1);
            CP_COMMIT();
            CP_WAIT1();
        } else {
            CP_WAIT0();
        }
        __syncthreads();
        uint32_t* base = sm + (ch & 1) * 4 * TW2;
        uint32_t* sAhi = base;
        uint32_t* sAlo = base + TW2;
        uint32_t* sBhi = base + 2 * TW2;
        uint32_t* sBlo = base + 3 * TW2;
#pragma unroll
        for (int ks = 0; ks < 2; ks++) {
            int kw = ks * 8;
            uint32_t bh[4][2], bl[4][2];
#pragma unroll
            for (int nt = 0; nt < 4; nt++) {
                int n = wc * 32 + nt * 8 + lq;
                bh[nt][0] = sBhi[n * RS2 + kw + lr];
                bh[nt][1] = sBhi[n * RS2 + kw + lr + 4];
                bl[nt][0] = sBlo[n * RS2 + kw + lr];
                bl[nt][1] = sBlo[n * RS2 + kw + lr + 4];
            }
#pragma unroll
            for (int mt = 0; mt < 4; mt++) {
                int r = wr * 64 + mt * 16 + lq;
                uint32_t ah[4], al[4];
                ah[0] = sAhi[r * RS2 + kw + lr];
                ah[1] = sAhi[(r + 8) * RS2 + kw + lr];
                ah[2] = sAhi[r * RS2 + kw + lr + 4];
                ah[3] = sAhi[(r + 8) * RS2 + kw + lr + 4];
                al[0] = sAlo[r * RS2 + kw + lr];
                al[1] = sAlo[(r + 8) * RS2 + kw + lr];
                al[2] = sAlo[r * RS2 + kw + lr + 4];
                al[3] = sAlo[(r + 8) * RS2 + kw + lr + 4];
#pragma unroll
                for (int nt = 0; nt < 4; nt++) {
                    mma16816(acc[mt][nt], ah, bh[nt]);
                    mma16816(acc[mt][nt], ah, bl[nt]);
                    mma16816(acc[mt][nt], al, bh[nt]);
                }
            }
        }
        __syncthreads();
    }
#undef PREFETCH
#pragma unroll
    for (int mt = 0; mt < 4; mt++) {
        int r = row0 + wr * 64 + mt * 16 + lq;
#pragma unroll
        for (int nt = 0; nt < 4; nt++) {
            int c = col0 + wc * 32 + nt * 8 + lr * 2;
            float b0 = bias ? bias[c] : 0.0f;
            float b1 = bias ? bias[c + 1] : 0.0f;
            float2 v0, v1;
            v0.x = acc[mt][nt][0] + b0;
            v0.y = acc[mt][nt][1] + b1;
            v1.x = acc[mt][nt][2] + b0;
            v1.y = acc[mt][nt][3] + b1;
            *(float2*)&C[(size_t)r * Ntot + c] = v0;
            *(float2*)&C[(size_t)(r + 8) * Ntot + c] = v1;
        }
    }
}
#define SMEM_MMA (8 * TW2 * 4)

// ---------------- column L2 norms for q,k ----------------
__global__ void k_cnpart(const float* __restrict__ qkv) {
    int chunk = blockIdx.x;
    int b = blockIdx.y;
    int tid = threadIdx.x;
    float s0 = 0.f, s1 = 0.f;
    int n0 = chunk * 128;
    const float* base = qkv + (size_t)(b * 8192 + n0) * 768;
#pragma unroll 4
    for (int j = 0; j < 128; j++) {
        const float* row = base + (size_t)j * 768;
        float v0 = row[tid];
        float v1 = row[256 + tid];
        s0 += v0 * v0;
        s1 += v1 * v1;
    }
    g_cnpart[(b * 64 + chunk) * 512 + tid] = s0;
    g_cnpart[(b * 64 + chunk) * 512 + 256 + tid] = s1;
}

__global__ void k_cnfin() {
    int idx = blockIdx.x * 256 + threadIdx.x;
    int b = idx >> 9, col = idx & 511;
    float s = 0.f;
#pragma unroll
    for (int ch = 0; ch < 64; ch++) s += g_cnpart[(b * 64 + ch) * 512 + col];
    g_rnorm[idx] = 1.0f / fmaxf(sqrtf(s), 1e-12f);
}

// ---------------- kp/vp projections on HMMA ----------------
#define SMEM_KV (64 * 65 * 4 + 4 * 64 * RS * 4)
__global__ void __launch_bounds__(128) k_kvproj(const float* __restrict__ qkv,
                                                const __nv_bfloat16* __restrict__ wsThi,
                                                const __nv_bfloat16* __restrict__ wsTlo) {
    extern __shared__ __align__(16) char smraw[];
    float* sF = (float*)smraw;
    uint32_t* sAhi = (uint32_t*)(smraw + 64 * 65 * 4);
    uint32_t* sAlo = sAhi + 64 * RS;
    uint32_t* sBhi = sAlo + 64 * RS;
    uint32_t* sBlo = sBhi + 64 * RS;

    int slice = blockIdx.x;
    int bh = blockIdx.y;
    int kind = blockIdx.z;
    int b = bh >> 2, h = bh & 3;
    int colbase = (kind == 0 ? 256 : 512) + h * 64;
    int tid = threadIdx.x;
    int wid = tid >> 5, lane = tid & 31;
    int wr = wid >> 1, wc = wid & 1;
    int lq = lane >> 2, lr = lane & 3;
    int wa = lane & 7, wb = lane >> 3;

    float acc[2][4][4] = {};

    int nbeg = slice * 512;
    for (int ch = 0; ch < 8; ch++) {
        int n0 = nbeg + ch * 64;
#pragma unroll
        for (int i = 0; i < 8; i++) {
            int idx = tid + i * 128;
            int r = idx >> 4, c4 = idx & 15;
            float4 v = *(const float4*)&qkv[(size_t)(b * 8192 + n0 + r) * 768 + colbase + c4 * 4];
            float* dst = &sF[r * 65 + c4 * 4];
            dst[0] = v.x; dst[1] = v.y; dst[2] = v.z; dst[3] = v.w;
        }
#pragma unroll
        for (int i = 0; i < 4; i++) {
            int idx = tid + i * 128;
            int r = idx >> 3, q = idx & 7;
            *(uint4*)&sBhi[r * RS + q * 4] = *(const uint4*)&wsThi[(size_t)r * 8192 + n0 + q * 8];
            *(uint4*)&sBlo[r * RS + q * 4] = *(const uint4*)&wsTlo[(size_t)r * 8192 + n0 + q * 8];
        }
        __syncthreads();
#pragma unroll
        for (int ia = 0; ia < 2; ia++) {
            int e = wid * 16 + 8 * ia + wa;
#pragma unroll
            for (int inp = 0; inp < 8; inp++) {
                int np = 4 * inp + wb;
                float v0 = sF[(2 * np) * 65 + e];
                float v1 = sF[(2 * np + 1) * 65 + e];
                sAhi[e * RS + np] = pack_bf16_hi(v0, v1);
                sAlo[e * RS + np] = pack_bf16_lo(v0, v1);
            }
        }
        __syncthreads();
#pragma unroll
        for (int ks = 0; ks < 4; ks++) {
            int kw = ks * 8;
            uint32_t bhf[4][2], blf[4][2];
#pragma unroll
            for (int nt = 0; nt < 4; nt++) {
                int nrow = wc * 32 + nt * 8 + lq;
                bhf[nt][0] = sBhi[nrow * RS + kw + lr];
                bhf[nt][1] = sBhi[nrow * RS + kw + lr + 4];
                blf[nt][0] = sBlo[nrow * RS + kw + lr];
                blf[nt][1] = sBlo[nrow * RS + kw + lr + 4];
            }
#pragma unroll
            for (int mt = 0; mt < 2; mt++) {
                int r = wr * 32 + mt * 16 + lq;
                uint32_t ah[4], al[4];
                ah[0] = sAhi[r * RS + kw + lr];
                ah[1] = sAhi[(r + 8) * RS + kw + lr];
                ah[2] = sAhi[r * RS + kw + lr + 4];
                ah[3] = sAhi[(r + 8) * RS + kw + lr + 4];
                al[0] = sAlo[r * RS + kw + lr];
                al[1] = sAlo[(r + 8) * RS + kw + lr];
                al[2] = sAlo[r * RS + kw + lr + 4];
                al[3] = sAlo[(r + 8) * RS + kw + lr + 4];
#pragma unroll
                for (int nt = 0; nt < 4; nt++) {
                    mma16816(acc[mt][nt], ah, bhf[nt]);
                    mma16816(acc[mt][nt], ah, blf[nt]);
                    mma16816(acc[mt][nt], al, bhf[nt]);
                }
            }
        }
        __syncthreads();
    }
    float* dst = g_kvpart + (size_t)((kind * 16 + bh) * 16 + slice) * 4096;
#pragma unroll
    for (int mt = 0; mt < 2; mt++) {
        int e = wr * 32 + mt * 16 + lq;
#pragma unroll
        for (int nt = 0; nt < 4; nt++) {
            int p = wc * 32 + nt * 8 + lr * 2;
            *(float2*)&dst[e * 64 + p] = make_float2(acc[mt][nt][0], acc[mt][nt][1]);
            *(float2*)&dst[(e + 8) * 64 + p] = make_float2(acc[mt][nt][2], acc[mt][nt][3]);
        }
    }
}

// reduce + bias + fold norms; emit kpT (scaled, transposed) and vp as bf16 hi/lo
__global__ void k_kvred(const float* __restrict__ bseq) {
    int idx = blockIdx.x * 256 + threadIdx.x;   // 131072 total
    int kb = idx >> 12;                          // kind*16+bh
    int ep = idx & 4095;
    float s = 0.f;
#pragma unroll
    for (int sl = 0; sl < 16; sl++) s += g_kvpart[(size_t)(kb * 16 + sl) * 4096 + ep];
    int kind = kb >> 4, bh = kb & 15;
    int b = bh >> 2, h = bh & 3;
    int e = ep >> 6, p = ep & 63;
    if (kind == 0) {
        float v = s * g_rnorm[b * 512 + 256 + h * 64 + e] + bseq[p];
        v *= g_rnorm[b * 512 + h * 64 + e];
        __nv_bfloat16 hi = __float2bfloat16(v);
        g_kpT_hi[bh * 4096 + p * 64 + e] = hi;
        g_kpT_lo[bh * 4096 + p * 64 + e] = __float2bfloat16(v - __bfloat162float(hi));
    } else {
        float v = s + bseq[p];
        __nv_bfloat16 hi = __float2bfloat16(v);
        g_vp_hi[bh * 4096 + ep] = hi;
        g_vp_lo[bh * 4096 + ep] = __float2bfloat16(v - __bfloat162float(hi));
    }
}

// ---------------- fused attention on HMMA ----------------
#define SMEM_AT ((128 * RS * 2 + 64 * RS * 4) * 4)
__global__ void __launch_bounds__(128) k_attn(const float* __restrict__ qkv,
                                              const float* __restrict__ temp) {
    extern __shared__ __align__(16) uint32_t sm[];
    uint32_t* sQhi = sm;
    uint32_t* sQlo = sm + 128 * RS;
    uint32_t* sKhi = sm + 256 * RS;
    uint32_t* sKlo = sKhi + 64 * RS;
    uint32_t* sVhi = sKlo + 64 * RS;
    uint32_t* sVlo = sVhi + 64 * RS;

    int tid = threadIdx.x;
    int wid = tid >> 5, lane = tid & 31;
    int lq = lane >> 2, lr = lane & 3;
    int h = blockIdx.y, b = blockIdx.z;
    int bh = b * 4 + h;
    int tok0 = blockIdx.x * 128;

    {
        const uint4* skh = (const uint4*)(g_kpT_hi + (size_t)bh * 4096);
        const uint4* skl = (const uint4*)(g_kpT_lo + (size_t)bh * 4096);
        const uint4* svh = (const uint4*)(g_vp_hi + (size_t)bh * 4096);
        const uint4* svl = (const uint4*)(g_vp_lo + (size_t)bh * 4096);
#pragma unroll
        for (int i = 0; i < 4; i++) {
            int idx = tid + i * 128;
            int r = idx >> 3, q = idx & 7;
            *(uint4*)&sKhi[r * RS + q * 4] = skh[idx];
            *(uint4*)&sKlo[r * RS + q * 4] = skl[idx];
            *(uint4*)&sVhi[r * RS + q * 4] = svh[idx];
            *(uint4*)&sVlo[r * RS + q * 4] = svl[idx];
        }
    }
#pragma unroll
    for (int i = 0; i < 16; i++) {
        int idx = tid + i * 128;
        int r = idx >> 4, c4 = idx & 15;
        float4 v = *(const float4*)&qkv[(size_t)(b * 8192 + tok0 + r) * 768 + h * 64 + c4 * 4];
        sQhi[r * RS + c4 * 2]     = pack_bf16_hi(v.x, v.y);
        sQhi[r * RS + c4 * 2 + 1] = pack_bf16_hi(v.z, v.w);
        sQlo[r * RS + c4 * 2]     = pack_bf16_lo(v.x, v.y);
        sQlo[r * RS + c4 * 2 + 1] = pack_bf16_lo(v.z, v.w);
    }
    __syncthreads();
    float tv = temp[h];

    float acc1[2][8][4] = {};
#pragma unroll
    for (int ks = 0; ks < 4; ks++) {
        int kw = ks * 8;
        uint32_t qh[2][4], ql2[2][4];
#pragma unroll
        for (int mt = 0; mt < 2; mt++) {
            int r = wid * 32 + mt * 16 + lq;
            qh[mt][0]  = sQhi[r * RS + kw + lr];
            qh[mt][1]  = sQhi[(r + 8) * RS + kw + lr];
            qh[mt][2]  = sQhi[r * RS + kw + lr + 4];
            qh[mt][3]  = sQhi[(r + 8) * RS + kw + lr + 4];
            ql2[mt][0] = sQlo[r * RS + kw + lr];
            ql2[mt][1] = sQlo[(r + 8) * RS + kw + lr];
            ql2[mt][2] = sQlo[r * RS + kw + lr + 4];
            ql2[mt][3] = sQlo[(r + 8) * RS + kw + lr + 4];
        }
#pragma unroll
        for (int nt = 0; nt < 8; nt++) {
            int n = nt * 8 + lq;
            uint32_t bh2[2], bl2[2];
            bh2[0] = sKhi[n * RS + kw + lr];
            bh2[1] = sKhi[n * RS + kw + lr + 4];
            bl2[0] = sKlo[n * RS + kw + lr];
            bl2[1] = sKlo[n * RS + kw + lr + 4];
#pragma unroll
            for (int mt = 0; mt < 2; mt++) {
                mma16816(acc1[mt][nt], qh[mt], bh2);
                mma16816(acc1[mt][nt], qh[mt], bl2);
                mma16816(acc1[mt][nt], ql2[mt], bh2);
            }
        }
    }

    uint32_t pa_hi[2][4][4], pa_lo[2][4][4];
#pragma unroll
    for (int mt = 0; mt < 2; mt++) {
#pragma unroll
        for (int nt = 0; nt < 8; nt++)
#pragma unroll
            for (int j = 0; j < 4; j++) acc1[mt][nt][j] *= tv;
        float m0 = -1e30f, m1 = -1e30f;
#pragma unroll
        for (int nt = 0; nt < 8; nt++) {
            m0 = fmaxf(m0, fmaxf(acc1[mt][nt][0], acc1[mt][nt][1]));
            m1 = fmaxf(m1, fmaxf(acc1[mt][nt][2], acc1[mt][nt][3]));
        }
        m0 = fmaxf(m0, __shfl_xor_sync(0xffffffffu, m0, 1));
        m0 = fmaxf(m0, __shfl_xor_sync(0xffffffffu, m0, 2));
        m1 = fmaxf(m1, __shfl_xor_sync(0xffffffffu, m1, 1));
        m1 = fmaxf(m1, __shfl_xor_sync(0xffffffffu, m1, 2));
        float s0 = 0.f, s1 = 0.f;
#pragma unroll
        for (int nt = 0; nt < 8; nt++) {
            acc1[mt][nt][0] = __expf(acc1[mt][nt][0] - m0);
            acc1[mt][nt][1] = __expf(acc1[mt][nt][1] - m0);
            acc1[mt][nt][2] = __expf(acc1[mt][nt][2] - m1);
            acc1[mt][nt][3] = __expf(acc1[mt][nt][3] - m1);
            s0 += acc1[mt][nt][0] + acc1[mt][nt][1];
            s1 += acc1[mt][nt][2] + acc1[mt][nt][3];
        }
        s0 += __shfl_xor_sync(0xffffffffu, s0, 1);
        s0 += __shfl_xor_sync(0xffffffffu, s0, 2);
        s1 += __shfl_xor_sync(0xffffffffu, s1, 1);
        s1 += __shfl_xor_sync(0xffffffffu, s1, 2);
        float i0 = 1.0f / s0, i1 = 1.0f / s1;
#pragma unroll
        for (int nt = 0; nt < 8; nt++) {
            acc1[mt][nt][0] *= i0; acc1[mt][nt][1] *= i0;
            acc1[mt][nt][2] *= i1; acc1[mt][nt][3] *= i1;
        }
#pragma unroll
        for (int ks = 0; ks < 4; ks++) {
            pa_hi[mt][ks][0] = pack_bf16_hi(acc1[mt][2*ks][0],   acc1[mt][2*ks][1]);
            pa_hi[mt][ks][1] = pack_bf16_hi(acc1[mt][2*ks][2],   acc1[mt][2*ks][3]);
            pa_hi[mt][ks][2] = pack_bf16_hi(acc1[mt][2*ks+1][0], acc1[mt][2*ks+1][1]);
            pa_hi[mt][ks][3] = pack_bf16_hi(acc1[mt][2*ks+1][2], acc1[mt][2*ks+1][3]);
            pa_lo[mt][ks][0] = pack_bf16_lo(acc1[mt][2*ks][0],   acc1[mt][2*ks][1]);
            pa_lo[mt][ks][1] = pack_bf16_lo(acc1[mt][2*ks][2],   acc1[mt][2*ks][3]);
            pa_lo[mt][ks][2] = pack_bf16_lo(acc1[mt][2*ks+1][0], acc1[mt][2*ks+1][1]);
            pa_lo[mt][ks][3] = pack_bf16_lo(acc1[mt][2*ks+1][2], acc1[mt][2*ks+1][3]);
        }
    }

    float acc2[2][8][4] = {};
#pragma unroll
    for (int ks = 0; ks < 4; ks++) {
        int kw = ks * 8;
#pragma unroll
        for (int nt = 0; nt < 8; nt++) {
            int n = nt * 8 + lq;
            uint32_t bh2[2], bl2[2];
            bh2[0] = sVhi[n * RS + kw + lr];
            bh2[1] = sVhi[n * RS + kw + lr + 4];
            bl2[0] = sVlo[n * RS + kw + lr];
            bl2[1] = sVlo[n * RS + kw + lr + 4];
#pragma unroll
            for (int mt = 0; mt < 2; mt++) {
                mma16816(acc2[mt][nt], pa_hi[mt][ks], bh2);
                mma16816(acc2[mt][nt], pa_hi[mt][ks], bl2);
                mma16816(acc2[mt][nt], pa_lo[mt][ks], bh2);
            }
        }
    }

#pragma unroll
    for (int mt = 0; mt < 2; mt++) {
        int r0 = wid * 32 + mt * 16 + lq;
#pragma unroll
        for (int nt = 0; nt < 8; nt++) {
            int e = nt * 8 + lr * 2;
            size_t off0 = (size_t)(b * 8192 + tok0 + r0) * 256 + h * 64 + e;
            size_t off1 = (size_t)(b * 8192 + tok0 + r0 + 8) * 256 + h * 64 + e;
            *(uint32_t*)(g_o_hi + off0) = pack_bf16_hi(acc2[mt][nt][0], acc2[mt][nt][1]);
            *(uint32_t*)(g_o_lo + off0) = pack_bf16_lo(acc2[mt][nt][0], acc2[mt][nt][1]);
            *(uint32_t*)(g_o_hi + off1) = pack_bf16_hi(acc2[mt][nt][2], acc2[mt][nt][3]);
            *(uint32_t*)(g_o_lo + off1) = pack_bf16_lo(acc2[mt][nt][2], acc2[mt][nt][3]);
        }
    }
}

// ---------------- LayerNorm stats per token ----------------
__global__ void k_lnstat() {
    int tid = threadIdx.x;
    int warp = tid >> 5, lane = tid & 31;
    int t = blockIdx.x * 8 + warp;
    const float4* row = (const float4*)(g_o2 + (size_t)t * 256);
    float s = 0.f, sq = 0.f;
#pragma unroll
    for (int j = 0; j < 2; j++) {
        float4 v = row[j * 32 + lane];
        s  += v.x + v.y + v.z + v.w;
        sq += v.x * v.x + v.y * v.y + v.z * v.z + v.w * v.w;
    }
#pragma unroll
    for (int off = 16; off; off >>= 1) {
        s  += __shfl_xor_sync(0xffffffffu, s, off);
        sq += __shfl_xor_sync(0xffffffffu, sq, off);
    }
    if (lane == 0) {
        float mu = s * (1.0f / 256.0f);
        float var = sq * (1.0f / 256.0f) - mu * mu;
        g_mu[t] = mu;
        g_rs[t] = rsqrtf(var + 1e-5f);
    }
}

// ---------------- LN apply + residual + restore NCDHW ----------------
__global__ void k_lnapply(const float* __restrict__ x, const float* __restrict__ g,
                          const float* __restrict__ be) {
    __shared__ float tl[64 * 65];
    __shared__ float mus[64], rss[64];
    int c0 = blockIdx.x * 64;
    int sp0 = blockIdx.y * 64;
    int b = blockIdx.z;
    int tid = threadIdx.x;
    if (tid < 64) {
        int sp = sp0 + tid;
        int d = sp >> 10, rem = sp & 1023, h = rem >> 5, w = rem & 31;
        int n = h * 256 + w * 8 + d;
        mus[tid] = g_mu[b * 8192 + n];
        rss[tid] = g_rs[b * 8192 + n];
    }
#pragma unroll
    for (int i = 0; i < 16; i++) {
        int idx = i * 256 + tid;
        int s = idx >> 6, c = idx & 63;
        int sp = sp0 + s;
        int d = sp >> 10, rem = sp & 1023, h = rem >> 5, w = rem & 31;
        int n = h * 256 + w * 8 + d;
        tl[s * 65 + c] = g_o2[(size_t)(b * 8192 + n) * 256 + c0 + c];
    }
    __syncthreads();
#pragma unroll
    for (int i = 0; i < 16; i++) {
        int idx = i * 256 + tid;
        int c = idx >> 6, s = idx & 63;
        float gg = g[c0 + c], bb = be[c0 + c];
        float r = (tl[s * 65 + c] - mus[s]) * rss[s] * gg + bb;
        size_t gi = (size_t)(b * 256 + c0 + c) * SPA + sp0 + s;
        g_y[gi] = x[gi] + r;
    }
}

// ---------------- depthwise 3x3x3 SAME conv (register-blocked, bf16 hi/lo out) ----------------
__global__ void k_dwconv(const float* __restrict__ dwk, const float* __restrict__ dwb) {
    __shared__ float tile[10 * 34 * 34];
    __shared__ float wk[27];
    int bc = blockIdx.x;
    int c = bc & 255;
    int tid = threadIdx.x;
    if (tid < 27) wk[tid] = dwk[c * 27 + tid];
    const float* src = g_y + (size_t)bc * SPA;
    for (int i = tid; i < 11560; i += 256) {
        int dz = i / 1156;
        int rem = i - dz * 1156;
        int hy = rem / 34;
        int wx = rem - hy * 34;
        int d = dz - 1, hh = hy - 1, w = wx - 1;
        float val = 0.f;
        if (d >= 0 && d < 8 && hh >= 0 && hh < 32 && w >= 0 && w < 32)
            val = src[d * 1024 + hh * 32 + w];
        tile[i] = val;
    }
    __syncthreads();
    float bias = dwb[c];
    // register blocking: thread handles 4 consecutive w, all 8 d slices
    int r = tid >> 3;           // hh 0..31
    int wg = (tid & 7) * 4;     // w0: 0,4,...,28
#pragma unroll
    for (int d = 0; d < 8; d++) {
        float a0 = 0.f, a1 = 0.f, a2 = 0.f, a3 = 0.f;
#pragma unroll
        for (int kd = 0; kd < 3; kd++) {
#pragma unroll
            for (int kh = 0; kh < 3; kh++) {
                const float* row = &tile[(d + kd) * 1156 + (r + kh) * 34 + wg];
                const float* wrow = &wk[kd * 9 + kh * 3];
                float t0 = row[0], t1 = row[1], t2 = row[2];
                float t3 = row[3], t4 = row[4], t5 = row[5];
                float w0 = wrow[0], w1 = wrow[1], w2 = wrow[2];
                a0 += w0 * t0 + w1 * t1 + w2 * t2;
                a1 += w0 * t1 + w1 * t2 + w2 * t3;
                a2 += w0 * t2 + w1 * t3 + w2 * t4;
                a3 += w0 * t3 + w1 * t4 + w2 * t5;
            }
        }
        size_t o = (size_t)bc * SPA + d * 1024 + r * 32 + wg;
        float v0 = a0 + bias, v1 = a1 + bias, v2 = a2 + bias, v3 = a3 + bias;
        uint2 vh, vl;
        vh.x = pack_bf16_hi(v0, v1); vh.y = pack_bf16_hi(v2, v3);
        vl.x = pack_bf16_lo(v0, v1); vl.y = pack_bf16_lo(v2, v3);
        *(uint2*)(g_dw_hi + o) = vh;
        *(uint2*)(g_dw_lo + o) = vl;
    }
}

// ---------------- pointwise conv on HMMA + bias + final residual ----------------
__global__ void __launch_bounds__(256, 2) k_pwfin(const float* __restrict__ pwb,
                                                  float* __restrict__ out) {
    extern __shared__ __align__(16) uint32_t sm[];
    uint32_t* sAhi = sm;
    uint32_t* sAlo = sAhi + TILE_W;
    uint32_t* sBhi = sAlo + TILE_W;
    uint32_t* sBlo = sBhi + TILE_W;

    int tid = threadIdx.x;
    int wid = tid >> 5, lane = tid & 31;
    int wr = wid >> 2, wc = wid & 3;
    int sp0 = blockIdx.x * 128;
    int co0 = blockIdx.y * 128;
    int b = blockIdx.z;
    int lq = lane >> 2, lr = lane & 3;

    float acc[4][4][4] = {};

    for (int ci0 = 0; ci0 < 256; ci0 += 64) {
#pragma unroll
        for (int i = 0; i < 4; i++) {
            int idx = tid + i * 256;
            int r = idx >> 3, gq = idx & 7;
            *(uint4*)&sAhi[r * RS + gq * 4] =
                *(const uint4*)&g_pwk_hi[(co0 + r) * 256 + ci0 + gq * 8];
            *(uint4*)&sAlo[r * RS + gq * 4] =
                *(const uint4*)&g_pwk_lo[(co0 + r) * 256 + ci0 + gq * 8];
        }
#pragma unroll
        for (int jl = 0; jl < 4; jl++) {
            int j = jl * 8 + wid;
            size_t rbase = (size_t)(b * 256 + ci0 + 2 * j) * SPA + sp0;
#pragma unroll
            for (int sh = 0; sh < 2; sh++) {
                int slp = (sh * 32 + lane) * 2;
                uint32_t u0 = *(const uint32_t*)(g_dw_hi + rbase + slp);
                uint32_t u1 = *(const uint32_t*)(g_dw_hi + rbase + SPA + slp);
                sBhi[slp * RS + j]       = __byte_perm(u0, u1, 0x5410);
                sBhi[(slp + 1) * RS + j] = __byte_perm(u0, u1, 0x7632);
                u0 = *(const uint32_t*)(g_dw_lo + rbase + slp);
                u1 = *(const uint32_t*)(g_dw_lo + rbase + SPA + slp);
                sBlo[slp * RS + j]       = __byte_perm(u0, u1, 0x5410);
                sBlo[(slp + 1) * RS + j] = __byte_perm(u0, u1, 0x7632);
            }
        }
        __syncthreads();
#pragma unroll
        for (int ks = 0; ks < 4; ks++) {
            int kw = ks * 8;
            uint32_t bh[4][2], bl[4][2];
#pragma unroll
            for (int nt = 0; nt < 4; nt++) {
                int n = wc * 32 + nt * 8 + lq;
                bh[nt][0] = sBhi[n * RS + kw + lr];
                bh[nt][1] = sBhi[n * RS + kw + lr + 4];
                bl[nt][0] = sBlo[n * RS + kw + lr];
                bl[nt][1] = sBlo[n * RS + kw + lr + 4];
            }
#pragma unroll
            for (int mt = 0; mt < 4; mt++) {
                int r = wr * 64 + mt * 16 + lq;
                uint32_t ah[4], al[4];
                ah[0] = sAhi[r * RS + kw + lr];
                ah[1] = sAhi[(r + 8) * RS + kw + lr];
                ah[2] = sAhi[r * RS + kw + lr + 4];
                ah[3] = sAhi[(r + 8) * RS + kw + lr + 4];
                al[0] = sAlo[r * RS + kw + lr];
                al[1] = sAlo[(r + 8) * RS + kw + lr];
                al[2] = sAlo[r * RS + kw + lr + 4];
                al[3] = sAlo[(r + 8) * RS + kw + lr + 4];
#pragma unroll
                for (int nt = 0; nt < 4; nt++) {
                    mma16816(acc[mt][nt], ah, bh[nt]);
                    mma16816(acc[mt][nt], ah, bl[nt]);
                    mma16816(acc[mt][nt], al, bh[nt]);
                }
            }
        }
        __syncthreads();
    }
#pragma unroll
    for (int mt = 0; mt < 4; mt++) {
        int r = co0 + wr * 64 + mt * 16 + lq;
        float bb0 = pwb[r], bb1 = pwb[r + 8];
#pragma unroll
        for (int nt = 0; nt < 4; nt++) {
            int c = sp0 + wc * 32 + nt * 8 + lr * 2;
            size_t i0 = (size_t)(b * 256 + r) * SPA + c;
            size_t i1 = (size_t)(b * 256 + r + 8) * SPA + c;
            float2 y0 = *(const float2*)&g_y[i0];
            float2 y1 = *(const float2*)&g_y[i1];
            float2 v0, v1;
            v0.x = acc[mt][nt][0] + bb0 + y0.x;
            v0.y = acc[mt][nt][1] + bb0 + y0.y;
            v1.x = acc[mt][nt][2] + bb1 + y1.x;
            v1.y = acc[mt][nt][3] + bb1 + y1.y;
            *(float2*)&out[i0] = v0;
            *(float2*)&out[i1] = v1;
        }
    }
}
#define SMEM_PW (4 * TILE_W * 4)

// ---------------- launch ----------------
extern "C" void kernel_launch(void* const* d_in, const int* in_sizes, int n_in,
                              void* d_out, int out_size) {
    (void)in_sizes; (void)n_in; (void)out_size;
    const float* x    = (const float*)d_in[0];
    const float* wqkv = (const float*)d_in[1];
    const float* wseq = (const float*)d_in[2];
    const float* bseq = (const float*)d_in[3];
    const float* temp = (const float*)d_in[4];
    const float* wout = (const float*)d_in[5];
    const float* bout = (const float*)d_in[6];
    const float* lng  = (const float*)d_in[7];
    const float* lnb  = (const float*)d_in[8];
    const float* dwk  = (const float*)d_in[9];
    const float* dwb  = (const float*)d_in[10];
    const float* pwk  = (const float*)d_in[11];
    const float* pwb  = (const float*)d_in[12];
    float* out = (float*)d_out;

    float *qkv, *o2;
    __nv_bfloat16 *t_hi, *t_lo, *o_hi, *o_lo;
    __nv_bfloat16 *wqkvT_hi, *wqkvT_lo, *woutT_hi, *woutT_lo, *pwk_hi, *pwk_lo;
    __nv_bfloat16 *wsT_hi, *wsT_lo;
    cudaGetSymbolAddress((void**)&qkv, g_qkv);
    cudaGetSymbolAddress((void**)&o2,  g_o2);
    cudaGetSymbolAddress((void**)&t_hi, g_t_hi);
    cudaGetSymbolAddress((void**)&t_lo, g_t_lo);
    cudaGetSymbolAddress((void**)&o_hi, g_o_hi);
    cudaGetSymbolAddress((void**)&o_lo, g_o_lo);
    cudaGetSymbolAddress((void**)&wqkvT_hi, g_wqkvT_hi);
    cudaGetSymbolAddress((void**)&wqkvT_lo, g_wqkvT_lo);
    cudaGetSymbolAddress((void**)&woutT_hi, g_woutT_hi);
    cudaGetSymbolAddress((void**)&woutT_lo, g_woutT_lo);
    cudaGetSymbolAddress((void**)&pwk_hi, g_pwk_hi);
    cudaGetSymbolAddress((void**)&pwk_lo, g_pwk_lo);
    cudaGetSymbolAddress((void**)&wsT_hi, g_wsT_hi);
    cudaGetSymbolAddress((void**)&wsT_lo, g_wsT_lo);

    cudaFuncSetAttribute(k_mma, cudaFuncAttributeMaxDynamicSharedMemorySize, SMEM_MMA);
    cudaFuncSetAttribute(k_pwfin, cudaFuncAttributeMaxDynamicSharedMemorySize, SMEM_PW);
    cudaFuncSetAttribute(k_kvproj, cudaFuncAttributeMaxDynamicSharedMemorySize, SMEM_KV);
    cudaFuncSetAttribute(k_attn, cudaFuncAttributeMaxDynamicSharedMemorySize, SMEM_AT);

    // 1. transpose to token-major bf16 hi/lo (packed stores)
    k_transpose<<<dim3(4, 128, 4), 256>>>(x);
    // 2. weight prep (merged transposes + direct split)
    k_wtprep_all<<<192, 256>>>(wqkv, wout, wseq);
    k_wprep_nt<<<256, 256>>>(pwk, pwk_hi, pwk_lo, 256 * 256);
    // 3. QKV GEMM (HMMA, cp.async pipelined, 2 CTA/SM)
    k_mma<<<dim3(6, 256), 256, SMEM_MMA>>>(t_hi, t_lo, wqkvT_hi, wqkvT_lo, nullptr, qkv, 256, 768);
    // 4. column L2 norms
    k_cnpart<<<dim3(64, 4), 256>>>(qkv);
    k_cnfin<<<8, 256>>>();
    // 5. kp/vp projections (HMMA) + reduce w/ norms+bias -> bf16 attn operands
    k_kvproj<<<dim3(16, 16, 2), 128, SMEM_KV>>>(qkv, wsT_hi, wsT_lo);
    k_kvred<<<512, 256>>>(bseq);
    // 6. fused attention (HMMA, in-register softmax)
    k_attn<<<dim3(64, 4, 4), 128, SMEM_AT>>>(qkv, temp);
    // 7. output projection (HMMA)
    k_mma<<<dim3(2, 256), 256, SMEM_MMA>>>(o_hi, o_lo, woutT_hi, woutT_lo, bout, o2, 256, 256);
    // 8. LayerNorm stats + apply/residual/transpose
    k_lnstat<<<4096, 256>>>();
    k_lnapply<<<dim3(4, 128, 4), 256>>>(x, lng, lnb);
    // 9. depthwise conv (register-blocked, bf16 hi/lo out)
    k_dwconv<<<1024, 256>>>(dwk, dwb);
    // 10. pointwise conv (HMMA) + bias + final residual
    k_pwfin<<<dim3(64, 2, 4), 256, SMEM_PW>>>(pwb, out);
}

// round 14
// speedup vs baseline: 2.2622x; 1.0086x over previous
#include <cuda_runtime.h>
#include <cuda_bf16.h>
#include <math.h>
#include <stdint.h>

// Problem constants
#define BQ   4
#define CC   256
#define NHEAD 4
#define PP   64
#define NN   8192
#define SPA  8192

// ---------------- scratch (device globals) ----------------
__device__ __align__(128) __nv_bfloat16 g_t_hi[(size_t)BQ * NN * CC];
__device__ __align__(128) __nv_bfloat16 g_t_lo[(size_t)BQ * NN * CC];
__device__ float g_qkv [(size_t)BQ * NN * 3 * CC];
__device__ float g_cnpart[256 * 512];
__device__ float g_rnorm [BQ * 512];
__device__ float g_kvpart[2 * 16 * 16 * 4096];
__device__ __align__(128) __nv_bfloat16 g_kpT_hi[16 * 4096];
__device__ __align__(128) __nv_bfloat16 g_kpT_lo[16 * 4096];
__device__ __align__(128) __nv_bfloat16 g_vp_hi [16 * 4096];
__device__ __align__(128) __nv_bfloat16 g_vp_lo [16 * 4096];
__device__ __align__(128) __nv_bfloat16 g_o_hi[(size_t)BQ * NN * CC];
__device__ __align__(128) __nv_bfloat16 g_o_lo[(size_t)BQ * NN * CC];
__device__ float g_o2  [(size_t)BQ * NN * CC];
__device__ float g_mu  [BQ * NN];
__device__ float g_rs  [BQ * NN];
__device__ float g_y   [(size_t)BQ * CC * SPA];
__device__ __align__(128) __nv_bfloat16 g_dw_hi[(size_t)BQ * CC * SPA];
__device__ __align__(128) __nv_bfloat16 g_dw_lo[(size_t)BQ * CC * SPA];
__device__ __align__(128) __nv_bfloat16 g_wqkvT_hi[768 * 256];
__device__ __align__(128) __nv_bfloat16 g_wqkvT_lo[768 * 256];
__device__ __align__(128) __nv_bfloat16 g_woutT_hi[256 * 256];
__device__ __align__(128) __nv_bfloat16 g_woutT_lo[256 * 256];
__device__ __align__(128) __nv_bfloat16 g_pwk_hi[256 * 256];
__device__ __align__(128) __nv_bfloat16 g_pwk_lo[256 * 256];
__device__ __align__(128) __nv_bfloat16 g_wsT_hi[64 * 8192];
__device__ __align__(128) __nv_bfloat16 g_wsT_lo[64 * 8192];

// ---------------- helpers ----------------
__device__ __forceinline__ uint32_t pack_bf16_hi(float a, float b) {
    __nv_bfloat16 ha = __float2bfloat16(a);
    __nv_bfloat16 hb = __float2bfloat16(b);
    return ((uint32_t)__bfloat16_as_ushort(hb) << 16) | __bfloat16_as_ushort(ha);
}
__device__ __forceinline__ uint32_t pack_bf16_lo(float a, float b) {
    __nv_bfloat16 ha = __float2bfloat16(a);
    __nv_bfloat16 hb = __float2bfloat16(b);
    __nv_bfloat16 la = __float2bfloat16(a - __bfloat162float(ha));
    __nv_bfloat16 lb = __float2bfloat16(b - __bfloat162float(hb));
    return ((uint32_t)__bfloat16_as_ushort(lb) << 16) | __bfloat16_as_ushort(la);
}

__device__ __forceinline__ void mma16816(float* d, const uint32_t* a, const uint32_t* b) {
    asm volatile(
        "mma.sync.aligned.m16n8k16.row.col.f32.bf16.bf16.f32 "
        "{%0,%1,%2,%3}, {%4,%5,%6,%7}, {%8,%9}, {%0,%1,%2,%3};"
        : "+f"(d[0]), "+f"(d[1]), "+f"(d[2]), "+f"(d[3])
        : "r"(a[0]), "r"(a[1]), "r"(a[2]), "r"(a[3]), "r"(b[0]), "r"(b[1]));
}

__device__ __forceinline__ uint32_t smem_u32(const void* p) {
    uint32_t a;
    asm("{ .reg .u64 t; cvta.to.shared.u64 t, %1; cvt.u32.u64 %0, t; }" : "=r"(a) : "l"(p));
    return a;
}
#define CP_ASYNC16(dst, src) \
    asm volatile("cp.async.cg.shared.global [%0], [%1], 16;" :: "r"(dst), "l"(src) : "memory")
#define CP_COMMIT() asm volatile("cp.async.commit_group;" ::: "memory")
#define CP_WAIT1()  asm volatile("cp.async.wait_group 1;" ::: "memory")
#define CP_WAIT0()  asm volatile("cp.async.wait_group 0;" ::: "memory")

#define RS 36
#define TILE_W (128 * RS)
#define RS2 20
#define TW2 (128 * RS2)

// ---------------- K0: transpose x (NCDHW) -> t_hi/lo [B,N,C] bf16 ----------------
__global__ void k_transpose(const float* __restrict__ x) {
    __shared__ float tile[64 * 65];
    int c0 = blockIdx.x * 64;
    int sp0 = blockIdx.y * 64;
    int b = blockIdx.z;
    int tid = threadIdx.x;
#pragma unroll
    for (int i = 0; i < 16; i++) {
        int idx = i * 256 + tid;
        int c = idx >> 6, s = idx & 63;
        tile[c * 65 + s] = x[(size_t)(b * 256 + c0 + c) * SPA + sp0 + s];
    }
    __syncthreads();
#pragma unroll
    for (int i = 0; i < 8; i++) {
        int idx = i * 256 + tid;
        int s = idx >> 5, c2 = idx & 31;
        int c = c2 * 2;
        int sp = sp0 + s;
        int d = sp >> 10, rem = sp & 1023, h = rem >> 5, w = rem & 31;
        int n = h * 256 + w * 8 + d;
        float v0 = tile[c * 65 + s];
        float v1 = tile[(c + 1) * 65 + s];
        size_t gi = (size_t)(b * 8192 + n) * 256 + c0 + c;
        *(uint32_t*)(g_t_hi + gi) = pack_bf16_hi(v0, v1);
        *(uint32_t*)(g_t_lo + gi) = pack_bf16_lo(v0, v1);
    }
}

// ---------------- merged weight prep ----------------
__global__ void k_wtprep_all(const float* __restrict__ wqkv,
                             const float* __restrict__ wout,
                             const float* __restrict__ wseq) {
    __shared__ float sm[64 * 65];
    int bid = blockIdx.x;
    const float* w;
    __nv_bfloat16 *thi, *tlo;
    int K, Nn, gx, gy;
    if (bid < 48) {
        w = wqkv; thi = g_wqkvT_hi; tlo = g_wqkvT_lo;
        K = 256; Nn = 768; gx = bid % 12; gy = bid / 12;
    } else if (bid < 64) {
        int b2 = bid - 48;
        w = wout; thi = g_woutT_hi; tlo = g_woutT_lo;
        K = 256; Nn = 256; gx = b2 & 3; gy = b2 >> 2;
    } else {
        int b3 = bid - 64;
        w = wseq; thi = g_wsT_hi; tlo = g_wsT_lo;
        K = 8192; Nn = 64; gx = 0; gy = b3;
    }
    int n0 = gx * 64;
    int k0 = gy * 64;
    int tid = threadIdx.x;
#pragma unroll
    for (int i = 0; i < 16; i++) {
        int idx = i * 256 + tid;
        int r = idx >> 6, c = idx & 63;
        sm[r * 65 + c] = w[(size_t)(k0 + r) * Nn + n0 + c];
    }
    __syncthreads();
#pragma unroll
    for (int i = 0; i < 16; i++) {
        int idx = i * 256 + tid;
        int r = idx >> 6, c = idx & 63;
        float a = sm[c * 65 + r];
        __nv_bfloat16 h = __float2bfloat16(a);
        size_t gi = (size_t)(n0 + r) * K + k0 + c;
        thi[gi] = h;
        tlo[gi] = __float2bfloat16(a - __bfloat162float(h));
    }
}
__global__ void k_wprep_nt(const float* __restrict__ w, __nv_bfloat16* __restrict__ thi,
                           __nv_bfloat16* __restrict__ tlo, int total) {
    int idx = blockIdx.x * 256 + threadIdx.x;
    if (idx >= total) return;
    float a = w[idx];
    __nv_bfloat16 h = __float2bfloat16(a);
    thi[idx] = h;
    tlo[idx] = __float2bfloat16(a - __bfloat162float(h));
}

// ---------------- HMMA bf16-split GEMM (term-outer MMA ordering) ----------------
__global__ void __launch_bounds__(256, 2) k_mma(const __nv_bfloat16* __restrict__ Ahi,
                                                const __nv_bfloat16* __restrict__ Alo,
                                                const __nv_bfloat16* __restrict__ Bhi,
                                                const __nv_bfloat16* __restrict__ Blo,
                                                const float* __restrict__ bias,
                                                float* __restrict__ C, int K, int Ntot) {
    extern __shared__ __align__(16) uint32_t sm[];
    uint32_t sbase = smem_u32(sm);

    int tid = threadIdx.x;
    int wid = tid >> 5, lane = tid & 31;
    int wr = wid >> 2, wc = wid & 3;
    int row0 = blockIdx.y * 128;
    int col0 = blockIdx.x * 128;
    int lq = lane >> 2, lr = lane & 3;

    float acc[4][4][4] = {};
    int nch = K >> 5;

#define PREFETCH(CH, STG) do {                                                     \
        int _k0 = (CH) << 5;                                                       \
        uint32_t _so = sbase + (STG) * 4 * TW2 * 4;                                \
        _Pragma("unroll")                                                          \
        for (int _i = 0; _i < 2; _i++) {                                           \
            int _idx = tid + _i * 256;                                             \
            int _r = _idx >> 2, _g = _idx & 3;                                     \
            uint32_t _d = _so + (_r * RS2 + _g * 4) * 4;                           \
            const __nv_bfloat16* _s = Ahi + (size_t)(row0 + _r) * K + _k0 + _g * 8;\
            CP_ASYNC16(_d, _s);                                                    \
            _d += TW2 * 4;                                                         \
            _s = Alo + (size_t)(row0 + _r) * K + _k0 + _g * 8;                     \
            CP_ASYNC16(_d, _s);                                                    \
            _d += TW2 * 4;                                                         \
            _s = Bhi + (size_t)(col0 + _r) * K + _k0 + _g * 8;                     \
            CP_ASYNC16(_d, _s);                                                    \
            _d += TW2 * 4;                                                         \
            _s = Blo + (size_t)(col0 + _r) * K + _k0 + _g * 8;                     \
            CP_ASYNC16(_d, _s);                                                    \
        }                                                                          \
    } while (0)

    PREFETCH(0, 0);
    CP_COMMIT();

    for (int ch = 0; ch < nch; ch++) {
        if (ch + 1 < nch) {
            PREFETCH(ch + 1, (ch + 1) & 1);
            CP_COMMIT();
            CP_WAIT1();
        } else {
            CP_WAIT0();
        }
        __syncthreads();
        uint32_t* base = sm + (ch & 1) * 4 * TW2;
        uint32_t* sAhi = base;
        uint32_t* sAlo = base + TW2;
        uint32_t* sBhi = base + 2 * TW2;
        uint32_t* sBlo = base + 3 * TW2;
#pragma unroll
        for (int ks = 0; ks < 2; ks++) {
            int kw = ks * 8;
            uint32_t bh[4][2], bl[4][2];
#pragma unroll
            for (int nt = 0; nt < 4; nt++) {
                int n = wc * 32 + nt * 8 + lq;
                bh[nt][0] = sBhi[n * RS2 + kw + lr];
                bh[nt][1] = sBhi[n * RS2 + kw + lr + 4];
                bl[nt][0] = sBlo[n * RS2 + kw + lr];
                bl[nt][1] = sBlo[n * RS2 + kw + lr + 4];
            }
#pragma unroll
            for (int mt = 0; mt < 4; mt++) {
                int r = wr * 64 + mt * 16 + lq;
                uint32_t ah[4], al[4];
                ah[0] = sAhi[r * RS2 + kw + lr];
                ah[1] = sAhi[(r + 8) * RS2 + kw + lr];
                ah[2] = sAhi[r * RS2 + kw + lr + 4];
                ah[3] = sAhi[(r + 8) * RS2 + kw + lr + 4];
                al[0] = sAlo[r * RS2 + kw + lr];
                al[1] = sAlo[(r + 8) * RS2 + kw + lr];
                al[2] = sAlo[r * RS2 + kw + lr + 4];
                al[3] = sAlo[(r + 8) * RS2 + kw + lr + 4];
                // term-outer: dependent revisit distance = 4 independent MMAs
#pragma unroll
                for (int nt = 0; nt < 4; nt++) mma16816(acc[mt][nt], ah, bh[nt]);
#pragma unroll
                for (int nt = 0; nt < 4; nt++) mma16816(acc[mt][nt], ah, bl[nt]);
#pragma unroll
                for (int nt = 0; nt < 4; nt++) mma16816(acc[mt][nt], al, bh[nt]);
            }
        }
        __syncthreads();
    }
#undef PREFETCH
#pragma unroll
    for (int mt = 0; mt < 4; mt++) {
        int r = row0 + wr * 64 + mt * 16 + lq;
#pragma unroll
        for (int nt = 0; nt < 4; nt++) {
            int c = col0 + wc * 32 + nt * 8 + lr * 2;
            float b0 = bias ? bias[c] : 0.0f;
            float b1 = bias ? bias[c + 1] : 0.0f;
            float2 v0, v1;
            v0.x = acc[mt][nt][0] + b0;
            v0.y = acc[mt][nt][1] + b1;
            v1.x = acc[mt][nt][2] + b0;
            v1.y = acc[mt][nt][3] + b1;
            *(float2*)&C[(size_t)r * Ntot + c] = v0;
            *(float2*)&C[(size_t)(r + 8) * Ntot + c] = v1;
        }
    }
}
#define SMEM_MMA (8 * TW2 * 4)

// ---------------- column L2 norms for q,k ----------------
__global__ void k_cnpart(const float* __restrict__ qkv) {
    int chunk = blockIdx.x;
    int b = blockIdx.y;
    int tid = threadIdx.x;
    float s0 = 0.f, s1 = 0.f;
    int n0 = chunk * 128;
    const float* base = qkv + (size_t)(b * 8192 + n0) * 768;
#pragma unroll 4
    for (int j = 0; j < 128; j++) {
        const float* row = base + (size_t)j * 768;
        float v0 = row[tid];
        float v1 = row[256 + tid];
        s0 += v0 * v0;
        s1 += v1 * v1;
    }
    g_cnpart[(b * 64 + chunk) * 512 + tid] = s0;
    g_cnpart[(b * 64 + chunk) * 512 + 256 + tid] = s1;
}

__global__ void k_cnfin() {
    int idx = blockIdx.x * 256 + threadIdx.x;
    int b = idx >> 9, col = idx & 511;
    float s = 0.f;
#pragma unroll
    for (int ch = 0; ch < 64; ch++) s += g_cnpart[(b * 64 + ch) * 512 + col];
    g_rnorm[idx] = 1.0f / fmaxf(sqrtf(s), 1e-12f);
}

// ---------------- kp/vp projections on HMMA ----------------
#define SMEM_KV (64 * 65 * 4 + 4 * 64 * RS * 4)
__global__ void __launch_bounds__(128) k_kvproj(const float* __restrict__ qkv,
                                                const __nv_bfloat16* __restrict__ wsThi,
                                                const __nv_bfloat16* __restrict__ wsTlo) {
    extern __shared__ __align__(16) char smraw[];
    float* sF = (float*)smraw;
    uint32_t* sAhi = (uint32_t*)(smraw + 64 * 65 * 4);
    uint32_t* sAlo = sAhi + 64 * RS;
    uint32_t* sBhi = sAlo + 64 * RS;
    uint32_t* sBlo = sBhi + 64 * RS;

    int slice = blockIdx.x;
    int bh = blockIdx.y;
    int kind = blockIdx.z;
    int b = bh >> 2, h = bh & 3;
    int colbase = (kind == 0 ? 256 : 512) + h * 64;
    int tid = threadIdx.x;
    int wid = tid >> 5, lane = tid & 31;
    int wr = wid >> 1, wc = wid & 1;
    int lq = lane >> 2, lr = lane & 3;
    int wa = lane & 7, wb = lane >> 3;

    float acc[2][4][4] = {};

    int nbeg = slice * 512;
    for (int ch = 0; ch < 8; ch++) {
        int n0 = nbeg + ch * 64;
#pragma unroll
        for (int i = 0; i < 8; i++) {
            int idx = tid + i * 128;
            int r = idx >> 4, c4 = idx & 15;
            float4 v = *(const float4*)&qkv[(size_t)(b * 8192 + n0 + r) * 768 + colbase + c4 * 4];
            float* dst = &sF[r * 65 + c4 * 4];
            dst[0] = v.x; dst[1] = v.y; dst[2] = v.z; dst[3] = v.w;
        }
#pragma unroll
        for (int i = 0; i < 4; i++) {
            int idx = tid + i * 128;
            int r = idx >> 3, q = idx & 7;
            *(uint4*)&sBhi[r * RS + q * 4] = *(const uint4*)&wsThi[(size_t)r * 8192 + n0 + q * 8];
            *(uint4*)&sBlo[r * RS + q * 4] = *(const uint4*)&wsTlo[(size_t)r * 8192 + n0 + q * 8];
        }
        __syncthreads();
#pragma unroll
        for (int ia = 0; ia < 2; ia++) {
            int e = wid * 16 + 8 * ia + wa;
#pragma unroll
            for (int inp = 0; inp < 8; inp++) {
                int np = 4 * inp + wb;
                float v0 = sF[(2 * np) * 65 + e];
                float v1 = sF[(2 * np + 1) * 65 + e];
                sAhi[e * RS + np] = pack_bf16_hi(v0, v1);
                sAlo[e * RS + np] = pack_bf16_lo(v0, v1);
            }
        }
        __syncthreads();
#pragma unroll
        for (int ks = 0; ks < 4; ks++) {
            int kw = ks * 8;
            uint32_t bhf[4][2], blf[4][2];
#pragma unroll
            for (int nt = 0; nt < 4; nt++) {
                int nrow = wc * 32 + nt * 8 + lq;
                bhf[nt][0] = sBhi[nrow * RS + kw + lr];
                bhf[nt][1] = sBhi[nrow * RS + kw + lr + 4];
                blf[nt][0] = sBlo[nrow * RS + kw + lr];
                blf[nt][1] = sBlo[nrow * RS + kw + lr + 4];
            }
#pragma unroll
            for (int mt = 0; mt < 2; mt++) {
                int r = wr * 32 + mt * 16 + lq;
                uint32_t ah[4], al[4];
                ah[0] = sAhi[r * RS + kw + lr];
                ah[1] = sAhi[(r + 8) * RS + kw + lr];
                ah[2] = sAhi[r * RS + kw + lr + 4];
                ah[3] = sAhi[(r + 8) * RS + kw + lr + 4];
                al[0] = sAlo[r * RS + kw + lr];
                al[1] = sAlo[(r + 8) * RS + kw + lr];
                al[2] = sAlo[r * RS + kw + lr + 4];
                al[3] = sAlo[(r + 8) * RS + kw + lr + 4];
#pragma unroll
                for (int nt = 0; nt < 4; nt++) mma16816(acc[mt][nt], ah, bhf[nt]);
#pragma unroll
                for (int nt = 0; nt < 4; nt++) mma16816(acc[mt][nt], ah, blf[nt]);
#pragma unroll
                for (int nt = 0; nt < 4; nt++) mma16816(acc[mt][nt], al, bhf[nt]);
            }
        }
        __syncthreads();
    }
    float* dst = g_kvpart + (size_t)((kind * 16 + bh) * 16 + slice) * 4096;
#pragma unroll
    for (int mt = 0; mt < 2; mt++) {
        int e = wr * 32 + mt * 16 + lq;
#pragma unroll
        for (int nt = 0; nt < 4; nt++) {
            int p = wc * 32 + nt * 8 + lr * 2;
            *(float2*)&dst[e * 64 + p] = make_float2(acc[mt][nt][0], acc[mt][nt][1]);
            *(float2*)&dst[(e + 8) * 64 + p] = make_float2(acc[mt][nt][2], acc[mt][nt][3]);
        }
    }
}

// reduce + bias + fold norms
__global__ void k_kvred(const float* __restrict__ bseq) {
    int idx = blockIdx.x * 256 + threadIdx.x;
    int kb = idx >> 12;
    int ep = idx & 4095;
    float s = 0.f;
#pragma unroll
    for (int sl = 0; sl < 16; sl++) s += g_kvpart[(size_t)(kb * 16 + sl) * 4096 + ep];
    int kind = kb >> 4, bh = kb & 15;
    int b = bh >> 2, h = bh & 3;
    int e = ep >> 6, p = ep & 63;
    if (kind == 0) {
        float v = s * g_rnorm[b * 512 + 256 + h * 64 + e] + bseq[p];
        v *= g_rnorm[b * 512 + h * 64 + e];
        __nv_bfloat16 hi = __float2bfloat16(v);
        g_kpT_hi[bh * 4096 + p * 64 + e] = hi;
        g_kpT_lo[bh * 4096 + p * 64 + e] = __float2bfloat16(v - __bfloat162float(hi));
    } else {
        float v = s + bseq[p];
        __nv_bfloat16 hi = __float2bfloat16(v);
        g_vp_hi[bh * 4096 + ep] = hi;
        g_vp_lo[bh * 4096 + ep] = __float2bfloat16(v - __bfloat162float(hi));
    }
}

// ---------------- fused attention on HMMA (term-outer passes) ----------------
#define SMEM_AT ((128 * RS * 2 + 64 * RS * 4) * 4)
__global__ void __launch_bounds__(128) k_attn(const float* __restrict__ qkv,
                                              const float* __restrict__ temp) {
    extern __shared__ __align__(16) uint32_t sm[];
    uint32_t* sQhi = sm;
    uint32_t* sQlo = sm + 128 * RS;
    uint32_t* sKhi = sm + 256 * RS;
    uint32_t* sKlo = sKhi + 64 * RS;
    uint32_t* sVhi = sKlo + 64 * RS;
    uint32_t* sVlo = sVhi + 64 * RS;

    int tid = threadIdx.x;
    int wid = tid >> 5, lane = tid & 31;
    int lq = lane >> 2, lr = lane & 3;
    int h = blockIdx.y, b = blockIdx.z;
    int bh = b * 4 + h;
    int tok0 = blockIdx.x * 128;

    {
        const uint4* skh = (const uint4*)(g_kpT_hi + (size_t)bh * 4096);
        const uint4* skl = (const uint4*)(g_kpT_lo + (size_t)bh * 4096);
        const uint4* svh = (const uint4*)(g_vp_hi + (size_t)bh * 4096);
        const uint4* svl = (const uint4*)(g_vp_lo + (size_t)bh * 4096);
#pragma unroll
        for (int i = 0; i < 4; i++) {
            int idx = tid + i * 128;
            int r = idx >> 3, q = idx & 7;
            *(uint4*)&sKhi[r * RS + q * 4] = skh[idx];
            *(uint4*)&sKlo[r * RS + q * 4] = skl[idx];
            *(uint4*)&sVhi[r * RS + q * 4] = svh[idx];
            *(uint4*)&sVlo[r * RS + q * 4] = svl[idx];
        }
    }
#pragma unroll
    for (int i = 0; i < 16; i++) {
        int idx = tid + i * 128;
        int r = idx >> 4, c4 = idx & 15;
        float4 v = *(const float4*)&qkv[(size_t)(b * 8192 + tok0 + r) * 768 + h * 64 + c4 * 4];
        sQhi[r * RS + c4 * 2]     = pack_bf16_hi(v.x, v.y);
        sQhi[r * RS + c4 * 2 + 1] = pack_bf16_hi(v.z, v.w);
        sQlo[r * RS + c4 * 2]     = pack_bf16_lo(v.x, v.y);
        sQlo[r * RS + c4 * 2 + 1] = pack_bf16_lo(v.z, v.w);
    }
    __syncthreads();
    float tv = temp[h];

    // --- MMA1: preload all B frags; 3 term passes (revisit distance 16) ---
    float acc1[2][8][4] = {};
#pragma unroll
    for (int ks = 0; ks < 4; ks++) {
        int kw = ks * 8;
        uint32_t qh[2][4], ql2[2][4];
#pragma unroll
        for (int mt = 0; mt < 2; mt++) {
            int r = wid * 32 + mt * 16 + lq;
            qh[mt][0]  = sQhi[r * RS + kw + lr];
            qh[mt][1]  = sQhi[(r + 8) * RS + kw + lr];
            qh[mt][2]  = sQhi[r * RS + kw + lr + 4];
            qh[mt][3]  = sQhi[(r + 8) * RS + kw + lr + 4];
            ql2[mt][0] = sQlo[r * RS + kw + lr];
            ql2[mt][1] = sQlo[(r + 8) * RS + kw + lr];
            ql2[mt][2] = sQlo[r * RS + kw + lr + 4];
            ql2[mt][3] = sQlo[(r + 8) * RS + kw + lr + 4];
        }
        uint32_t kb[8][2], kl[8][2];
#pragma unroll
        for (int nt = 0; nt < 8; nt++) {
            int n = nt * 8 + lq;
            kb[nt][0] = sKhi[n * RS + kw + lr];
            kb[nt][1] = sKhi[n * RS + kw + lr + 4];
            kl[nt][0] = sKlo[n * RS + kw + lr];
            kl[nt][1] = sKlo[n * RS + kw + lr + 4];
        }
#pragma unroll
        for (int nt = 0; nt < 8; nt++)
#pragma unroll
            for (int mt = 0; mt < 2; mt++) mma16816(acc1[mt][nt], qh[mt], kb[nt]);
#pragma unroll
        for (int nt = 0; nt < 8; nt++)
#pragma unroll
            for (int mt = 0; mt < 2; mt++) mma16816(acc1[mt][nt], qh[mt], kl[nt]);
#pragma unroll
        for (int nt = 0; nt < 8; nt++)
#pragma unroll
            for (int mt = 0; mt < 2; mt++) mma16816(acc1[mt][nt], ql2[mt], kb[nt]);
    }

    uint32_t pa_hi[2][4][4], pa_lo[2][4][4];
#pragma unroll
    for (int mt = 0; mt < 2; mt++) {
#pragma unroll
        for (int nt = 0; nt < 8; nt++)
#pragma unroll
            for (int j = 0; j < 4; j++) acc1[mt][nt][j] *= tv;
        float m0 = -1e30f, m1 = -1e30f;
#pragma unroll
        for (int nt = 0; nt < 8; nt++) {
            m0 = fmaxf(m0, fmaxf(acc1[mt][nt][0], acc1[mt][nt][1]));
            m1 = fmaxf(m1, fmaxf(acc1[mt][nt][2], acc1[mt][nt][3]));
        }
        m0 = fmaxf(m0, __shfl_xor_sync(0xffffffffu, m0, 1));
        m0 = fmaxf(m0, __shfl_xor_sync(0xffffffffu, m0, 2));
        m1 = fmaxf(m1, __shfl_xor_sync(0xffffffffu, m1, 1));
        m1 = fmaxf(m1, __shfl_xor_sync(0xffffffffu, m1, 2));
        float s0 = 0.f, s1 = 0.f;
#pragma unroll
        for (int nt = 0; nt < 8; nt++) {
            acc1[mt][nt][0] = __expf(acc1[mt][nt][0] - m0);
            acc1[mt][nt][1] = __expf(acc1[mt][nt][1] - m0);
            acc1[mt][nt][2] = __expf(acc1[mt][nt][2] - m1);
            acc1[mt][nt][3] = __expf(acc1[mt][nt][3] - m1);
            s0 += acc1[mt][nt][0] + acc1[mt][nt][1];
            s1 += acc1[mt][nt][2] + acc1[mt][nt][3];
        }
        s0 += __shfl_xor_sync(0xffffffffu, s0, 1);
        s0 += __shfl_xor_sync(0xffffffffu, s0, 2);
        s1 += __shfl_xor_sync(0xffffffffu, s1, 1);
        s1 += __shfl_xor_sync(0xffffffffu, s1, 2);
        float i0 = 1.0f / s0, i1 = 1.0f / s1;
#pragma unroll
        for (int nt = 0; nt < 8; nt++) {
            acc1[mt][nt][0] *= i0; acc1[mt][nt][1] *= i0;
            acc1[mt][nt][2] *= i1; acc1[mt][nt][3] *= i1;
        }
#pragma unroll
        for (int ks = 0; ks < 4; ks++) {
            pa_hi[mt][ks][0] = pack_bf16_hi(acc1[mt][2*ks][0],   acc1[mt][2*ks][1]);
            pa_hi[mt][ks][1] = pack_bf16_hi(acc1[mt][2*ks][2],   acc1[mt][2*ks][3]);
            pa_hi[mt][ks][2] = pack_bf16_hi(acc1[mt][2*ks+1][0], acc1[mt][2*ks+1][1]);
            pa_hi[mt][ks][3] = pack_bf16_hi(acc1[mt][2*ks+1][2], acc1[mt][2*ks+1][3]);
            pa_lo[mt][ks][0] = pack_bf16_lo(acc1[mt][2*ks][0],   acc1[mt][2*ks][1]);
            pa_lo[mt][ks][1] = pack_bf16_lo(acc1[mt][2*ks][2],   acc1[mt][2*ks][3]);
            pa_lo[mt][ks][2] = pack_bf16_lo(acc1[mt][2*ks+1][0], acc1[mt][2*ks+1][1]);
            pa_lo[mt][ks][3] = pack_bf16_lo(acc1[mt][2*ks+1][2], acc1[mt][2*ks+1][3]);
        }
    }

    // --- MMA2: preload V frags per ks; 3 term passes ---
    float acc2[2][8][4] = {};
#pragma unroll
    for (int ks = 0; ks < 4; ks++) {
        int kw = ks * 8;
        uint32_t vb[8][2], vl[8][2];
#pragma unroll
        for (int nt = 0; nt < 8; nt++) {
            int n = nt * 8 + lq;
            vb[nt][0] = sVhi[n * RS + kw + lr];
            vb[nt][1] = sVhi[n * RS + kw + lr + 4];
            vl[nt][0] = sVlo[n * RS + kw + lr];
            vl[nt][1] = sVlo[n * RS + kw + lr + 4];
        }
#pragma unroll
        for (int nt = 0; nt < 8; nt++)
#pragma unroll
            for (int mt = 0; mt < 2; mt++) mma16816(acc2[mt][nt], pa_hi[mt][ks], vb[nt]);
#pragma unroll
        for (int nt = 0; nt < 8; nt++)
#pragma unroll
            for (int mt = 0; mt < 2; mt++) mma16816(acc2[mt][nt], pa_hi[mt][ks], vl[nt]);
#pragma unroll
        for (int nt = 0; nt < 8; nt++)
#pragma unroll
            for (int mt = 0; mt < 2; mt++) mma16816(acc2[mt][nt], pa_lo[mt][ks], vb[nt]);
    }

#pragma unroll
    for (int mt = 0; mt < 2; mt++) {
        int r0 = wid * 32 + mt * 16 + lq;
#pragma unroll
        for (int nt = 0; nt < 8; nt++) {
            int e = nt * 8 + lr * 2;
            size_t off0 = (size_t)(b * 8192 + tok0 + r0) * 256 + h * 64 + e;
            size_t off1 = (size_t)(b * 8192 + tok0 + r0 + 8) * 256 + h * 64 + e;
            *(uint32_t*)(g_o_hi + off0) = pack_bf16_hi(acc2[mt][nt][0], acc2[mt][nt][1]);
            *(uint32_t*)(g_o_lo + off0) = pack_bf16_lo(acc2[mt][nt][0], acc2[mt][nt][1]);
            *(uint32_t*)(g_o_hi + off1) = pack_bf16_hi(acc2[mt][nt][2], acc2[mt][nt][3]);
            *(uint32_t*)(g_o_lo + off1) = pack_bf16_lo(acc2[mt][nt][2], acc2[mt][nt][3]);
        }
    }
}

// ---------------- LayerNorm stats per token ----------------
__global__ void k_lnstat() {
    int tid = threadIdx.x;
    int warp = tid >> 5, lane = tid & 31;
    int t = blockIdx.x * 8 + warp;
    const float4* row = (const float4*)(g_o2 + (size_t)t * 256);
    float s = 0.f, sq = 0.f;
#pragma unroll
    for (int j = 0; j < 2; j++) {
        float4 v = row[j * 32 + lane];
        s  += v.x + v.y + v.z + v.w;
        sq += v.x * v.x + v.y * v.y + v.z * v.z + v.w * v.w;
    }
#pragma unroll
    for (int off = 16; off; off >>= 1) {
        s  += __shfl_xor_sync(0xffffffffu, s, off);
        sq += __shfl_xor_sync(0xffffffffu, sq, off);
    }
    if (lane == 0) {
        float mu = s * (1.0f / 256.0f);
        float var = sq * (1.0f / 256.0f) - mu * mu;
        g_mu[t] = mu;
        g_rs[t] = rsqrtf(var + 1e-5f);
    }
}

// ---------------- LN apply + residual + restore NCDHW ----------------
__global__ void k_lnapply(const float* __restrict__ x, const float* __restrict__ g,
                          const float* __restrict__ be) {
    __shared__ float tl[64 * 65];
    __shared__ float mus[64], rss[64];
    int c0 = blockIdx.x * 64;
    int sp0 = blockIdx.y * 64;
    int b = blockIdx.z;
    int tid = threadIdx.x;
    if (tid < 64) {
        int sp = sp0 + tid;
        int d = sp >> 10, rem = sp & 1023, h = rem >> 5, w = rem & 31;
        int n = h * 256 + w * 8 + d;
        mus[tid] = g_mu[b * 8192 + n];
        rss[tid] = g_rs[b * 8192 + n];
    }
#pragma unroll
    for (int i = 0; i < 16; i++) {
        int idx = i * 256 + tid;
        int s = idx >> 6, c = idx & 63;
        int sp = sp0 + s;
        int d = sp >> 10, rem = sp & 1023, h = rem >> 5, w = rem & 31;
        int n = h * 256 + w * 8 + d;
        tl[s * 65 + c] = g_o2[(size_t)(b * 8192 + n) * 256 + c0 + c];
    }
    __syncthreads();
#pragma unroll
    for (int i = 0; i < 16; i++) {
        int idx = i * 256 + tid;
        int c = idx >> 6, s = idx & 63;
        float gg = g[c0 + c], bb = be[c0 + c];
        float r = (tl[s * 65 + c] - mus[s]) * rss[s] * gg + bb;
        size_t gi = (size_t)(b * 256 + c0 + c) * SPA + sp0 + s;
        g_y[gi] = x[gi] + r;
    }
}

// ---------------- depthwise 3x3x3 SAME conv (register-blocked) ----------------
__global__ void k_dwconv(const float* __restrict__ dwk, const float* __restrict__ dwb) {
    __shared__ float tile[10 * 34 * 34];
    __shared__ float wk[27];
    int bc = blockIdx.x;
    int c = bc & 255;
    int tid = threadIdx.x;
    if (tid < 27) wk[tid] = dwk[c * 27 + tid];
    const float* src = g_y + (size_t)bc * SPA;
    for (int i = tid; i < 11560; i += 256) {
        int dz = i / 1156;
        int rem = i - dz * 1156;
        int hy = rem / 34;
        int wx = rem - hy * 34;
        int d = dz - 1, hh = hy - 1, w = wx - 1;
        float val = 0.f;
        if (d >= 0 && d < 8 && hh >= 0 && hh < 32 && w >= 0 && w < 32)
            val = src[d * 1024 + hh * 32 + w];
        tile[i] = val;
    }
    __syncthreads();
    float bias = dwb[c];
    int r = tid >> 3;
    int wg = (tid & 7) * 4;
#pragma unroll
    for (int d = 0; d < 8; d++) {
        float a0 = 0.f, a1 = 0.f, a2 = 0.f, a3 = 0.f;
#pragma unroll
        for (int kd = 0; kd < 3; kd++) {
#pragma unroll
            for (int kh = 0; kh < 3; kh++) {
                const float* row = &tile[(d + kd) * 1156 + (r + kh) * 34 + wg];
                const float* wrow = &wk[kd * 9 + kh * 3];
                float t0 = row[0], t1 = row[1], t2 = row[2];
                float t3 = row[3], t4 = row[4], t5 = row[5];
                float w0 = wrow[0], w1 = wrow[1], w2 = wrow[2];
                a0 += w0 * t0 + w1 * t1 + w2 * t2;
                a1 += w0 * t1 + w1 * t2 + w2 * t3;
                a2 += w0 * t2 + w1 * t3 + w2 * t4;
                a3 += w0 * t3 + w1 * t4 + w2 * t5;
            }
        }
        size_t o = (size_t)bc * SPA + d * 1024 + r * 32 + wg;
        float v0 = a0 + bias, v1 = a1 + bias, v2 = a2 + bias, v3 = a3 + bias;
        uint2 vh, vl;
        vh.x = pack_bf16_hi(v0, v1); vh.y = pack_bf16_hi(v2, v3);
        vl.x = pack_bf16_lo(v0, v1); vl.y = pack_bf16_lo(v2, v3);
        *(uint2*)(g_dw_hi + o) = vh;
        *(uint2*)(g_dw_lo + o) = vl;
    }
}

// ---------------- pointwise conv on HMMA + bias + final residual ----------------
__global__ void __launch_bounds__(256, 2) k_pwfin(const float* __restrict__ pwb,
                                                  float* __restrict__ out) {
    extern __shared__ __align__(16) uint32_t sm[];
    uint32_t* sAhi = sm;
    uint32_t* sAlo = sAhi + TILE_W;
    uint32_t* sBhi = sAlo + TILE_W;
    uint32_t* sBlo = sBhi + TILE_W;

    int tid = threadIdx.x;
    int wid = tid >> 5, lane = tid & 31;
    int wr = wid >> 2, wc = wid & 3;
    int sp0 = blockIdx.x * 128;
    int co0 = blockIdx.y * 128;
    int b = blockIdx.z;
    int lq = lane >> 2, lr = lane & 3;

    float acc[4][4][4] = {};

    for (int ci0 = 0; ci0 < 256; ci0 += 64) {
#pragma unroll
        for (int i = 0; i < 4; i++) {
            int idx = tid + i * 256;
            int r = idx >> 3, gq = idx & 7;
            *(uint4*)&sAhi[r * RS + gq * 4] =
                *(const uint4*)&g_pwk_hi[(co0 + r) * 256 + ci0 + gq * 8];
            *(uint4*)&sAlo[r * RS + gq * 4] =
                *(const uint4*)&g_pwk_lo[(co0 + r) * 256 + ci0 + gq * 8];
        }
#pragma unroll
        for (int jl = 0; jl < 4; jl++) {
            int j = jl * 8 + wid;
            size_t rbase = (size_t)(b * 256 + ci0 + 2 * j) * SPA + sp0;
#pragma unroll
            for (int sh = 0; sh < 2; sh++) {
                int slp = (sh * 32 + lane) * 2;
                uint32_t u0 = *(const uint32_t*)(g_dw_hi + rbase + slp);
                uint32_t u1 = *(const uint32_t*)(g_dw_hi + rbase + SPA + slp);
                sBhi[slp * RS + j]       = __byte_perm(u0, u1, 0x5410);
                sBhi[(slp + 1) * RS + j] = __byte_perm(u0, u1, 0x7632);
                u0 = *(const uint32_t*)(g_dw_lo + rbase + slp);
                u1 = *(const uint32_t*)(g_dw_lo + rbase + SPA + slp);
                sBlo[slp * RS + j]       = __byte_perm(u0, u1, 0x5410);
                sBlo[(slp + 1) * RS + j] = __byte_perm(u0, u1, 0x7632);
            }
        }
        __syncthreads();
#pragma unroll
        for (int ks = 0; ks < 4; ks++) {
            int kw = ks * 8;
            uint32_t bh[4][2], bl[4][2];
#pragma unroll
            for (int nt = 0; nt < 4; nt++) {
                int n = wc * 32 + nt * 8 + lq;
                bh[nt][0] = sBhi[n * RS + kw + lr];
                bh[nt][1] = sBhi[n * RS + kw + lr + 4];
                bl[nt][0] = sBlo[n * RS + kw + lr];
                bl[nt][1] = sBlo[n * RS + kw + lr + 4];
            }
#pragma unroll
            for (int mt = 0; mt < 4; mt++) {
                int r = wr * 64 + mt * 16 + lq;
                uint32_t ah[4], al[4];
                ah[0] = sAhi[r * RS + kw + lr];
                ah[1] = sAhi[(r + 8) * RS + kw + lr];
                ah[2] = sAhi[r * RS + kw + lr + 4];
                ah[3] = sAhi[(r + 8) * RS + kw + lr + 4];
                al[0] = sAlo[r * RS + kw + lr];
                al[1] = sAlo[(r + 8) * RS + kw + lr];
                al[2] = sAlo[r * RS + kw + lr + 4];
                al[3] = sAlo[(r + 8) * RS + kw + lr + 4];
#pragma unroll
                for (int nt = 0; nt < 4; nt++) mma16816(acc[mt][nt], ah, bh[nt]);
#pragma unroll
                for (int nt = 0; nt < 4; nt++) mma16816(acc[mt][nt], ah, bl[nt]);
#pragma unroll
                for (int nt = 0; nt < 4; nt++) mma16816(acc[mt][nt], al, bh[nt]);
            }
        }
        __syncthreads();
    }
#pragma unroll
    for (int mt = 0; mt < 4; mt++) {
        int r = co0 + wr * 64 + mt * 16 + lq;
        float bb0 = pwb[r], bb1 = pwb[r + 8];
#pragma unroll
        for (int nt = 0; nt < 4; nt++) {
            int c = sp0 + wc * 32 + nt * 8 + lr * 2;
            size_t i0 = (size_t)(b * 256 + r) * SPA + c;
            size_t i1 = (size_t)(b * 256 + r + 8) * SPA + c;
            float2 y0 = *(const float2*)&g_y[i0];
            float2 y1 = *(const float2*)&g_y[i1];
            float2 v0, v1;
            v0.x = acc[mt][nt][0] + bb0 + y0.x;
            v0.y = acc[mt][nt][1] + bb0 + y0.y;
            v1.x = acc[mt][nt][2] + bb1 + y1.x;
            v1.y = acc[mt][nt][3] + bb1 + y1.y;
            *(float2*)&out[i0] = v0;
            *(float2*)&out[i1] = v1;
        }
    }
}
#define SMEM_PW (4 * TILE_W * 4)

// ---------------- launch ----------------
extern "C" void kernel_launch(void* const* d_in, const int* in_sizes, int n_in,
                              void* d_out, int out_size) {
    (void)in_sizes; (void)n_in; (void)out_size;
    const float* x    = (const float*)d_in[0];
    const float* wqkv = (const float*)d_in[1];
    const float* wseq = (const float*)d_in[2];
    const float* bseq = (const float*)d_in[3];
    const float* temp = (const float*)d_in[4];
    const float* wout = (const float*)d_in[5];
    const float* bout = (const float*)d_in[6];
    const float* lng  = (const float*)d_in[7];
    const float* lnb  = (const float*)d_in[8];
    const float* dwk  = (const float*)d_in[9];
    const float* dwb  = (const float*)d_in[10];
    const float* pwk  = (const float*)d_in[11];
    const float* pwb  = (const float*)d_in[12];
    float* out = (float*)d_out;

    float *qkv, *o2;
    __nv_bfloat16 *t_hi, *t_lo, *o_hi, *o_lo;
    __nv_bfloat16 *wqkvT_hi, *wqkvT_lo, *woutT_hi, *woutT_lo, *pwk_hi, *pwk_lo;
    __nv_bfloat16 *wsT_hi, *wsT_lo;
    cudaGetSymbolAddress((void**)&qkv, g_qkv);
    cudaGetSymbolAddress((void**)&o2,  g_o2);
    cudaGetSymbolAddress((void**)&t_hi, g_t_hi);
    cudaGetSymbolAddress((void**)&t_lo, g_t_lo);
    cudaGetSymbolAddress((void**)&o_hi, g_o_hi);
    cudaGetSymbolAddress((void**)&o_lo, g_o_lo);
    cudaGetSymbolAddress((void**)&wqkvT_hi, g_wqkvT_hi);
    cudaGetSymbolAddress((void**)&wqkvT_lo, g_wqkvT_lo);
    cudaGetSymbolAddress((void**)&woutT_hi, g_woutT_hi);
    cudaGetSymbolAddress((void**)&woutT_lo, g_woutT_lo);
    cudaGetSymbolAddress((void**)&pwk_hi, g_pwk_hi);
    cudaGetSymbolAddress((void**)&pwk_lo, g_pwk_lo);
    cudaGetSymbolAddress((void**)&wsT_hi, g_wsT_hi);
    cudaGetSymbolAddress((void**)&wsT_lo, g_wsT_lo);

    cudaFuncSetAttribute(k_mma, cudaFuncAttributeMaxDynamicSharedMemorySize, SMEM_MMA);
    cudaFuncSetAttribute(k_pwfin, cudaFuncAttributeMaxDynamicSharedMemorySize, SMEM_PW);
    cudaFuncSetAttribute(k_kvproj, cudaFuncAttributeMaxDynamicSharedMemorySize, SMEM_KV);
    cudaFuncSetAttribute(k_attn, cudaFuncAttributeMaxDynamicSharedMemorySize, SMEM_AT);

    k_transpose<<<dim3(4, 128, 4), 256>>>(x);
    k_wtprep_all<<<192, 256>>>(wqkv, wout, wseq);
    k_wprep_nt<<<256, 256>>>(pwk, pwk_hi, pwk_lo, 256 * 256);
    k_mma<<<dim3(6, 256), 256, SMEM_MMA>>>(t_hi, t_lo, wqkvT_hi, wqkvT_lo, nullptr, qkv, 256, 768);
    k_cnpart<<<dim3(64, 4), 256>>>(qkv);
    k_cnfin<<<8, 256>>>();
    k_kvproj<<<dim3(16, 16, 2), 128, SMEM_KV>>>(qkv, wsT_hi, wsT_lo);
    k_kvred<<<512, 256>>>(bseq);
    k_attn<<<dim3(64, 4, 4), 128, SMEM_AT>>>(qkv, temp);
    k_mma<<<dim3(2, 256), 256, SMEM_MMA>>>(o_hi, o_lo, woutT_hi, woutT_lo, bout, o2, 256, 256);
    k_lnstat<<<4096, 256>>>();
    k_lnapply<<<dim3(4, 128, 4), 256>>>(x, lng, lnb);
    k_dwconv<<<1024, 256>>>(dwk, dwb);
    k_pwfin<<<dim3(64, 2, 4), 256, SMEM_PW>>>(pwb, out);
}

// round 15
// speedup vs baseline: 2.3239x; 1.0273x over previous
#include <cuda_runtime.h>
#include <cuda_bf16.h>
#include <math.h>
#include <stdint.h>

// Problem constants
#define BQ   4
#define CC   256
#define NHEAD 4
#define PP   64
#define NN   8192
#define SPA  8192

// ---------------- scratch (device globals) ----------------
__device__ __align__(128) __nv_bfloat16 g_t_hi[(size_t)BQ * NN * CC];
__device__ __align__(128) __nv_bfloat16 g_t_lo[(size_t)BQ * NN * CC];
__device__ float g_qkv [(size_t)BQ * NN * 3 * CC];
__device__ float g_cnpart[256 * 512];
__device__ float g_rnorm [BQ * 512];
__device__ float g_kvpart[2 * 16 * 16 * 4096];
__device__ __align__(128) __nv_bfloat16 g_kpT_hi[16 * 4096];
__device__ __align__(128) __nv_bfloat16 g_kpT_lo[16 * 4096];
__device__ __align__(128) __nv_bfloat16 g_vp_hi [16 * 4096];
__device__ __align__(128) __nv_bfloat16 g_vp_lo [16 * 4096];
__device__ __align__(128) __nv_bfloat16 g_o_hi[(size_t)BQ * NN * CC];
__device__ __align__(128) __nv_bfloat16 g_o_lo[(size_t)BQ * NN * CC];
__device__ float g_o2  [(size_t)BQ * NN * CC];
__device__ float g_mu  [BQ * NN];
__device__ float g_rs  [BQ * NN];
__device__ float g_y   [(size_t)BQ * CC * SPA];
__device__ __align__(128) __nv_bfloat16 g_dw_hi[(size_t)BQ * CC * SPA];
__device__ __align__(128) __nv_bfloat16 g_dw_lo[(size_t)BQ * CC * SPA];
__device__ __align__(128) __nv_bfloat16 g_wqkvT_hi[768 * 256];
__device__ __align__(128) __nv_bfloat16 g_wqkvT_lo[768 * 256];
__device__ __align__(128) __nv_bfloat16 g_woutT_hi[256 * 256];
__device__ __align__(128) __nv_bfloat16 g_woutT_lo[256 * 256];
__device__ __align__(128) __nv_bfloat16 g_pwk_hi[256 * 256];
__device__ __align__(128) __nv_bfloat16 g_pwk_lo[256 * 256];
__device__ __align__(128) __nv_bfloat16 g_wsT_hi[64 * 8192];
__device__ __align__(128) __nv_bfloat16 g_wsT_lo[64 * 8192];

// ---------------- helpers ----------------
__device__ __forceinline__ uint32_t pack_bf16_hi(float a, float b) {
    __nv_bfloat16 ha = __float2bfloat16(a);
    __nv_bfloat16 hb = __float2bfloat16(b);
    return ((uint32_t)__bfloat16_as_ushort(hb) << 16) | __bfloat16_as_ushort(ha);
}
__device__ __forceinline__ uint32_t pack_bf16_lo(float a, float b) {
    __nv_bfloat16 ha = __float2bfloat16(a);
    __nv_bfloat16 hb = __float2bfloat16(b);
    __nv_bfloat16 la = __float2bfloat16(a - __bfloat162float(ha));
    __nv_bfloat16 lb = __float2bfloat16(b - __bfloat162float(hb));
    return ((uint32_t)__bfloat16_as_ushort(lb) << 16) | __bfloat16_as_ushort(la);
}

__device__ __forceinline__ void mma16816(float* d, const uint32_t* a, const uint32_t* b) {
    asm volatile(
        "mma.sync.aligned.m16n8k16.row.col.f32.bf16.bf16.f32 "
        "{%0,%1,%2,%3}, {%4,%5,%6,%7}, {%8,%9}, {%0,%1,%2,%3};"
        : "+f"(d[0]), "+f"(d[1]), "+f"(d[2]), "+f"(d[3])
        : "r"(a[0]), "r"(a[1]), "r"(a[2]), "r"(a[3]), "r"(b[0]), "r"(b[1]));
}

__device__ __forceinline__ void ldsm_x4(uint32_t* r, uint32_t addr) {
    asm volatile("ldmatrix.sync.aligned.m8n8.x4.shared.b16 {%0,%1,%2,%3}, [%4];"
        : "=r"(r[0]), "=r"(r[1]), "=r"(r[2]), "=r"(r[3]) : "r"(addr));
}

__device__ __forceinline__ uint32_t smem_u32(const void* p) {
    uint32_t a;
    asm("{ .reg .u64 t; cvta.to.shared.u64 t, %1; cvt.u32.u64 %0, t; }" : "=r"(a) : "l"(p));
    return a;
}
#define CP_ASYNC16(dst, src) \
    asm volatile("cp.async.cg.shared.global [%0], [%1], 16;" :: "r"(dst), "l"(src) : "memory")
#define CP_COMMIT() asm volatile("cp.async.commit_group;" ::: "memory")
#define CP_WAIT1()  asm volatile("cp.async.wait_group 1;" ::: "memory")
#define CP_WAIT0()  asm volatile("cp.async.wait_group 0;" ::: "memory")

#define RS 36
#define TILE_W (128 * RS)
#define RS2 20
#define TW2 (128 * RS2)

// ---------------- K0: transpose x (NCDHW) -> t_hi/lo [B,N,C] bf16 ----------------
__global__ void k_transpose(const float* __restrict__ x) {
    __shared__ float tile[64 * 65];
    int c0 = blockIdx.x * 64;
    int sp0 = blockIdx.y * 64;
    int b = blockIdx.z;
    int tid = threadIdx.x;
#pragma unroll
    for (int i = 0; i < 16; i++) {
        int idx = i * 256 + tid;
        int c = idx >> 6, s = idx & 63;
        tile[c * 65 + s] = x[(size_t)(b * 256 + c0 + c) * SPA + sp0 + s];
    }
    __syncthreads();
#pragma unroll
    for (int i = 0; i < 8; i++) {
        int idx = i * 256 + tid;
        int s = idx >> 5, c2 = idx & 31;
        int c = c2 * 2;
        int sp = sp0 + s;
        int d = sp >> 10, rem = sp & 1023, h = rem >> 5, w = rem & 31;
        int n = h * 256 + w * 8 + d;
        float v0 = tile[c * 65 + s];
        float v1 = tile[(c + 1) * 65 + s];
        size_t gi = (size_t)(b * 8192 + n) * 256 + c0 + c;
        *(uint32_t*)(g_t_hi + gi) = pack_bf16_hi(v0, v1);
        *(uint32_t*)(g_t_lo + gi) = pack_bf16_lo(v0, v1);
    }
}

// ---------------- merged weight prep ----------------
__global__ void k_wtprep_all(const float* __restrict__ wqkv,
                             const float* __restrict__ wout,
                             const float* __restrict__ wseq) {
    __shared__ float sm[64 * 65];
    int bid = blockIdx.x;
    const float* w;
    __nv_bfloat16 *thi, *tlo;
    int K, Nn, gx, gy;
    if (bid < 48) {
        w = wqkv; thi = g_wqkvT_hi; tlo = g_wqkvT_lo;
        K = 256; Nn = 768; gx = bid % 12; gy = bid / 12;
    } else if (bid < 64) {
        int b2 = bid - 48;
        w = wout; thi = g_woutT_hi; tlo = g_woutT_lo;
        K = 256; Nn = 256; gx = b2 & 3; gy = b2 >> 2;
    } else {
        int b3 = bid - 64;
        w = wseq; thi = g_wsT_hi; tlo = g_wsT_lo;
        K = 8192; Nn = 64; gx = 0; gy = b3;
    }
    int n0 = gx * 64;
    int k0 = gy * 64;
    int tid = threadIdx.x;
#pragma unroll
    for (int i = 0; i < 16; i++) {
        int idx = i * 256 + tid;
        int r = idx >> 6, c = idx & 63;
        sm[r * 65 + c] = w[(size_t)(k0 + r) * Nn + n0 + c];
    }
    __syncthreads();
#pragma unroll
    for (int i = 0; i < 16; i++) {
        int idx = i * 256 + tid;
        int r = idx >> 6, c = idx & 63;
        float a = sm[c * 65 + r];
        __nv_bfloat16 h = __float2bfloat16(a);
        size_t gi = (size_t)(n0 + r) * K + k0 + c;
        thi[gi] = h;
        tlo[gi] = __float2bfloat16(a - __bfloat162float(h));
    }
}
__global__ void k_wprep_nt(const float* __restrict__ w, __nv_bfloat16* __restrict__ thi,
                           __nv_bfloat16* __restrict__ tlo, int total) {
    int idx = blockIdx.x * 256 + threadIdx.x;
    if (idx >= total) return;
    float a = w[idx];
    __nv_bfloat16 h = __float2bfloat16(a);
    thi[idx] = h;
    tlo[idx] = __float2bfloat16(a - __bfloat162float(h));
}

// ---------------- HMMA bf16-split GEMM (ldmatrix fragment loads) ----------------
__global__ void __launch_bounds__(256, 2) k_mma(const __nv_bfloat16* __restrict__ Ahi,
                                                const __nv_bfloat16* __restrict__ Alo,
                                                const __nv_bfloat16* __restrict__ Bhi,
                                                const __nv_bfloat16* __restrict__ Blo,
                                                const float* __restrict__ bias,
                                                float* __restrict__ C, int K, int Ntot) {
    extern __shared__ __align__(16) uint32_t sm[];
    uint32_t sbase = smem_u32(sm);

    int tid = threadIdx.x;
    int wid = tid >> 5, lane = tid & 31;
    int wr = wid >> 2, wc = wid & 3;
    int row0 = blockIdx.y * 128;
    int col0 = blockIdx.x * 128;
    int lq = lane >> 2, lr = lane & 3;
    int lt = lane >> 3, lrr = lane & 7;     // ldmatrix tile id / row-in-tile

    float acc[4][4][4] = {};
    int nch = K >> 5;

#define PREFETCH(CH, STG) do {                                                     \
        int _k0 = (CH) << 5;                                                       \
        uint32_t _so = sbase + (STG) * 4 * TW2 * 4;                                \
        _Pragma("unroll")                                                          \
        for (int _i = 0; _i < 2; _i++) {                                           \
            int _idx = tid + _i * 256;                                             \
            int _r = _idx >> 2, _g = _idx & 3;                                     \
            uint32_t _d = _so + (_r * RS2 + _g * 4) * 4;                           \
            const __nv_bfloat16* _s = Ahi + (size_t)(row0 + _r) * K + _k0 + _g * 8;\
            CP_ASYNC16(_d, _s);                                                    \
            _d += TW2 * 4;                                                         \
            _s = Alo + (size_t)(row0 + _r) * K + _k0 + _g * 8;                     \
            CP_ASYNC16(_d, _s);                                                    \
            _d += TW2 * 4;                                                         \
            _s = Bhi + (size_t)(col0 + _r) * K + _k0 + _g * 8;                     \
            CP_ASYNC16(_d, _s);                                                    \
            _d += TW2 * 4;                                                         \
            _s = Blo + (size_t)(col0 + _r) * K + _k0 + _g * 8;                     \
            CP_ASYNC16(_d, _s);                                                    \
        }                                                                          \
    } while (0)

    PREFETCH(0, 0);
    CP_COMMIT();

    for (int ch = 0; ch < nch; ch++) {
        if (ch + 1 < nch) {
            PREFETCH(ch + 1, (ch + 1) & 1);
            CP_COMMIT();
            CP_WAIT1();
        } else {
            CP_WAIT0();
        }
        __syncthreads();
        uint32_t stg = sbase + (ch & 1) * 4 * TW2 * 4;
        uint32_t aHiB = stg;
        uint32_t aLoB = stg + TW2 * 4;
        uint32_t bHiB = stg + 2 * TW2 * 4;
        uint32_t bLoB = stg + 3 * TW2 * 4;
#pragma unroll
        for (int ks = 0; ks < 2; ks++) {
            int kw = ks * 8;
            // B frags: ldmatrix x4 per nt-pair (tiles: n+{0,8}+rr rows; k-half (lt&1))
            uint32_t bh[4][2], bl[4][2];
#pragma unroll
            for (int p = 0; p < 2; p++) {
                int brow = wc * 32 + p * 16 + lrr + ((lt >> 1) << 3);
                int bcol = kw + ((lt & 1) << 2);
                uint32_t boff = (uint32_t)(brow * RS2 + bcol) * 4;
                uint32_t tmp[4];
                ldsm_x4(tmp, bHiB + boff);
                bh[2 * p][0] = tmp[0]; bh[2 * p][1] = tmp[1];
                bh[2 * p + 1][0] = tmp[2]; bh[2 * p + 1][1] = tmp[3];
                ldsm_x4(tmp, bLoB + boff);
                bl[2 * p][0] = tmp[0]; bl[2 * p][1] = tmp[1];
                bl[2 * p + 1][0] = tmp[2]; bl[2 * p + 1][1] = tmp[3];
            }
#pragma unroll
            for (int mt = 0; mt < 4; mt++) {
                int arow = wr * 64 + mt * 16 + lrr + ((lt & 1) << 3);
                int acol = kw + ((lt >> 1) << 2);
                uint32_t aoff = (uint32_t)(arow * RS2 + acol) * 4;
                uint32_t ah[4], al[4];
                ldsm_x4(ah, aHiB + aoff);
                ldsm_x4(al, aLoB + aoff);
#pragma unroll
                for (int nt = 0; nt < 4; nt++) mma16816(acc[mt][nt], ah, bh[nt]);
#pragma unroll
                for (int nt = 0; nt < 4; nt++) mma16816(acc[mt][nt], ah, bl[nt]);
#pragma unroll
                for (int nt = 0; nt < 4; nt++) mma16816(acc[mt][nt], al, bh[nt]);
            }
        }
        __syncthreads();
    }
#undef PREFETCH
#pragma unroll
    for (int mt = 0; mt < 4; mt++) {
        int r = row0 + wr * 64 + mt * 16 + lq;
#pragma unroll
        for (int nt = 0; nt < 4; nt++) {
            int c = col0 + wc * 32 + nt * 8 + lr * 2;
            float b0 = bias ? bias[c] : 0.0f;
            float b1 = bias ? bias[c + 1] : 0.0f;
            float2 v0, v1;
            v0.x = acc[mt][nt][0] + b0;
            v0.y = acc[mt][nt][1] + b1;
            v1.x = acc[mt][nt][2] + b0;
            v1.y = acc[mt][nt][3] + b1;
            *(float2*)&C[(size_t)r * Ntot + c] = v0;
            *(float2*)&C[(size_t)(r + 8) * Ntot + c] = v1;
        }
    }
}
#define SMEM_MMA (8 * TW2 * 4)

// ---------------- column L2 norms for q,k ----------------
__global__ void k_cnpart(const float* __restrict__ qkv) {
    int chunk = blockIdx.x;
    int b = blockIdx.y;
    int tid = threadIdx.x;
    float s0 = 0.f, s1 = 0.f;
    int n0 = chunk * 128;
    const float* base = qkv + (size_t)(b * 8192 + n0) * 768;
#pragma unroll 4
    for (int j = 0; j < 128; j++) {
        const float* row = base + (size_t)j * 768;
        float v0 = row[tid];
        float v1 = row[256 + tid];
        s0 += v0 * v0;
        s1 += v1 * v1;
    }
    g_cnpart[(b * 64 + chunk) * 512 + tid] = s0;
    g_cnpart[(b * 64 + chunk) * 512 + 256 + tid] = s1;
}

__global__ void k_cnfin() {
    int idx = blockIdx.x * 256 + threadIdx.x;
    int b = idx >> 9, col = idx & 511;
    float s = 0.f;
#pragma unroll
    for (int ch = 0; ch < 64; ch++) s += g_cnpart[(b * 64 + ch) * 512 + col];
    g_rnorm[idx] = 1.0f / fmaxf(sqrtf(s), 1e-12f);
}

// ---------------- kp/vp projections on HMMA ----------------
#define SMEM_KV (64 * 65 * 4 + 4 * 64 * RS * 4)
__global__ void __launch_bounds__(128) k_kvproj(const float* __restrict__ qkv,
                                                const __nv_bfloat16* __restrict__ wsThi,
                                                const __nv_bfloat16* __restrict__ wsTlo) {
    extern __shared__ __align__(16) char smraw[];
    float* sF = (float*)smraw;
    uint32_t* sAhi = (uint32_t*)(smraw + 64 * 65 * 4);
    uint32_t* sAlo = sAhi + 64 * RS;
    uint32_t* sBhi = sAlo + 64 * RS;
    uint32_t* sBlo = sBhi + 64 * RS;

    int slice = blockIdx.x;
    int bh = blockIdx.y;
    int kind = blockIdx.z;
    int b = bh >> 2, h = bh & 3;
    int colbase = (kind == 0 ? 256 : 512) + h * 64;
    int tid = threadIdx.x;
    int wid = tid >> 5, lane = tid & 31;
    int wr = wid >> 1, wc = wid & 1;
    int lq = lane >> 2, lr = lane & 3;
    int wa = lane & 7, wb = lane >> 3;

    float acc[2][4][4] = {};

    int nbeg = slice * 512;
    for (int ch = 0; ch < 8; ch++) {
        int n0 = nbeg + ch * 64;
#pragma unroll
        for (int i = 0; i < 8; i++) {
            int idx = tid + i * 128;
            int r = idx >> 4, c4 = idx & 15;
            float4 v = *(const float4*)&qkv[(size_t)(b * 8192 + n0 + r) * 768 + colbase + c4 * 4];
            float* dst = &sF[r * 65 + c4 * 4];
            dst[0] = v.x; dst[1] = v.y; dst[2] = v.z; dst[3] = v.w;
        }
#pragma unroll
        for (int i = 0; i < 4; i++) {
            int idx = tid + i * 128;
            int r = idx >> 3, q = idx & 7;
            *(uint4*)&sBhi[r * RS + q * 4] = *(const uint4*)&wsThi[(size_t)r * 8192 + n0 + q * 8];
            *(uint4*)&sBlo[r * RS + q * 4] = *(const uint4*)&wsTlo[(size_t)r * 8192 + n0 + q * 8];
        }
        __syncthreads();
#pragma unroll
        for (int ia = 0; ia < 2; ia++) {
            int e = wid * 16 + 8 * ia + wa;
#pragma unroll
            for (int inp = 0; inp < 8; inp++) {
                int np = 4 * inp + wb;
                float v0 = sF[(2 * np) * 65 + e];
                float v1 = sF[(2 * np + 1) * 65 + e];
                sAhi[e * RS + np] = pack_bf16_hi(v0, v1);
                sAlo[e * RS + np] = pack_bf16_lo(v0, v1);
            }
        }
        __syncthreads();
#pragma unroll
        for (int ks = 0; ks < 4; ks++) {
            int kw = ks * 8;
            uint32_t bhf[4][2], blf[4][2];
#pragma unroll
            for (int nt = 0; nt < 4; nt++) {
                int nrow = wc * 32 + nt * 8 + lq;
                bhf[nt][0] = sBhi[nrow * RS + kw + lr];
                bhf[nt][1] = sBhi[nrow * RS + kw + lr + 4];
                blf[nt][0] = sBlo[nrow * RS + kw + lr];
                blf[nt][1] = sBlo[nrow * RS + kw + lr + 4];
            }
#pragma unroll
            for (int mt = 0; mt < 2; mt++) {
                int r = wr * 32 + mt * 16 + lq;
                uint32_t ah[4], al[4];
                ah[0] = sAhi[r * RS + kw + lr];
                ah[1] = sAhi[(r + 8) * RS + kw + lr];
                ah[2] = sAhi[r * RS + kw + lr + 4];
                ah[3] = sAhi[(r + 8) * RS + kw + lr + 4];
                al[0] = sAlo[r * RS + kw + lr];
                al[1] = sAlo[(r + 8) * RS + kw + lr];
                al[2] = sAlo[r * RS + kw + lr + 4];
                al[3] = sAlo[(r + 8) * RS + kw + lr + 4];
#pragma unroll
                for (int nt = 0; nt < 4; nt++) mma16816(acc[mt][nt], ah, bhf[nt]);
#pragma unroll
                for (int nt = 0; nt < 4; nt++) mma16816(acc[mt][nt], ah, blf[nt]);
#pragma unroll
                for (int nt = 0; nt < 4; nt++) mma16816(acc[mt][nt], al, bhf[nt]);
            }
        }
        __syncthreads();
    }
    float* dst = g_kvpart + (size_t)((kind * 16 + bh) * 16 + slice) * 4096;
#pragma unroll
    for (int mt = 0; mt < 2; mt++) {
        int e = wr * 32 + mt * 16 + lq;
#pragma unroll
        for (int nt = 0; nt < 4; nt++) {
            int p = wc * 32 + nt * 8 + lr * 2;
            *(float2*)&dst[e * 64 + p] = make_float2(acc[mt][nt][0], acc[mt][nt][1]);
            *(float2*)&dst[(e + 8) * 64 + p] = make_float2(acc[mt][nt][2], acc[mt][nt][3]);
        }
    }
}

// reduce + bias + fold norms
__global__ void k_kvred(const float* __restrict__ bseq) {
    int idx = blockIdx.x * 256 + threadIdx.x;
    int kb = idx >> 12;
    int ep = idx & 4095;
    float s = 0.f;
#pragma unroll
    for (int sl = 0; sl < 16; sl++) s += g_kvpart[(size_t)(kb * 16 + sl) * 4096 + ep];
    int kind = kb >> 4, bh = kb & 15;
    int b = bh >> 2, h = bh & 3;
    int e = ep >> 6, p = ep & 63;
    if (kind == 0) {
        float v = s * g_rnorm[b * 512 + 256 + h * 64 + e] + bseq[p];
        v *= g_rnorm[b * 512 + h * 64 + e];
        __nv_bfloat16 hi = __float2bfloat16(v);
        g_kpT_hi[bh * 4096 + p * 64 + e] = hi;
        g_kpT_lo[bh * 4096 + p * 64 + e] = __float2bfloat16(v - __bfloat162float(hi));
    } else {
        float v = s + bseq[p];
        __nv_bfloat16 hi = __float2bfloat16(v);
        g_vp_hi[bh * 4096 + ep] = hi;
        g_vp_lo[bh * 4096 + ep] = __float2bfloat16(v - __bfloat162float(hi));
    }
}

// ---------------- fused attention on HMMA ----------------
#define SMEM_AT ((128 * RS * 2 + 64 * RS * 4) * 4)
__global__ void __launch_bounds__(128) k_attn(const float* __restrict__ qkv,
                                              const float* __restrict__ temp) {
    extern __shared__ __align__(16) uint32_t sm[];
    uint32_t* sQhi = sm;
    uint32_t* sQlo = sm + 128 * RS;
    uint32_t* sKhi = sm + 256 * RS;
    uint32_t* sKlo = sKhi + 64 * RS;
    uint32_t* sVhi = sKlo + 64 * RS;
    uint32_t* sVlo = sVhi + 64 * RS;

    int tid = threadIdx.x;
    int wid = tid >> 5, lane = tid & 31;
    int lq = lane >> 2, lr = lane & 3;
    int h = blockIdx.y, b = blockIdx.z;
    int bh = b * 4 + h;
    int tok0 = blockIdx.x * 128;

    {
        const uint4* skh = (const uint4*)(g_kpT_hi + (size_t)bh * 4096);
        const uint4* skl = (const uint4*)(g_kpT_lo + (size_t)bh * 4096);
        const uint4* svh = (const uint4*)(g_vp_hi + (size_t)bh * 4096);
        const uint4* svl = (const uint4*)(g_vp_lo + (size_t)bh * 4096);
#pragma unroll
        for (int i = 0; i < 4; i++) {
            int idx = tid + i * 128;
            int r = idx >> 3, q = idx & 7;
            *(uint4*)&sKhi[r * RS + q * 4] = skh[idx];
            *(uint4*)&sKlo[r * RS + q * 4] = skl[idx];
            *(uint4*)&sVhi[r * RS + q * 4] = svh[idx];
            *(uint4*)&sVlo[r * RS + q * 4] = svl[idx];
        }
    }
#pragma unroll
    for (int i = 0; i < 16; i++) {
        int idx = tid + i * 128;
        int r = idx >> 4, c4 = idx & 15;
        float4 v = *(const float4*)&qkv[(size_t)(b * 8192 + tok0 + r) * 768 + h * 64 + c4 * 4];
        sQhi[r * RS + c4 * 2]     = pack_bf16_hi(v.x, v.y);
        sQhi[r * RS + c4 * 2 + 1] = pack_bf16_hi(v.z, v.w);
        sQlo[r * RS + c4 * 2]     = pack_bf16_lo(v.x, v.y);
        sQlo[r * RS + c4 * 2 + 1] = pack_bf16_lo(v.z, v.w);
    }
    __syncthreads();
    float tv = temp[h];

    float acc1[2][8][4] = {};
#pragma unroll
    for (int ks = 0; ks < 4; ks++) {
        int kw = ks * 8;
        uint32_t qh[2][4], ql2[2][4];
#pragma unroll
        for (int mt = 0; mt < 2; mt++) {
            int r = wid * 32 + mt * 16 + lq;
            qh[mt][0]  = sQhi[r * RS + kw + lr];
            qh[mt][1]  = sQhi[(r + 8) * RS + kw + lr];
            qh[mt][2]  = sQhi[r * RS + kw + lr + 4];
            qh[mt][3]  = sQhi[(r + 8) * RS + kw + lr + 4];
            ql2[mt][0] = sQlo[r * RS + kw + lr];
            ql2[mt][1] = sQlo[(r + 8) * RS + kw + lr];
            ql2[mt][2] = sQlo[r * RS + kw + lr + 4];
            ql2[mt][3] = sQlo[(r + 8) * RS + kw + lr + 4];
        }
        uint32_t kb[8][2], kl[8][2];
#pragma unroll
        for (int nt = 0; nt < 8; nt++) {
            int n = nt * 8 + lq;
            kb[nt][0] = sKhi[n * RS + kw + lr];
            kb[nt][1] = sKhi[n * RS + kw + lr + 4];
            kl[nt][0] = sKlo[n * RS + kw + lr];
            kl[nt][1] = sKlo[n * RS + kw + lr + 4];
        }
#pragma unroll
        for (int nt = 0; nt < 8; nt++)
#pragma unroll
            for (int mt = 0; mt < 2; mt++) mma16816(acc1[mt][nt], qh[mt], kb[nt]);
#pragma unroll
        for (int nt = 0; nt < 8; nt++)
#pragma unroll
            for (int mt = 0; mt < 2; mt++) mma16816(acc1[mt][nt], qh[mt], kl[nt]);
#pragma unroll
        for (int nt = 0; nt < 8; nt++)
#pragma unroll
            for (int mt = 0; mt < 2; mt++) mma16816(acc1[mt][nt], ql2[mt], kb[nt]);
    }

    uint32_t pa_hi[2][4][4], pa_lo[2][4][4];
#pragma unroll
    for (int mt = 0; mt < 2; mt++) {
#pragma unroll
        for (int nt = 0; nt < 8; nt++)
#pragma unroll
            for (int j = 0; j < 4; j++) acc1[mt][nt][j] *= tv;
        float m0 = -1e30f, m1 = -1e30f;
#pragma unroll
        for (int nt = 0; nt < 8; nt++) {
            m0 = fmaxf(m0, fmaxf(acc1[mt][nt][0], acc1[mt][nt][1]));
            m1 = fmaxf(m1, fmaxf(acc1[mt][nt][2], acc1[mt][nt][3]));
        }
        m0 = fmaxf(m0, __shfl_xor_sync(0xffffffffu, m0, 1));
        m0 = fmaxf(m0, __shfl_xor_sync(0xffffffffu, m0, 2));
        m1 = fmaxf(m1, __shfl_xor_sync(0xffffffffu, m1, 1));
        m1 = fmaxf(m1, __shfl_xor_sync(0xffffffffu, m1, 2));
        float s0 = 0.f, s1 = 0.f;
#pragma unroll
        for (int nt = 0; nt < 8; nt++) {
            acc1[mt][nt][0] = __expf(acc1[mt][nt][0] - m0);
            acc1[mt][nt][1] = __expf(acc1[mt][nt][1] - m0);
            acc1[mt][nt][2] = __expf(acc1[mt][nt][2] - m1);
            acc1[mt][nt][3] = __expf(acc1[mt][nt][3] - m1);
            s0 += acc1[mt][nt][0] + acc1[mt][nt][1];
            s1 += acc1[mt][nt][2] + acc1[mt][nt][3];
        }
        s0 += __shfl_xor_sync(0xffffffffu, s0, 1);
        s0 += __shfl_xor_sync(0xffffffffu, s0, 2);
        s1 += __shfl_xor_sync(0xffffffffu, s1, 1);
        s1 += __shfl_xor_sync(0xffffffffu, s1, 2);
        float i0 = 1.0f / s0, i1 = 1.0f / s1;
#pragma unroll
        for (int nt = 0; nt < 8; nt++) {
            acc1[mt][nt][0] *= i0; acc1[mt][nt][1] *= i0;
            acc1[mt][nt][2] *= i1; acc1[mt][nt][3] *= i1;
        }
#pragma unroll
        for (int ks = 0; ks < 4; ks++) {
            pa_hi[mt][ks][0] = pack_bf16_hi(acc1[mt][2*ks][0],   acc1[mt][2*ks][1]);
            pa_hi[mt][ks][1] = pack_bf16_hi(acc1[mt][2*ks][2],   acc1[mt][2*ks][3]);
            pa_hi[mt][ks][2] = pack_bf16_hi(acc1[mt][2*ks+1][0], acc1[mt][2*ks+1][1]);
            pa_hi[mt][ks][3] = pack_bf16_hi(acc1[mt][2*ks+1][2], acc1[mt][2*ks+1][3]);
            pa_lo[mt][ks][0] = pack_bf16_lo(acc1[mt][2*ks][0],   acc1[mt][2*ks][1]);
            pa_lo[mt][ks][1] = pack_bf16_lo(acc1[mt][2*ks][2],   acc1[mt][2*ks][3]);
            pa_lo[mt][ks][2] = pack_bf16_lo(acc1[mt][2*ks+1][0], acc1[mt][2*ks+1][1]);
            pa_lo[mt][ks][3] = pack_bf16_lo(acc1[mt][2*ks+1][2], acc1[mt][2*ks+1][3]);
        }
    }

    float acc2[2][8][4] = {};
#pragma unroll
    for (int ks = 0; ks < 4; ks++) {
        int kw = ks * 8;
        uint32_t vb[8][2], vl[8][2];
#pragma unroll
        for (int nt = 0; nt < 8; nt++) {
            int n = nt * 8 + lq;
            vb[nt][0] = sVhi[n * RS + kw + lr];
            vb[nt][1] = sVhi[n * RS + kw + lr + 4];
            vl[nt][0] = sVlo[n * RS + kw + lr];
            vl[nt][1] = sVlo[n * RS + kw + lr + 4];
        }
#pragma unroll
        for (int nt = 0; nt < 8; nt++)
#pragma unroll
            for (int mt = 0; mt < 2; mt++) mma16816(acc2[mt][nt], pa_hi[mt][ks], vb[nt]);
#pragma unroll
        for (int nt = 0; nt < 8; nt++)
#pragma unroll
            for (int mt = 0; mt < 2; mt++) mma16816(acc2[mt][nt], pa_hi[mt][ks], vl[nt]);
#pragma unroll
        for (int nt = 0; nt < 8; nt++)
#pragma unroll
            for (int mt = 0; mt < 2; mt++) mma16816(acc2[mt][nt], pa_lo[mt][ks], vb[nt]);
    }

#pragma unroll
    for (int mt = 0; mt < 2; mt++) {
        int r0 = wid * 32 + mt * 16 + lq;
#pragma unroll
        for (int nt = 0; nt < 8; nt++) {
            int e = nt * 8 + lr * 2;
            size_t off0 = (size_t)(b * 8192 + tok0 + r0) * 256 + h * 64 + e;
            size_t off1 = (size_t)(b * 8192 + tok0 + r0 + 8) * 256 + h * 64 + e;
            *(uint32_t*)(g_o_hi + off0) = pack_bf16_hi(acc2[mt][nt][0], acc2[mt][nt][1]);
            *(uint32_t*)(g_o_lo + off0) = pack_bf16_lo(acc2[mt][nt][0], acc2[mt][nt][1]);
            *(uint32_t*)(g_o_hi + off1) = pack_bf16_hi(acc2[mt][nt][2], acc2[mt][nt][3]);
            *(uint32_t*)(g_o_lo + off1) = pack_bf16_lo(acc2[mt][nt][2], acc2[mt][nt][3]);
        }
    }
}

// ---------------- LayerNorm stats per token ----------------
__global__ void k_lnstat() {
    int tid = threadIdx.x;
    int warp = tid >> 5, lane = tid & 31;
    int t = blockIdx.x * 8 + warp;
    const float4* row = (const float4*)(g_o2 + (size_t)t * 256);
    float s = 0.f, sq = 0.f;
#pragma unroll
    for (int j = 0; j < 2; j++) {
        float4 v = row[j * 32 + lane];
        s  += v.x + v.y + v.z + v.w;
        sq += v.x * v.x + v.y * v.y + v.z * v.z + v.w * v.w;
    }
#pragma unroll
    for (int off = 16; off; off >>= 1) {
        s  += __shfl_xor_sync(0xffffffffu, s, off);
        sq += __shfl_xor_sync(0xffffffffu, sq, off);
    }
    if (lane == 0) {
        float mu = s * (1.0f / 256.0f);
        float var = sq * (1.0f / 256.0f) - mu * mu;
        g_mu[t] = mu;
        g_rs[t] = rsqrtf(var + 1e-5f);
    }
}

// ---------------- LN apply + residual + restore NCDHW ----------------
__global__ void k_lnapply(const float* __restrict__ x, const float* __restrict__ g,
                          const float* __restrict__ be) {
    __shared__ float tl[64 * 65];
    __shared__ float mus[64], rss[64];
    int c0 = blockIdx.x * 64;
    int sp0 = blockIdx.y * 64;
    int b = blockIdx.z;
    int tid = threadIdx.x;
    if (tid < 64) {
        int sp = sp0 + tid;
        int d = sp >> 10, rem = sp & 1023, h = rem >> 5, w = rem & 31;
        int n = h * 256 + w * 8 + d;
        mus[tid] = g_mu[b * 8192 + n];
        rss[tid] = g_rs[b * 8192 + n];
    }
#pragma unroll
    for (int i = 0; i < 16; i++) {
        int idx = i * 256 + tid;
        int s = idx >> 6, c = idx & 63;
        int sp = sp0 + s;
        int d = sp >> 10, rem = sp & 1023, h = rem >> 5, w = rem & 31;
        int n = h * 256 + w * 8 + d;
        tl[s * 65 + c] = g_o2[(size_t)(b * 8192 + n) * 256 + c0 + c];
    }
    __syncthreads();
#pragma unroll
    for (int i = 0; i < 16; i++) {
        int idx = i * 256 + tid;
        int c = idx >> 6, s = idx & 63;
        float gg = g[c0 + c], bb = be[c0 + c];
        float r = (tl[s * 65 + c] - mus[s]) * rss[s] * gg + bb;
        size_t gi = (size_t)(b * 256 + c0 + c) * SPA + sp0 + s;
        g_y[gi] = x[gi] + r;
    }
}

// ---------------- depthwise 3x3x3 SAME conv (register-blocked) ----------------
__global__ void k_dwconv(const float* __restrict__ dwk, const float* __restrict__ dwb) {
    __shared__ float tile[10 * 34 * 34];
    __shared__ float wk[27];
    int bc = blockIdx.x;
    int c = bc & 255;
    int tid = threadIdx.x;
    if (tid < 27) wk[tid] = dwk[c * 27 + tid];
    const float* src = g_y + (size_t)bc * SPA;
    for (int i = tid; i < 11560; i += 256) {
        int dz = i / 1156;
        int rem = i - dz * 1156;
        int hy = rem / 34;
        int wx = rem - hy * 34;
        int d = dz - 1, hh = hy - 1, w = wx - 1;
        float val = 0.f;
        if (d >= 0 && d < 8 && hh >= 0 && hh < 32 && w >= 0 && w < 32)
            val = src[d * 1024 + hh * 32 + w];
        tile[i] = val;
    }
    __syncthreads();
    float bias = dwb[c];
    int r = tid >> 3;
    int wg = (tid & 7) * 4;
#pragma unroll
    for (int d = 0; d < 8; d++) {
        float a0 = 0.f, a1 = 0.f, a2 = 0.f, a3 = 0.f;
#pragma unroll
        for (int kd = 0; kd < 3; kd++) {
#pragma unroll
            for (int kh = 0; kh < 3; kh++) {
                const float* row = &tile[(d + kd) * 1156 + (r + kh) * 34 + wg];
                const float* wrow = &wk[kd * 9 + kh * 3];
                float t0 = row[0], t1 = row[1], t2 = row[2];
                float t3 = row[3], t4 = row[4], t5 = row[5];
                float w0 = wrow[0], w1 = wrow[1], w2 = wrow[2];
                a0 += w0 * t0 + w1 * t1 + w2 * t2;
                a1 += w0 * t1 + w1 * t2 + w2 * t3;
                a2 += w0 * t2 + w1 * t3 + w2 * t4;
                a3 += w0 * t3 + w1 * t4 + w2 * t5;
            }
        }
        size_t o = (size_t)bc * SPA + d * 1024 + r * 32 + wg;
        float v0 = a0 + bias, v1 = a1 + bias, v2 = a2 + bias, v3 = a3 + bias;
        uint2 vh, vl;
        vh.x = pack_bf16_hi(v0, v1); vh.y = pack_bf16_hi(v2, v3);
        vl.x = pack_bf16_lo(v0, v1); vl.y = pack_bf16_lo(v2, v3);
        *(uint2*)(g_dw_hi + o) = vh;
        *(uint2*)(g_dw_lo + o) = vl;
    }
}

// ---------------- pointwise conv on HMMA (ldmatrix frags) + final residual ----------------
__global__ void __launch_bounds__(256, 2) k_pwfin(const float* __restrict__ pwb,
                                                  float* __restrict__ out) {
    extern __shared__ __align__(16) uint32_t sm[];
    uint32_t sbase = smem_u32(sm);
    uint32_t* sAhi = sm;
    uint32_t* sAlo = sAhi + TILE_W;
    uint32_t* sBhi = sAlo + TILE_W;
    uint32_t* sBlo = sBhi + TILE_W;

    int tid = threadIdx.x;
    int wid = tid >> 5, lane = tid & 31;
    int wr = wid >> 2, wc = wid & 3;
    int sp0 = blockIdx.x * 128;
    int co0 = blockIdx.y * 128;
    int b = blockIdx.z;
    int lq = lane >> 2, lr = lane & 3;
    int lt = lane >> 3, lrr = lane & 7;

    float acc[4][4][4] = {};

    for (int ci0 = 0; ci0 < 256; ci0 += 64) {
#pragma unroll
        for (int i = 0; i < 4; i++) {
            int idx = tid + i * 256;
            int r = idx >> 3, gq = idx & 7;
            *(uint4*)&sAhi[r * RS + gq * 4] =
                *(const uint4*)&g_pwk_hi[(co0 + r) * 256 + ci0 + gq * 8];
            *(uint4*)&sAlo[r * RS + gq * 4] =
                *(const uint4*)&g_pwk_lo[(co0 + r) * 256 + ci0 + gq * 8];
        }
#pragma unroll
        for (int jl = 0; jl < 4; jl++) {
            int j = jl * 8 + wid;
            size_t rbase = (size_t)(b * 256 + ci0 + 2 * j) * SPA + sp0;
#pragma unroll
            for (int sh = 0; sh < 2; sh++) {
                int slp = (sh * 32 + lane) * 2;
                uint32_t u0 = *(const uint32_t*)(g_dw_hi + rbase + slp);
                uint32_t u1 = *(const uint32_t*)(g_dw_hi + rbase + SPA + slp);
                sBhi[slp * RS + j]       = __byte_perm(u0, u1, 0x5410);
                sBhi[(slp + 1) * RS + j] = __byte_perm(u0, u1, 0x7632);
                u0 = *(const uint32_t*)(g_dw_lo + rbase + slp);
                u1 = *(const uint32_t*)(g_dw_lo + rbase + SPA + slp);
                sBlo[slp * RS + j]       = __byte_perm(u0, u1, 0x5410);
                sBlo[(slp + 1) * RS + j] = __byte_perm(u0, u1, 0x7632);
            }
        }
        __syncthreads();
        uint32_t aHiB = sbase;
        uint32_t aLoB = sbase + TILE_W * 4;
        uint32_t bHiB = sbase + 2 * TILE_W * 4;
        uint32_t bLoB = sbase + 3 * TILE_W * 4;
#pragma unroll
        for (int ks = 0; ks < 4; ks++) {
            int kw = ks * 8;
            uint32_t bh[4][2], bl[4][2];
#pragma unroll
            for (int p = 0; p < 2; p++) {
                int brow = wc * 32 + p * 16 + lrr + ((lt >> 1) << 3);
                int bcol = kw + ((lt & 1) << 2);
                uint32_t boff = (uint32_t)(brow * RS + bcol) * 4;
                uint32_t tmp[4];
                ldsm_x4(tmp, bHiB + boff);
                bh[2 * p][0] = tmp[0]; bh[2 * p][1] = tmp[1];
                bh[2 * p + 1][0] = tmp[2]; bh[2 * p + 1][1] = tmp[3];
                ldsm_x4(tmp, bLoB + boff);
                bl[2 * p][0] = tmp[0]; bl[2 * p][1] = tmp[1];
                bl[2 * p + 1][0] = tmp[2]; bl[2 * p + 1][1] = tmp[3];
            }
#pragma unroll
            for (int mt = 0; mt < 4; mt++) {
                int arow = wr * 64 + mt * 16 + lrr + ((lt & 1) << 3);
                int acol = kw + ((lt >> 1) << 2);
                uint32_t aoff = (uint32_t)(arow * RS + acol) * 4;
                uint32_t ah[4], al[4];
                ldsm_x4(ah, aHiB + aoff);
                ldsm_x4(al, aLoB + aoff);
#pragma unroll
                for (int nt = 0; nt < 4; nt++) mma16816(acc[mt][nt], ah, bh[nt]);
#pragma unroll
                for (int nt = 0; nt < 4; nt++) mma16816(acc[mt][nt], ah, bl[nt]);
#pragma unroll
                for (int nt = 0; nt < 4; nt++) mma16816(acc[mt][nt], al, bh[nt]);
            }
        }
        __syncthreads();
    }
#pragma unroll
    for (int mt = 0; mt < 4; mt++) {
        int r = co0 + wr * 64 + mt * 16 + lq;
        float bb0 = pwb[r], bb1 = pwb[r + 8];
#pragma unroll
        for (int nt = 0; nt < 4; nt++) {
            int c = sp0 + wc * 32 + nt * 8 + lr * 2;
            size_t i0 = (size_t)(b * 256 + r) * SPA + c;
            size_t i1 = (size_t)(b * 256 + r + 8) * SPA + c;
            float2 y0 = *(const float2*)&g_y[i0];
            float2 y1 = *(const float2*)&g_y[i1];
            float2 v0, v1;
            v0.x = acc[mt][nt][0] + bb0 + y0.x;
            v0.y = acc[mt][nt][1] + bb0 + y0.y;
            v1.x = acc[mt][nt][2] + bb1 + y1.x;
            v1.y = acc[mt][nt][3] + bb1 + y1.y;
            *(float2*)&out[i0] = v0;
            *(float2*)&out[i1] = v1;
        }
    }
}
#define SMEM_PW (4 * TILE_W * 4)

// ---------------- launch ----------------
extern "C" void kernel_launch(void* const* d_in, const int* in_sizes, int n_in,
                              void* d_out, int out_size) {
    (void)in_sizes; (void)n_in; (void)out_size;
    const float* x    = (const float*)d_in[0];
    const float* wqkv = (const float*)d_in[1];
    const float* wseq = (const float*)d_in[2];
    const float* bseq = (const float*)d_in[3];
    const float* temp = (const float*)d_in[4];
    const float* wout = (const float*)d_in[5];
    const float* bout = (const float*)d_in[6];
    const float* lng  = (const float*)d_in[7];
    const float* lnb  = (const float*)d_in[8];
    const float* dwk  = (const float*)d_in[9];
    const float* dwb  = (const float*)d_in[10];
    const float* pwk  = (const float*)d_in[11];
    const float* pwb  = (const float*)d_in[12];
    float* out = (float*)d_out;

    float *qkv, *o2;
    __nv_bfloat16 *t_hi, *t_lo, *o_hi, *o_lo;
    __nv_bfloat16 *wqkvT_hi, *wqkvT_lo, *woutT_hi, *woutT_lo, *pwk_hi, *pwk_lo;
    __nv_bfloat16 *wsT_hi, *wsT_lo;
    cudaGetSymbolAddress((void**)&qkv, g_qkv);
    cudaGetSymbolAddress((void**)&o2,  g_o2);
    cudaGetSymbolAddress((void**)&t_hi, g_t_hi);
    cudaGetSymbolAddress((void**)&t_lo, g_t_lo);
    cudaGetSymbolAddress((void**)&o_hi, g_o_hi);
    cudaGetSymbolAddress((void**)&o_lo, g_o_lo);
    cudaGetSymbolAddress((void**)&wqkvT_hi, g_wqkvT_hi);
    cudaGetSymbolAddress((void**)&wqkvT_lo, g_wqkvT_lo);
    cudaGetSymbolAddress((void**)&woutT_hi, g_woutT_hi);
    cudaGetSymbolAddress((void**)&woutT_lo, g_woutT_lo);
    cudaGetSymbolAddress((void**)&pwk_hi, g_pwk_hi);
    cudaGetSymbolAddress((void**)&pwk_lo, g_pwk_lo);
    cudaGetSymbolAddress((void**)&wsT_hi, g_wsT_hi);
    cudaGetSymbolAddress((void**)&wsT_lo, g_wsT_lo);

    cudaFuncSetAttribute(k_mma, cudaFuncAttributeMaxDynamicSharedMemorySize, SMEM_MMA);
    cudaFuncSetAttribute(k_pwfin, cudaFuncAttributeMaxDynamicSharedMemorySize, SMEM_PW);
    cudaFuncSetAttribute(k_kvproj, cudaFuncAttributeMaxDynamicSharedMemorySize, SMEM_KV);
    cudaFuncSetAttribute(k_attn, cudaFuncAttributeMaxDynamicSharedMemorySize, SMEM_AT);

    k_transpose<<<dim3(4, 128, 4), 256>>>(x);
    k_wtprep_all<<<192, 256>>>(wqkv, wout, wseq);
    k_wprep_nt<<<256, 256>>>(pwk, pwk_hi, pwk_lo, 256 * 256);
    k_mma<<<dim3(6, 256), 256, SMEM_MMA>>>(t_hi, t_lo, wqkvT_hi, wqkvT_lo, nullptr, qkv, 256, 768);
    k_cnpart<<<dim3(64, 4), 256>>>(qkv);
    k_cnfin<<<8, 256>>>();
    k_kvproj<<<dim3(16, 16, 2), 128, SMEM_KV>>>(qkv, wsT_hi, wsT_lo);
    k_kvred<<<512, 256>>>(bseq);
    k_attn<<<dim3(64, 4, 4), 128, SMEM_AT>>>(qkv, temp);
    k_mma<<<dim3(2, 256), 256, SMEM_MMA>>>(o_hi, o_lo, woutT_hi, woutT_lo, bout, o2, 256, 256);
    k_lnstat<<<4096, 256>>>();
    k_lnapply<<<dim3(4, 128, 4), 256>>>(x, lng, lnb);
    k_dwconv<<<1024, 256>>>(dwk, dwb);
    k_pwfin<<<dim3(64, 2, 4), 256, SMEM_PW>>>(pwb, out);
}

// round 16
// speedup vs baseline: 2.4248x; 1.0434x over previous
#include <cuda_runtime.h>
#include <cuda_bf16.h>
#include <math.h>
#include <stdint.h>

// Problem constants
#define BQ   4
#define CC   256
#define NHEAD 4
#define PP   64
#define NN   8192
#define SPA  8192

// ---------------- scratch (device globals) ----------------
__device__ __align__(128) __nv_bfloat16 g_t_hi[(size_t)BQ * NN * CC];
__device__ __align__(128) __nv_bfloat16 g_t_lo[(size_t)BQ * NN * CC];
__device__ float g_qkv [(size_t)BQ * NN * 3 * CC];
__device__ float g_cnsum[BQ * 512];       // fused col sumsq (atomic)
__device__ float g_rnorm [BQ * 512];
__device__ float g_lnsum[BQ * NN];        // fused LN row sum (atomic)
__device__ float g_lnsq [BQ * NN];        // fused LN row sumsq (atomic)
__device__ float g_kvpart[2 * 16 * 16 * 4096];
__device__ __align__(128) __nv_bfloat16 g_kpT_hi[16 * 4096];
__device__ __align__(128) __nv_bfloat16 g_kpT_lo[16 * 4096];
__device__ __align__(128) __nv_bfloat16 g_vp_hi [16 * 4096];
__device__ __align__(128) __nv_bfloat16 g_vp_lo [16 * 4096];
__device__ __align__(128) __nv_bfloat16 g_o_hi[(size_t)BQ * NN * CC];
__device__ __align__(128) __nv_bfloat16 g_o_lo[(size_t)BQ * NN * CC];
__device__ float g_o2  [(size_t)BQ * NN * CC];
__device__ float g_mu  [BQ * NN];
__device__ float g_rs  [BQ * NN];
__device__ float g_y   [(size_t)BQ * CC * SPA];
__device__ __align__(128) __nv_bfloat16 g_dw_hi[(size_t)BQ * CC * SPA];
__device__ __align__(128) __nv_bfloat16 g_dw_lo[(size_t)BQ * CC * SPA];
__device__ __align__(128) __nv_bfloat16 g_wqkvT_hi[768 * 256];
__device__ __align__(128) __nv_bfloat16 g_wqkvT_lo[768 * 256];
__device__ __align__(128) __nv_bfloat16 g_woutT_hi[256 * 256];
__device__ __align__(128) __nv_bfloat16 g_woutT_lo[256 * 256];
__device__ __align__(128) __nv_bfloat16 g_pwk_hi[256 * 256];
__device__ __align__(128) __nv_bfloat16 g_pwk_lo[256 * 256];
__device__ __align__(128) __nv_bfloat16 g_wsT_hi[64 * 8192];
__device__ __align__(128) __nv_bfloat16 g_wsT_lo[64 * 8192];

// ---------------- helpers ----------------
__device__ __forceinline__ uint32_t pack_bf16_hi(float a, float b) {
    __nv_bfloat16 ha = __float2bfloat16(a);
    __nv_bfloat16 hb = __float2bfloat16(b);
    return ((uint32_t)__bfloat16_as_ushort(hb) << 16) | __bfloat16_as_ushort(ha);
}
__device__ __forceinline__ uint32_t pack_bf16_lo(float a, float b) {
    __nv_bfloat16 ha = __float2bfloat16(a);
    __nv_bfloat16 hb = __float2bfloat16(b);
    __nv_bfloat16 la = __float2bfloat16(a - __bfloat162float(ha));
    __nv_bfloat16 lb = __float2bfloat16(b - __bfloat162float(hb));
    return ((uint32_t)__bfloat16_as_ushort(lb) << 16) | __bfloat16_as_ushort(la);
}

__device__ __forceinline__ void mma16816(float* d, const uint32_t* a, const uint32_t* b) {
    asm volatile(
        "mma.sync.aligned.m16n8k16.row.col.f32.bf16.bf16.f32 "
        "{%0,%1,%2,%3}, {%4,%5,%6,%7}, {%8,%9}, {%0,%1,%2,%3};"
        : "+f"(d[0]), "+f"(d[1]), "+f"(d[2]), "+f"(d[3])
        : "r"(a[0]), "r"(a[1]), "r"(a[2]), "r"(a[3]), "r"(b[0]), "r"(b[1]));
}

__device__ __forceinline__ void ldsm_x4(uint32_t* r, uint32_t addr) {
    asm volatile("ldmatrix.sync.aligned.m8n8.x4.shared.b16 {%0,%1,%2,%3}, [%4];"
        : "=r"(r[0]), "=r"(r[1]), "=r"(r[2]), "=r"(r[3]) : "r"(addr));
}

__device__ __forceinline__ uint32_t smem_u32(const void* p) {
    uint32_t a;
    asm("{ .reg .u64 t; cvta.to.shared.u64 t, %1; cvt.u32.u64 %0, t; }" : "=r"(a) : "l"(p));
    return a;
}
#define CP_ASYNC16(dst, src) \
    asm volatile("cp.async.cg.shared.global [%0], [%1], 16;" :: "r"(dst), "l"(src) : "memory")
#define CP_COMMIT() asm volatile("cp.async.commit_group;" ::: "memory")
#define CP_WAIT1()  asm volatile("cp.async.wait_group 1;" ::: "memory")
#define CP_WAIT0()  asm volatile("cp.async.wait_group 0;" ::: "memory")

#define RS 36
#define TILE_W (128 * RS)
#define RS2 20
#define TW2 (128 * RS2)

// ---------------- K0: transpose x (NCDHW) -> t_hi/lo [B,N,C] bf16 ----------------
__global__ void k_transpose(const float* __restrict__ x) {
    __shared__ float tile[64 * 65];
    int c0 = blockIdx.x * 64;
    int sp0 = blockIdx.y * 64;
    int b = blockIdx.z;
    int tid = threadIdx.x;
#pragma unroll
    for (int i = 0; i < 16; i++) {
        int idx = i * 256 + tid;
        int c = idx >> 6, s = idx & 63;
        tile[c * 65 + s] = x[(size_t)(b * 256 + c0 + c) * SPA + sp0 + s];
    }
    __syncthreads();
#pragma unroll
    for (int i = 0; i < 8; i++) {
        int idx = i * 256 + tid;
        int s = idx >> 5, c2 = idx & 31;
        int c = c2 * 2;
        int sp = sp0 + s;
        int d = sp >> 10, rem = sp & 1023, h = rem >> 5, w = rem & 31;
        int n = h * 256 + w * 8 + d;
        float v0 = tile[c * 65 + s];
        float v1 = tile[(c + 1) * 65 + s];
        size_t gi = (size_t)(b * 8192 + n) * 256 + c0 + c;
        *(uint32_t*)(g_t_hi + gi) = pack_bf16_hi(v0, v1);
        *(uint32_t*)(g_t_lo + gi) = pack_bf16_lo(v0, v1);
    }
}

// ---------------- merged weight prep ----------------
__global__ void k_wtprep_all(const float* __restrict__ wqkv,
                             const float* __restrict__ wout,
                             const float* __restrict__ wseq) {
    __shared__ float sm[64 * 65];
    int bid = blockIdx.x;
    const float* w;
    __nv_bfloat16 *thi, *tlo;
    int K, Nn, gx, gy;
    if (bid < 48) {
        w = wqkv; thi = g_wqkvT_hi; tlo = g_wqkvT_lo;
        K = 256; Nn = 768; gx = bid % 12; gy = bid / 12;
    } else if (bid < 64) {
        int b2 = bid - 48;
        w = wout; thi = g_woutT_hi; tlo = g_woutT_lo;
        K = 256; Nn = 256; gx = b2 & 3; gy = b2 >> 2;
    } else {
        int b3 = bid - 64;
        w = wseq; thi = g_wsT_hi; tlo = g_wsT_lo;
        K = 8192; Nn = 64; gx = 0; gy = b3;
    }
    int n0 = gx * 64;
    int k0 = gy * 64;
    int tid = threadIdx.x;
#pragma unroll
    for (int i = 0; i < 16; i++) {
        int idx = i * 256 + tid;
        int r = idx >> 6, c = idx & 63;
        sm[r * 65 + c] = w[(size_t)(k0 + r) * Nn + n0 + c];
    }
    __syncthreads();
#pragma unroll
    for (int i = 0; i < 16; i++) {
        int idx = i * 256 + tid;
        int r = idx >> 6, c = idx & 63;
        float a = sm[c * 65 + r];
        __nv_bfloat16 h = __float2bfloat16(a);
        size_t gi = (size_t)(n0 + r) * K + k0 + c;
        thi[gi] = h;
        tlo[gi] = __float2bfloat16(a - __bfloat162float(h));
    }
}
__global__ void k_wprep_nt(const float* __restrict__ w, __nv_bfloat16* __restrict__ thi,
                           __nv_bfloat16* __restrict__ tlo, int total) {
    int idx = blockIdx.x * 256 + threadIdx.x;
    if (idx >= total) return;
    float a = w[idx];
    __nv_bfloat16 h = __float2bfloat16(a);
    thi[idx] = h;
    tlo[idx] = __float2bfloat16(a - __bfloat162float(h));
}

// ---------------- HMMA bf16-split GEMM (ldmatrix; fused reduction epilogues) ----------------
// mode 0: plain; 1: col sumsq -> st1[b*512+col] for cols<512; 2: row sum/sumsq -> st1/st2[row]
__global__ void __launch_bounds__(256, 2) k_mma(const __nv_bfloat16* __restrict__ Ahi,
                                                const __nv_bfloat16* __restrict__ Alo,
                                                const __nv_bfloat16* __restrict__ Bhi,
                                                const __nv_bfloat16* __restrict__ Blo,
                                                const float* __restrict__ bias,
                                                float* __restrict__ C, int K, int Ntot,
                                                float* __restrict__ st1,
                                                float* __restrict__ st2, int mode) {
    extern __shared__ __align__(16) uint32_t sm[];
    uint32_t sbase = smem_u32(sm);

    int tid = threadIdx.x;
    int wid = tid >> 5, lane = tid & 31;
    int wr = wid >> 2, wc = wid & 3;
    int row0 = blockIdx.y * 128;
    int col0 = blockIdx.x * 128;
    int lq = lane >> 2, lr = lane & 3;
    int lt = lane >> 3, lrr = lane & 7;

    float acc[4][4][4] = {};
    int nch = K >> 5;

#define PREFETCH(CH, STG) do {                                                     \
        int _k0 = (CH) << 5;                                                       \
        uint32_t _so = sbase + (STG) * 4 * TW2 * 4;                                \
        _Pragma("unroll")                                                          \
        for (int _i = 0; _i < 2; _i++) {                                           \
            int _idx = tid + _i * 256;                                             \
            int _r = _idx >> 2, _g = _idx & 3;                                     \
            uint32_t _d = _so + (_r * RS2 + _g * 4) * 4;                           \
            const __nv_bfloat16* _s = Ahi + (size_t)(row0 + _r) * K + _k0 + _g * 8;\
            CP_ASYNC16(_d, _s);                                                    \
            _d += TW2 * 4;                                                         \
            _s = Alo + (size_t)(row0 + _r) * K + _k0 + _g * 8;                     \
            CP_ASYNC16(_d, _s);                                                    \
            _d += TW2 * 4;                                                         \
            _s = Bhi + (size_t)(col0 + _r) * K + _k0 + _g * 8;                     \
            CP_ASYNC16(_d, _s);                                                    \
            _d += TW2 * 4;                                                         \
            _s = Blo + (size_t)(col0 + _r) * K + _k0 + _g * 8;                     \
            CP_ASYNC16(_d, _s);                                                    \
        }                                                                          \
    } while (0)

    PREFETCH(0, 0);
    CP_COMMIT();

    for (int ch = 0; ch < nch; ch++) {
        if (ch + 1 < nch) {
            PREFETCH(ch + 1, (ch + 1) & 1);
            CP_COMMIT();
            CP_WAIT1();
        } else {
            CP_WAIT0();
        }
        __syncthreads();
        uint32_t stg = sbase + (ch & 1) * 4 * TW2 * 4;
        uint32_t aHiB = stg;
        uint32_t aLoB = stg + TW2 * 4;
        uint32_t bHiB = stg + 2 * TW2 * 4;
        uint32_t bLoB = stg + 3 * TW2 * 4;
#pragma unroll
        for (int ks = 0; ks < 2; ks++) {
            int kw = ks * 8;
            uint32_t bh[4][2], bl[4][2];
#pragma unroll
            for (int p = 0; p < 2; p++) {
                int brow = wc * 32 + p * 16 + lrr + ((lt >> 1) << 3);
                int bcol = kw + ((lt & 1) << 2);
                uint32_t boff = (uint32_t)(brow * RS2 + bcol) * 4;
                uint32_t tmp[4];
                ldsm_x4(tmp, bHiB + boff);
                bh[2 * p][0] = tmp[0]; bh[2 * p][1] = tmp[1];
                bh[2 * p + 1][0] = tmp[2]; bh[2 * p + 1][1] = tmp[3];
                ldsm_x4(tmp, bLoB + boff);
                bl[2 * p][0] = tmp[0]; bl[2 * p][1] = tmp[1];
                bl[2 * p + 1][0] = tmp[2]; bl[2 * p + 1][1] = tmp[3];
            }
#pragma unroll
            for (int mt = 0; mt < 4; mt++) {
                int arow = wr * 64 + mt * 16 + lrr + ((lt & 1) << 3);
                int acol = kw + ((lt >> 1) << 2);
                uint32_t aoff = (uint32_t)(arow * RS2 + acol) * 4;
                uint32_t ah[4], al[4];
                ldsm_x4(ah, aHiB + aoff);
                ldsm_x4(al, aLoB + aoff);
#pragma unroll
                for (int nt = 0; nt < 4; nt++) mma16816(acc[mt][nt], ah, bh[nt]);
#pragma unroll
                for (int nt = 0; nt < 4; nt++) mma16816(acc[mt][nt], ah, bl[nt]);
#pragma unroll
                for (int nt = 0; nt < 4; nt++) mma16816(acc[mt][nt], al, bh[nt]);
            }
        }
        __syncthreads();
    }
#undef PREFETCH
#pragma unroll
    for (int mt = 0; mt < 4; mt++) {
        int r = row0 + wr * 64 + mt * 16 + lq;
#pragma unroll
        for (int nt = 0; nt < 4; nt++) {
            int c = col0 + wc * 32 + nt * 8 + lr * 2;
            float b0 = bias ? bias[c] : 0.0f;
            float b1 = bias ? bias[c + 1] : 0.0f;
            float2 v0, v1;
            v0.x = acc[mt][nt][0] + b0;
            v0.y = acc[mt][nt][1] + b1;
            v1.x = acc[mt][nt][2] + b0;
            v1.y = acc[mt][nt][3] + b1;
            *(float2*)&C[(size_t)r * Ntot + c] = v0;
            *(float2*)&C[(size_t)(r + 8) * Ntot + c] = v1;
        }
    }
    // fused reductions
    if (mode == 1) {
        if (col0 < 512) {
            int bq = row0 >> 13;
#pragma unroll
            for (int nt = 0; nt < 4; nt++) {
                float s0 = 0.f, s1 = 0.f;
#pragma unroll
                for (int mt = 0; mt < 4; mt++) {
                    s0 += acc[mt][nt][0] * acc[mt][nt][0] + acc[mt][nt][2] * acc[mt][nt][2];
                    s1 += acc[mt][nt][1] * acc[mt][nt][1] + acc[mt][nt][3] * acc[mt][nt][3];
                }
#pragma unroll
                for (int off = 4; off <= 16; off <<= 1) {
                    s0 += __shfl_xor_sync(0xffffffffu, s0, off);
                    s1 += __shfl_xor_sync(0xffffffffu, s1, off);
                }
                if (lq == 0) {
                    int c = col0 + wc * 32 + nt * 8 + lr * 2;
                    atomicAdd(&st1[bq * 512 + c], s0);
                    atomicAdd(&st1[bq * 512 + c + 1], s1);
                }
            }
        }
    } else if (mode == 2) {
#pragma unroll
        for (int mt = 0; mt < 4; mt++) {
            int r = row0 + wr * 64 + mt * 16 + lq;
            float t0 = 0.f, q0 = 0.f, t1 = 0.f, q1 = 0.f;
#pragma unroll
            for (int nt = 0; nt < 4; nt++) {
                int c = col0 + wc * 32 + nt * 8 + lr * 2;
                float b0 = bias[c], b1 = bias[c + 1];
                float a0 = acc[mt][nt][0] + b0, a1 = acc[mt][nt][1] + b1;
                float a2 = acc[mt][nt][2] + b0, a3 = acc[mt][nt][3] + b1;
                t0 += a0 + a1; q0 += a0 * a0 + a1 * a1;
                t1 += a2 + a3; q1 += a2 * a2 + a3 * a3;
            }
#pragma unroll
            for (int off = 1; off <= 2; off <<= 1) {
                t0 += __shfl_xor_sync(0xffffffffu, t0, off);
                q0 += __shfl_xor_sync(0xffffffffu, q0, off);
                t1 += __shfl_xor_sync(0xffffffffu, t1, off);
                q1 += __shfl_xor_sync(0xffffffffu, q1, off);
            }
            if (lr == 0) {
                atomicAdd(&st1[r], t0);
                atomicAdd(&st2[r], q0);
                atomicAdd(&st1[r + 8], t1);
                atomicAdd(&st2[r + 8], q1);
            }
        }
    }
}
#define SMEM_MMA (8 * TW2 * 4)

// ---------------- finalize column norms ----------------
__global__ void k_cnfin() {
    int idx = blockIdx.x * 256 + threadIdx.x;
    float s = g_cnsum[idx];
    g_rnorm[idx] = 1.0f / fmaxf(sqrtf(s), 1e-12f);
}

// ---------------- finalize LN stats ----------------
__global__ void k_lnfin() {
    int t = blockIdx.x * 256 + threadIdx.x;
    float mu = g_lnsum[t] * (1.0f / 256.0f);
    float var = g_lnsq[t] * (1.0f / 256.0f) - mu * mu;
    g_mu[t] = mu;
    g_rs[t] = rsqrtf(var + 1e-5f);
}

// ---------------- kp/vp projections on HMMA ----------------
#define SMEM_KV (64 * 65 * 4 + 4 * 64 * RS * 4)
__global__ void __launch_bounds__(128) k_kvproj(const float* __restrict__ qkv,
                                                const __nv_bfloat16* __restrict__ wsThi,
                                                const __nv_bfloat16* __restrict__ wsTlo) {
    extern __shared__ __align__(16) char smraw[];
    float* sF = (float*)smraw;
    uint32_t* sAhi = (uint32_t*)(smraw + 64 * 65 * 4);
    uint32_t* sAlo = sAhi + 64 * RS;
    uint32_t* sBhi = sAlo + 64 * RS;
    uint32_t* sBlo = sBhi + 64 * RS;

    int slice = blockIdx.x;
    int bh = blockIdx.y;
    int kind = blockIdx.z;
    int b = bh >> 2, h = bh & 3;
    int colbase = (kind == 0 ? 256 : 512) + h * 64;
    int tid = threadIdx.x;
    int wid = tid >> 5, lane = tid & 31;
    int wr = wid >> 1, wc = wid & 1;
    int lq = lane >> 2, lr = lane & 3;
    int wa = lane & 7, wb = lane >> 3;

    float acc[2][4][4] = {};

    int nbeg = slice * 512;
    for (int ch = 0; ch < 8; ch++) {
        int n0 = nbeg + ch * 64;
#pragma unroll
        for (int i = 0; i < 8; i++) {
            int idx = tid + i * 128;
            int r = idx >> 4, c4 = idx & 15;
            float4 v = *(const float4*)&qkv[(size_t)(b * 8192 + n0 + r) * 768 + colbase + c4 * 4];
            float* dst = &sF[r * 65 + c4 * 4];
            dst[0] = v.x; dst[1] = v.y; dst[2] = v.z; dst[3] = v.w;
        }
#pragma unroll
        for (int i = 0; i < 4; i++) {
            int idx = tid + i * 128;
            int r = idx >> 3, q = idx & 7;
            *(uint4*)&sBhi[r * RS + q * 4] = *(const uint4*)&wsThi[(size_t)r * 8192 + n0 + q * 8];
            *(uint4*)&sBlo[r * RS + q * 4] = *(const uint4*)&wsTlo[(size_t)r * 8192 + n0 + q * 8];
        }
        __syncthreads();
#pragma unroll
        for (int ia = 0; ia < 2; ia++) {
            int e = wid * 16 + 8 * ia + wa;
#pragma unroll
            for (int inp = 0; inp < 8; inp++) {
                int np = 4 * inp + wb;
                float v0 = sF[(2 * np) * 65 + e];
                float v1 = sF[(2 * np + 1) * 65 + e];
                sAhi[e * RS + np] = pack_bf16_hi(v0, v1);
                sAlo[e * RS + np] = pack_bf16_lo(v0, v1);
            }
        }
        __syncthreads();
#pragma unroll
        for (int ks = 0; ks < 4; ks++) {
            int kw = ks * 8;
            uint32_t bhf[4][2], blf[4][2];
#pragma unroll
            for (int nt = 0; nt < 4; nt++) {
                int nrow = wc * 32 + nt * 8 + lq;
                bhf[nt][0] = sBhi[nrow * RS + kw + lr];
                bhf[nt][1] = sBhi[nrow * RS + kw + lr + 4];
                blf[nt][0] = sBlo[nrow * RS + kw + lr];
                blf[nt][1] = sBlo[nrow * RS + kw + lr + 4];
            }
#pragma unroll
            for (int mt = 0; mt < 2; mt++) {
                int r = wr * 32 + mt * 16 + lq;
                uint32_t ah[4], al[4];
                ah[0] = sAhi[r * RS + kw + lr];
                ah[1] = sAhi[(r + 8) * RS + kw + lr];
                ah[2] = sAhi[r * RS + kw + lr + 4];
                ah[3] = sAhi[(r + 8) * RS + kw + lr + 4];
                al[0] = sAlo[r * RS + kw + lr];
                al[1] = sAlo[(r + 8) * RS + kw + lr];
                al[2] = sAlo[r * RS + kw + lr + 4];
                al[3] = sAlo[(r + 8) * RS + kw + lr + 4];
#pragma unroll
                for (int nt = 0; nt < 4; nt++) mma16816(acc[mt][nt], ah, bhf[nt]);
#pragma unroll
                for (int nt = 0; nt < 4; nt++) mma16816(acc[mt][nt], ah, blf[nt]);
#pragma unroll
                for (int nt = 0; nt < 4; nt++) mma16816(acc[mt][nt], al, bhf[nt]);
            }
        }
        __syncthreads();
    }
    float* dst = g_kvpart + (size_t)((kind * 16 + bh) * 16 + slice) * 4096;
#pragma unroll
    for (int mt = 0; mt < 2; mt++) {
        int e = wr * 32 + mt * 16 + lq;
#pragma unroll
        for (int nt = 0; nt < 4; nt++) {
            int p = wc * 32 + nt * 8 + lr * 2;
            *(float2*)&dst[e * 64 + p] = make_float2(acc[mt][nt][0], acc[mt][nt][1]);
            *(float2*)&dst[(e + 8) * 64 + p] = make_float2(acc[mt][nt][2], acc[mt][nt][3]);
        }
    }
}

// reduce + bias + fold norms
__global__ void k_kvred(const float* __restrict__ bseq) {
    int idx = blockIdx.x * 256 + threadIdx.x;
    int kb = idx >> 12;
    int ep = idx & 4095;
    float s = 0.f;
#pragma unroll
    for (int sl = 0; sl < 16; sl++) s += g_kvpart[(size_t)(kb * 16 + sl) * 4096 + ep];
    int kind = kb >> 4, bh = kb & 15;
    int b = bh >> 2, h = bh & 3;
    int e = ep >> 6, p = ep & 63;
    if (kind == 0) {
        float v = s * g_rnorm[b * 512 + 256 + h * 64 + e] + bseq[p];
        v *= g_rnorm[b * 512 + h * 64 + e];
        __nv_bfloat16 hi = __float2bfloat16(v);
        g_kpT_hi[bh * 4096 + p * 64 + e] = hi;
        g_kpT_lo[bh * 4096 + p * 64 + e] = __float2bfloat16(v - __bfloat162float(hi));
    } else {
        float v = s + bseq[p];
        __nv_bfloat16 hi = __float2bfloat16(v);
        g_vp_hi[bh * 4096 + ep] = hi;
        g_vp_lo[bh * 4096 + ep] = __float2bfloat16(v - __bfloat162float(hi));
    }
}

// ---------------- fused attention on HMMA ----------------
#define SMEM_AT ((128 * RS * 2 + 64 * RS * 4) * 4)
__global__ void __launch_bounds__(128) k_attn(const float* __restrict__ qkv,
                                              const float* __restrict__ temp) {
    extern __shared__ __align__(16) uint32_t sm[];
    uint32_t* sQhi = sm;
    uint32_t* sQlo = sm + 128 * RS;
    uint32_t* sKhi = sm + 256 * RS;
    uint32_t* sKlo = sKhi + 64 * RS;
    uint32_t* sVhi = sKlo + 64 * RS;
    uint32_t* sVlo = sVhi + 64 * RS;

    int tid = threadIdx.x;
    int wid = tid >> 5, lane = tid & 31;
    int lq = lane >> 2, lr = lane & 3;
    int h = blockIdx.y, b = blockIdx.z;
    int bh = b * 4 + h;
    int tok0 = blockIdx.x * 128;

    {
        const uint4* skh = (const uint4*)(g_kpT_hi + (size_t)bh * 4096);
        const uint4* skl = (const uint4*)(g_kpT_lo + (size_t)bh * 4096);
        const uint4* svh = (const uint4*)(g_vp_hi + (size_t)bh * 4096);
        const uint4* svl = (const uint4*)(g_vp_lo + (size_t)bh * 4096);
#pragma unroll
        for (int i = 0; i < 4; i++) {
            int idx = tid + i * 128;
            int r = idx >> 3, q = idx & 7;
            *(uint4*)&sKhi[r * RS + q * 4] = skh[idx];
            *(uint4*)&sKlo[r * RS + q * 4] = skl[idx];
            *(uint4*)&sVhi[r * RS + q * 4] = svh[idx];
            *(uint4*)&sVlo[r * RS + q * 4] = svl[idx];
        }
    }
#pragma unroll
    for (int i = 0; i < 16; i++) {
        int idx = tid + i * 128;
        int r = idx >> 4, c4 = idx & 15;
        float4 v = *(const float4*)&qkv[(size_t)(b * 8192 + tok0 + r) * 768 + h * 64 + c4 * 4];
        sQhi[r * RS + c4 * 2]     = pack_bf16_hi(v.x, v.y);
        sQhi[r * RS + c4 * 2 + 1] = pack_bf16_hi(v.z, v.w);
        sQlo[r * RS + c4 * 2]     = pack_bf16_lo(v.x, v.y);
        sQlo[r * RS + c4 * 2 + 1] = pack_bf16_lo(v.z, v.w);
    }
    __syncthreads();
    float tv = temp[h];

    float acc1[2][8][4] = {};
#pragma unroll
    for (int ks = 0; ks < 4; ks++) {
        int kw = ks * 8;
        uint32_t qh[2][4], ql2[2][4];
#pragma unroll
        for (int mt = 0; mt < 2; mt++) {
            int r = wid * 32 + mt * 16 + lq;
            qh[mt][0]  = sQhi[r * RS + kw + lr];
            qh[mt][1]  = sQhi[(r + 8) * RS + kw + lr];
            qh[mt][2]  = sQhi[r * RS + kw + lr + 4];
            qh[mt][3]  = sQhi[(r + 8) * RS + kw + lr + 4];
            ql2[mt][0] = sQlo[r * RS + kw + lr];
            ql2[mt][1] = sQlo[(r + 8) * RS + kw + lr];
            ql2[mt][2] = sQlo[r * RS + kw + lr + 4];
            ql2[mt][3] = sQlo[(r + 8) * RS + kw + lr + 4];
        }
        uint32_t kb[8][2], kl[8][2];
#pragma unroll
        for (int nt = 0; nt < 8; nt++) {
            int n = nt * 8 + lq;
            kb[nt][0] = sKhi[n * RS + kw + lr];
            kb[nt][1] = sKhi[n * RS + kw + lr + 4];
            kl[nt][0] = sKlo[n * RS + kw + lr];
            kl[nt][1] = sKlo[n * RS + kw + lr + 4];
        }
#pragma unroll
        for (int nt = 0; nt < 8; nt++)
#pragma unroll
            for (int mt = 0; mt < 2; mt++) mma16816(acc1[mt][nt], qh[mt], kb[nt]);
#pragma unroll
        for (int nt = 0; nt < 8; nt++)
#pragma unroll
            for (int mt = 0; mt < 2; mt++) mma16816(acc1[mt][nt], qh[mt], kl[nt]);
#pragma unroll
        for (int nt = 0; nt < 8; nt++)
#pragma unroll
            for (int mt = 0; mt < 2; mt++) mma16816(acc1[mt][nt], ql2[mt], kb[nt]);
    }

    uint32_t pa_hi[2][4][4], pa_lo[2][4][4];
#pragma unroll
    for (int mt = 0; mt < 2; mt++) {
#pragma unroll
        for (int nt = 0; nt < 8; nt++)
#pragma unroll
            for (int j = 0; j < 4; j++) acc1[mt][nt][j] *= tv;
        float m0 = -1e30f, m1 = -1e30f;
#pragma unroll
        for (int nt = 0; nt < 8; nt++) {
            m0 = fmaxf(m0, fmaxf(acc1[mt][nt][0], acc1[mt][nt][1]));
            m1 = fmaxf(m1, fmaxf(acc1[mt][nt][2], acc1[mt][nt][3]));
        }
        m0 = fmaxf(m0, __shfl_xor_sync(0xffffffffu, m0, 1));
        m0 = fmaxf(m0, __shfl_xor_sync(0xffffffffu, m0, 2));
        m1 = fmaxf(m1, __shfl_xor_sync(0xffffffffu, m1, 1));
        m1 = fmaxf(m1, __shfl_xor_sync(0xffffffffu, m1, 2));
        float s0 = 0.f, s1 = 0.f;
#pragma unroll
        for (int nt = 0; nt < 8; nt++) {
            acc1[mt][nt][0] = __expf(acc1[mt][nt][0] - m0);
            acc1[mt][nt][1] = __expf(acc1[mt][nt][1] - m0);
            acc1[mt][nt][2] = __expf(acc1[mt][nt][2] - m1);
            acc1[mt][nt][3] = __expf(acc1[mt][nt][3] - m1);
            s0 += acc1[mt][nt][0] + acc1[mt][nt][1];
            s1 += acc1[mt][nt][2] + acc1[mt][nt][3];
        }
        s0 += __shfl_xor_sync(0xffffffffu, s0, 1);
        s0 += __shfl_xor_sync(0xffffffffu, s0, 2);
        s1 += __shfl_xor_sync(0xffffffffu, s1, 1);
        s1 += __shfl_xor_sync(0xffffffffu, s1, 2);
        float i0 = 1.0f / s0, i1 = 1.0f / s1;
#pragma unroll
        for (int nt = 0; nt < 8; nt++) {
            acc1[mt][nt][0] *= i0; acc1[mt][nt][1] *= i0;
            acc1[mt][nt][2] *= i1; acc1[mt][nt][3] *= i1;
        }
#pragma unroll
        for (int ks = 0; ks < 4; ks++) {
            pa_hi[mt][ks][0] = pack_bf16_hi(acc1[mt][2*ks][0],   acc1[mt][2*ks][1]);
            pa_hi[mt][ks][1] = pack_bf16_hi(acc1[mt][2*ks][2],   acc1[mt][2*ks][3]);
            pa_hi[mt][ks][2] = pack_bf16_hi(acc1[mt][2*ks+1][0], acc1[mt][2*ks+1][1]);
            pa_hi[mt][ks][3] = pack_bf16_hi(acc1[mt][2*ks+1][2], acc1[mt][2*ks+1][3]);
            pa_lo[mt][ks][0] = pack_bf16_lo(acc1[mt][2*ks][0],   acc1[mt][2*ks][1]);
            pa_lo[mt][ks][1] = pack_bf16_lo(acc1[mt][2*ks][2],   acc1[mt][2*ks][3]);
            pa_lo[mt][ks][2] = pack_bf16_lo(acc1[mt][2*ks+1][0], acc1[mt][2*ks+1][1]);
            pa_lo[mt][ks][3] = pack_bf16_lo(acc1[mt][2*ks+1][2], acc1[mt][2*ks+1][3]);
        }
    }

    float acc2[2][8][4] = {};
#pragma unroll
    for (int ks = 0; ks < 4; ks++) {
        int kw = ks * 8;
        uint32_t vb[8][2], vl[8][2];
#pragma unroll
        for (int nt = 0; nt < 8; nt++) {
            int n = nt * 8 + lq;
            vb[nt][0] = sVhi[n * RS + kw + lr];
            vb[nt][1] = sVhi[n * RS + kw + lr + 4];
            vl[nt][0] = sVlo[n * RS + kw + lr];
            vl[nt][1] = sVlo[n * RS + kw + lr + 4];
        }
#pragma unroll
        for (int nt = 0; nt < 8; nt++)
#pragma unroll
            for (int mt = 0; mt < 2; mt++) mma16816(acc2[mt][nt], pa_hi[mt][ks], vb[nt]);
#pragma unroll
        for (int nt = 0; nt < 8; nt++)
#pragma unroll
            for (int mt = 0; mt < 2; mt++) mma16816(acc2[mt][nt], pa_hi[mt][ks], vl[nt]);
#pragma unroll
        for (int nt = 0; nt < 8; nt++)
#pragma unroll
            for (int mt = 0; mt < 2; mt++) mma16816(acc2[mt][nt], pa_lo[mt][ks], vb[nt]);
    }

#pragma unroll
    for (int mt = 0; mt < 2; mt++) {
        int r0 = wid * 32 + mt * 16 + lq;
#pragma unroll
        for (int nt = 0; nt < 8; nt++) {
            int e = nt * 8 + lr * 2;
            size_t off0 = (size_t)(b * 8192 + tok0 + r0) * 256 + h * 64 + e;
            size_t off1 = (size_t)(b * 8192 + tok0 + r0 + 8) * 256 + h * 64 + e;
            *(uint32_t*)(g_o_hi + off0) = pack_bf16_hi(acc2[mt][nt][0], acc2[mt][nt][1]);
            *(uint32_t*)(g_o_lo + off0) = pack_bf16_lo(acc2[mt][nt][0], acc2[mt][nt][1]);
            *(uint32_t*)(g_o_hi + off1) = pack_bf16_hi(acc2[mt][nt][2], acc2[mt][nt][3]);
            *(uint32_t*)(g_o_lo + off1) = pack_bf16_lo(acc2[mt][nt][2], acc2[mt][nt][3]);
        }
    }
}

// ---------------- LN apply + residual + restore NCDHW ----------------
__global__ void k_lnapply(const float* __restrict__ x, const float* __restrict__ g,
                          const float* __restrict__ be) {
    __shared__ float tl[64 * 65];
    __shared__ float mus[64], rss[64];
    int c0 = blockIdx.x * 64;
    int sp0 = blockIdx.y * 64;
    int b = blockIdx.z;
    int tid = threadIdx.x;
    if (tid < 64) {
        int sp = sp0 + tid;
        int d = sp >> 10, rem = sp & 1023, h = rem >> 5, w = rem & 31;
        int n = h * 256 + w * 8 + d;
        mus[tid] = g_mu[b * 8192 + n];
        rss[tid] = g_rs[b * 8192 + n];
    }
#pragma unroll
    for (int i = 0; i < 16; i++) {
        int idx = i * 256 + tid;
        int s = idx >> 6, c = idx & 63;
        int sp = sp0 + s;
        int d = sp >> 10, rem = sp & 1023, h = rem >> 5, w = rem & 31;
        int n = h * 256 + w * 8 + d;
        tl[s * 65 + c] = g_o2[(size_t)(b * 8192 + n) * 256 + c0 + c];
    }
    __syncthreads();
#pragma unroll
    for (int i = 0; i < 16; i++) {
        int idx = i * 256 + tid;
        int c = idx >> 6, s = idx & 63;
        float gg = g[c0 + c], bb = be[c0 + c];
        float r = (tl[s * 65 + c] - mus[s]) * rss[s] * gg + bb;
        size_t gi = (size_t)(b * 256 + c0 + c) * SPA + sp0 + s;
        g_y[gi] = x[gi] + r;
    }
}

// ---------------- depthwise 3x3x3 SAME conv (register-blocked) ----------------
__global__ void k_dwconv(const float* __restrict__ dwk, const float* __restrict__ dwb) {
    __shared__ float tile[10 * 34 * 34];
    __shared__ float wk[27];
    int bc = blockIdx.x;
    int c = bc & 255;
    int tid = threadIdx.x;
    if (tid < 27) wk[tid] = dwk[c * 27 + tid];
    const float* src = g_y + (size_t)bc * SPA;
    for (int i = tid; i < 11560; i += 256) {
        int dz = i / 1156;
        int rem = i - dz * 1156;
        int hy = rem / 34;
        int wx = rem - hy * 34;
        int d = dz - 1, hh = hy - 1, w = wx - 1;
        float val = 0.f;
        if (d >= 0 && d < 8 && hh >= 0 && hh < 32 && w >= 0 && w < 32)
            val = src[d * 1024 + hh * 32 + w];
        tile[i] = val;
    }
    __syncthreads();
    float bias = dwb[c];
    int r = tid >> 3;
    int wg = (tid & 7) * 4;
#pragma unroll
    for (int d = 0; d < 8; d++) {
        float a0 = 0.f, a1 = 0.f, a2 = 0.f, a3 = 0.f;
#pragma unroll
        for (int kd = 0; kd < 3; kd++) {
#pragma unroll
            for (int kh = 0; kh < 3; kh++) {
                const float* row = &tile[(d + kd) * 1156 + (r + kh) * 34 + wg];
                const float* wrow = &wk[kd * 9 + kh * 3];
                float t0 = row[0], t1 = row[1], t2 = row[2];
                float t3 = row[3], t4 = row[4], t5 = row[5];
                float w0 = wrow[0], w1 = wrow[1], w2 = wrow[2];
                a0 += w0 * t0 + w1 * t1 + w2 * t2;
                a1 += w0 * t1 + w1 * t2 + w2 * t3;
                a2 += w0 * t2 + w1 * t3 + w2 * t4;
                a3 += w0 * t3 + w1 * t4 + w2 * t5;
            }
        }
        size_t o = (size_t)bc * SPA + d * 1024 + r * 32 + wg;
        float v0 = a0 + bias, v1 = a1 + bias, v2 = a2 + bias, v3 = a3 + bias;
        uint2 vh, vl;
        vh.x = pack_bf16_hi(v0, v1); vh.y = pack_bf16_hi(v2, v3);
        vl.x = pack_bf16_lo(v0, v1); vl.y = pack_bf16_lo(v2, v3);
        *(uint2*)(g_dw_hi + o) = vh;
        *(uint2*)(g_dw_lo + o) = vl;
    }
}

// ---------------- pointwise conv on HMMA (ldmatrix frags) + final residual ----------------
__global__ void __launch_bounds__(256, 2) k_pwfin(const float* __restrict__ pwb,
                                                  float* __restrict__ out) {
    extern __shared__ __align__(16) uint32_t sm[];
    uint32_t sbase = smem_u32(sm);
    uint32_t* sAhi = sm;
    uint32_t* sAlo = sAhi + TILE_W;
    uint32_t* sBhi = sAlo + TILE_W;
    uint32_t* sBlo = sBhi + TILE_W;

    int tid = threadIdx.x;
    int wid = tid >> 5, lane = tid & 31;
    int wr = wid >> 2, wc = wid & 3;
    int sp0 = blockIdx.x * 128;
    int co0 = blockIdx.y * 128;
    int b = blockIdx.z;
    int lq = lane >> 2, lr = lane & 3;
    int lt = lane >> 3, lrr = lane & 7;

    float acc[4][4][4] = {};

    for (int ci0 = 0; ci0 < 256; ci0 += 64) {
#pragma unroll
        for (int i = 0; i < 4; i++) {
            int idx = tid + i * 256;
            int r = idx >> 3, gq = idx & 7;
            *(uint4*)&sAhi[r * RS + gq * 4] =
                *(const uint4*)&g_pwk_hi[(co0 + r) * 256 + ci0 + gq * 8];
            *(uint4*)&sAlo[r * RS + gq * 4] =
                *(const uint4*)&g_pwk_lo[(co0 + r) * 256 + ci0 + gq * 8];
        }
#pragma unroll
        for (int jl = 0; jl < 4; jl++) {
            int j = jl * 8 + wid;
            size_t rbase = (size_t)(b * 256 + ci0 + 2 * j) * SPA + sp0;
#pragma unroll
            for (int sh = 0; sh < 2; sh++) {
                int slp = (sh * 32 + lane) * 2;
                uint32_t u0 = *(const uint32_t*)(g_dw_hi + rbase + slp);
                uint32_t u1 = *(const uint32_t*)(g_dw_hi + rbase + SPA + slp);
                sBhi[slp * RS + j]       = __byte_perm(u0, u1, 0x5410);
                sBhi[(slp + 1) * RS + j] = __byte_perm(u0, u1, 0x7632);
                u0 = *(const uint32_t*)(g_dw_lo + rbase + slp);
                u1 = *(const uint32_t*)(g_dw_lo + rbase + SPA + slp);
                sBlo[slp * RS + j]       = __byte_perm(u0, u1, 0x5410);
                sBlo[(slp + 1) * RS + j] = __byte_perm(u0, u1, 0x7632);
            }
        }
        __syncthreads();
        uint32_t aHiB = sbase;
        uint32_t aLoB = sbase + TILE_W * 4;
        uint32_t bHiB = sbase + 2 * TILE_W * 4;
        uint32_t bLoB = sbase + 3 * TILE_W * 4;
#pragma unroll
        for (int ks = 0; ks < 4; ks++) {
            int kw = ks * 8;
            uint32_t bh[4][2], bl[4][2];
#pragma unroll
            for (int p = 0; p < 2; p++) {
                int brow = wc * 32 + p * 16 + lrr + ((lt >> 1) << 3);
                int bcol = kw + ((lt & 1) << 2);
                uint32_t boff = (uint32_t)(brow * RS + bcol) * 4;
                uint32_t tmp[4];
                ldsm_x4(tmp, bHiB + boff);
                bh[2 * p][0] = tmp[0]; bh[2 * p][1] = tmp[1];
                bh[2 * p + 1][0] = tmp[2]; bh[2 * p + 1][1] = tmp[3];
                ldsm_x4(tmp, bLoB + boff);
                bl[2 * p][0] = tmp[0]; bl[2 * p][1] = tmp[1];
                bl[2 * p + 1][0] = tmp[2]; bl[2 * p + 1][1] = tmp[3];
            }
#pragma unroll
            for (int mt = 0; mt < 4; mt++) {
                int arow = wr * 64 + mt * 16 + lrr + ((lt & 1) << 3);
                int acol = kw + ((lt >> 1) << 2);
                uint32_t aoff = (uint32_t)(arow * RS + acol) * 4;
                uint32_t ah[4], al[4];
                ldsm_x4(ah, aHiB + aoff);
                ldsm_x4(al, aLoB + aoff);
#pragma unroll
                for (int nt = 0; nt < 4; nt++) mma16816(acc[mt][nt], ah, bh[nt]);
#pragma unroll
                for (int nt = 0; nt < 4; nt++) mma16816(acc[mt][nt], ah, bl[nt]);
#pragma unroll
                for (int nt = 0; nt < 4; nt++) mma16816(acc[mt][nt], al, bh[nt]);
            }
        }
        __syncthreads();
    }
#pragma unroll
    for (int mt = 0; mt < 4; mt++) {
        int r = co0 + wr * 64 + mt * 16 + lq;
        float bb0 = pwb[r], bb1 = pwb[r + 8];
#pragma unroll
        for (int nt = 0; nt < 4; nt++) {
            int c = sp0 + wc * 32 + nt * 8 + lr * 2;
            size_t i0 = (size_t)(b * 256 + r) * SPA + c;
            size_t i1 = (size_t)(b * 256 + r + 8) * SPA + c;
            float2 y0 = *(const float2*)&g_y[i0];
            float2 y1 = *(const float2*)&g_y[i1];
            float2 v0, v1;
            v0.x = acc[mt][nt][0] + bb0 + y0.x;
            v0.y = acc[mt][nt][1] + bb0 + y0.y;
            v1.x = acc[mt][nt][2] + bb1 + y1.x;
            v1.y = acc[mt][nt][3] + bb1 + y1.y;
            *(float2*)&out[i0] = v0;
            *(float2*)&out[i1] = v1;
        }
    }
}
#define SMEM_PW (4 * TILE_W * 4)

// ---------------- launch ----------------
extern "C" void kernel_launch(void* const* d_in, const int* in_sizes, int n_in,
                              void* d_out, int out_size) {
    (void)in_sizes; (void)n_in; (void)out_size;
    const float* x    = (const float*)d_in[0];
    const float* wqkv = (const float*)d_in[1];
    const float* wseq = (const float*)d_in[2];
    const float* bseq = (const float*)d_in[3];
    const float* temp = (const float*)d_in[4];
    const float* wout = (const float*)d_in[5];
    const float* bout = (const float*)d_in[6];
    const float* lng  = (const float*)d_in[7];
    const float* lnb  = (const float*)d_in[8];
    const float* dwk  = (const float*)d_in[9];
    const float* dwb  = (const float*)d_in[10];
    const float* pwk  = (const float*)d_in[11];
    const float* pwb  = (const float*)d_in[12];
    float* out = (float*)d_out;

    float *qkv, *o2, *cnsum, *lnsum, *lnsq;
    __nv_bfloat16 *t_hi, *t_lo, *o_hi, *o_lo;
    __nv_bfloat16 *wqkvT_hi, *wqkvT_lo, *woutT_hi, *woutT_lo, *pwk_hi, *pwk_lo;
    __nv_bfloat16 *wsT_hi, *wsT_lo;
    cudaGetSymbolAddress((void**)&qkv, g_qkv);
    cudaGetSymbolAddress((void**)&o2,  g_o2);
    cudaGetSymbolAddress((void**)&cnsum, g_cnsum);
    cudaGetSymbolAddress((void**)&lnsum, g_lnsum);
    cudaGetSymbolAddress((void**)&lnsq,  g_lnsq);
    cudaGetSymbolAddress((void**)&t_hi, g_t_hi);
    cudaGetSymbolAddress((void**)&t_lo, g_t_lo);
    cudaGetSymbolAddress((void**)&o_hi, g_o_hi);
    cudaGetSymbolAddress((void**)&o_lo, g_o_lo);
    cudaGetSymbolAddress((void**)&wqkvT_hi, g_wqkvT_hi);
    cudaGetSymbolAddress((void**)&wqkvT_lo, g_wqkvT_lo);
    cudaGetSymbolAddress((void**)&woutT_hi, g_woutT_hi);
    cudaGetSymbolAddress((void**)&woutT_lo, g_woutT_lo);
    cudaGetSymbolAddress((void**)&pwk_hi, g_pwk_hi);
    cudaGetSymbolAddress((void**)&pwk_lo, g_pwk_lo);
    cudaGetSymbolAddress((void**)&wsT_hi, g_wsT_hi);
    cudaGetSymbolAddress((void**)&wsT_lo, g_wsT_lo);

    cudaFuncSetAttribute(k_mma, cudaFuncAttributeMaxDynamicSharedMemorySize, SMEM_MMA);
    cudaFuncSetAttribute(k_pwfin, cudaFuncAttributeMaxDynamicSharedMemorySize, SMEM_PW);
    cudaFuncSetAttribute(k_kvproj, cudaFuncAttributeMaxDynamicSharedMemorySize, SMEM_KV);
    cudaFuncSetAttribute(k_attn, cudaFuncAttributeMaxDynamicSharedMemorySize, SMEM_AT);

    // zero fused-reduction accumulators (async memset: graph-capturable, no alloc)
    cudaMemsetAsync(cnsum, 0, BQ * 512 * sizeof(float));
    cudaMemsetAsync(lnsum, 0, BQ * NN * sizeof(float));
    cudaMemsetAsync(lnsq,  0, BQ * NN * sizeof(float));

    k_transpose<<<dim3(4, 128, 4), 256>>>(x);
    k_wtprep_all<<<192, 256>>>(wqkv, wout, wseq);
    k_wprep_nt<<<256, 256>>>(pwk, pwk_hi, pwk_lo, 256 * 256);
    // QKV GEMM with fused q/k column sumsq
    k_mma<<<dim3(6, 256), 256, SMEM_MMA>>>(t_hi, t_lo, wqkvT_hi, wqkvT_lo, nullptr,
                                           qkv, 256, 768, cnsum, nullptr, 1);
    k_cnfin<<<8, 256>>>();
    k_kvproj<<<dim3(16, 16, 2), 128, SMEM_KV>>>(qkv, wsT_hi, wsT_lo);
    k_kvred<<<512, 256>>>(bseq);
    k_attn<<<dim3(64, 4, 4), 128, SMEM_AT>>>(qkv, temp);
    // out-proj GEMM with fused LN row stats
    k_mma<<<dim3(2, 256), 256, SMEM_MMA>>>(o_hi, o_lo, woutT_hi, woutT_lo, bout,
                                           o2, 256, 256, lnsum, lnsq, 2);
    k_lnfin<<<128, 256>>>();
    k_lnapply<<<dim3(4, 128, 4), 256>>>(x, lng, lnb);
    k_dwconv<<<1024, 256>>>(dwk, dwb);
    k_pwfin<<<dim3(64, 2, 4), 256, SMEM_PW>>>(pwb, out);
}